// round 3
// baseline (speedup 1.0000x reference)
#include <cuda_runtime.h>
#include <math.h>
#include <stdint.h>

#define B 16
#define N 1024
#define IN 128
#define H 32
#define KC 32
#define KM 16
#define MAXD 128
#define EPSV 1e-15f

// ------------------ scratch (device globals; no allocation) ------------------
__device__ float g_xh[B*N*H];        // x @ W1 + b1
__device__ int   g_cols[B*N*MAXD];   // neighbor lists (sorted, deterministic)
__device__ int   g_deg[B*N];
__device__ float g_srw[B*N*2];       // rewiring softmax (k=2); f = s[...,0]
__device__ float g_sct[B*N*KC];      // CT softmax (k=32)
__device__ float g_sqct[B*N];        // ||s_ct||^2 per node
__device__ float g_rowA[B*N];        // per-row partials (num_rw / sas)
__device__ float g_rowB[B*N];        // per-row partials (den terms)
__device__ float g_rowC[B*N];        // per-row partials (sds term)
__device__ float g_y[B*N*H];         // A_new @ xh
__device__ float g_xg[B*N*H];        // dgc output (x_gap / x_ct, reused)
__device__ float g_smc[B*N*KM];      // pool assignment softmax
__device__ float g_t16[B*N*KM];      // A_new @ smc
__device__ float g_dnew[B*N];        // row sums of rewired adj
__device__ float g_wct[B*N*MAXD];    // CT edge weights
__device__ float g_vol[B];
__device__ float g_poolx[B*KM*H];
__device__ float g_pooladj[B*KM*KM];
__device__ float g_x2gap[B*KM*H];
__device__ float g_x2ct[B*KM*H];
__device__ float g_loss[2];          // main, ortho

__device__ __forceinline__ float wsum(float v){
    #pragma unroll
    for(int o=16;o;o>>=1) v += __shfl_xor_sync(0xffffffffu, v, o);
    return v;
}

__global__ void k_zero(){ g_loss[0]=0.f; g_loss[1]=0.f; }

// Build neighbor lists: one warp per row, ballot compaction (deterministic order)
__global__ void k_build(const float* __restrict__ adj){
    int wid = (blockIdx.x*blockDim.x + threadIdx.x) >> 5;
    int lane = threadIdx.x & 31;
    if (wid >= B*N) return;
    const float* row = adj + (size_t)wid * N;
    int* cols = g_cols + (size_t)wid * MAXD;
    int cnt = 0;
    for (int c = 0; c < N; c += 32){
        float v = row[c + lane];
        unsigned m = __ballot_sync(0xffffffffu, v != 0.f);
        if (v != 0.f){
            int idx = cnt + __popc(m & ((1u<<lane)-1u));
            if (idx < MAXD) cols[idx] = c + lane;
        }
        cnt += __popc(m);
    }
    if (lane == 0) g_deg[wid] = cnt < MAXD ? cnt : MAXD;
}

// xh = x @ W1 + b1 ; block = 8 rows x 32 cols, W1 in shared
__global__ void k_xh(const float* __restrict__ x, const float* __restrict__ W1,
                     const float* __restrict__ b1){
    __shared__ float Ws[IN*H];
    for (int i = threadIdx.x; i < IN*H; i += blockDim.x) Ws[i] = W1[i];
    __syncthreads();
    int h = threadIdx.x & 31, rr = threadIdx.x >> 5;
    int row = blockIdx.x*8 + rr;
    const float* xr = x + (size_t)row*IN;
    float acc = b1[h];
    #pragma unroll 8
    for (int k = 0; k < IN; k++) acc += xr[k]*Ws[k*H+h];
    g_xh[row*H+h] = acc;
}

// rewiring softmax (k=2) + den partial
__global__ void k_srw(const float* __restrict__ Wrw, const float* __restrict__ brw){
    int r = blockIdx.x*blockDim.x + threadIdx.x;
    if (r >= B*N) return;
    const float* xr = g_xh + r*H;
    float a0 = brw[0], a1 = brw[1];
    #pragma unroll
    for (int k = 0; k < H; k++){ float v = xr[k]; a0 += v*Wrw[k*2]; a1 += v*Wrw[k*2+1]; }
    float m = fmaxf(a0,a1);
    float e0 = expf(a0-m), e1 = expf(a1-m);
    float inv = 1.f/(e0+e1);
    float s0 = e0*inv, s1 = e1*inv;
    g_srw[2*r] = s0; g_srw[2*r+1] = s1;
    g_rowB[r] = (float)g_deg[r]*(s0*s0 + s1*s1);
}

// per-row contribution to trace(S^T A S), k=2
__global__ void k_numrw(){
    int wid = (blockIdx.x*blockDim.x + threadIdx.x) >> 5;
    int lane = threadIdx.x & 31;
    if (wid >= B*N) return;
    int bN = (wid/N)*N;
    int deg = g_deg[wid];
    const int* cols = g_cols + wid*MAXD;
    float t0 = 0.f, t1 = 0.f;
    for (int j = lane; j < deg; j += 32){
        int m = cols[j];
        t0 += g_srw[2*(bN+m)];
        t1 += g_srw[2*(bN+m)+1];
    }
    t0 = wsum(t0); t1 = wsum(t1);
    if (lane == 0) g_rowA[wid] = g_srw[2*wid]*t0 + g_srw[2*wid+1]*t1;
}

// per-batch rewiring losses
__global__ void k_loss_rw(){
    int b = blockIdx.x, t = threadIdx.x;
    float num=0, den=0, s00=0, s01=0, s11=0;
    for (int n = t; n < N; n += 256){
        int r = b*N + n;
        num += g_rowA[r]; den += g_rowB[r];
        float a = g_srw[2*r], c = g_srw[2*r+1];
        s00 += a*a; s01 += a*c; s11 += c*c;
    }
    __shared__ float sh[5][256];
    sh[0][t]=num; sh[1][t]=den; sh[2][t]=s00; sh[3][t]=s01; sh[4][t]=s11;
    __syncthreads();
    for (int o = 128; o; o >>= 1){
        if (t < o){ for (int q = 0; q < 5; q++) sh[q][t] += sh[q][t+o]; }
        __syncthreads();
    }
    if (t == 0){
        num = sh[0][0]; den = sh[1][0] + EPSV;
        s00 = sh[2][0]; s01 = sh[3][0]; s11 = sh[4][0];
        float nrm = sqrtf(s00*s00 + 2.f*s01*s01 + s11*s11);
        const float isk = 0.70710678118654752f;
        float d00 = s00/nrm - isk, d01 = s01/nrm, d11 = s11/nrm - isk;
        float orth = sqrtf(d00*d00 + 2.f*d01*d01 + d11*d11);
        atomicAdd(&g_loss[0], -(num/den)/(float)B);
        atomicAdd(&g_loss[1], orth/(float)B);
    }
}

// y = A_new @ xh ; d_new = rowsum(A_new). mode 0: gap weights, mode 1: ct weights
__global__ void k_agg(int mode){
    int wid = (blockIdx.x*blockDim.x + threadIdx.x) >> 5;
    int lane = threadIdx.x & 31;
    if (wid >= B*N) return;
    int bN = (wid/N)*N;
    int deg = g_deg[wid];
    const int* cols = g_cols + wid*MAXD;
    float fn = g_srw[2*wid];
    float acc = 0.f, dsum = 0.f;
    for (int j = 0; j < deg; j++){
        int m = cols[j];
        float w;
        if (mode) w = g_wct[wid*MAXD + j];
        else { float d = fn - g_srw[2*(bN+m)]; w = 1.f - d*d; }
        acc += w * g_xh[(bN+m)*H + lane];
        dsum += w;
    }
    g_y[wid*H + lane] = acc;
    if (lane == 0) g_dnew[wid] = dsum;
}

// out = y @ Wrel + brel + xh @ Wroot
__global__ void k_lin(const float* __restrict__ Wrel, const float* __restrict__ brel,
                      const float* __restrict__ Wroot, float* __restrict__ out){
    __shared__ float Wr[H*H], Wo[H*H];
    for (int i = threadIdx.x; i < H*H; i += blockDim.x){ Wr[i]=Wrel[i]; Wo[i]=Wroot[i]; }
    __syncthreads();
    int h = threadIdx.x & 31, rr = threadIdx.x >> 5;
    int row = blockIdx.x*8 + rr;
    const float* yr = g_y + row*H;
    const float* xr = g_xh + row*H;
    float acc = brel[h];
    #pragma unroll
    for (int k = 0; k < H; k++) acc += yr[k]*Wr[k*H+h] + xr[k]*Wo[k*H+h];
    out[row*H+h] = acc;
}

// pool assignment softmax (KM=16) + den partial (uses g_dnew)
__global__ void k_smc(const float* __restrict__ xin, const float* __restrict__ W,
                      const float* __restrict__ bb){
    int r = blockIdx.x*blockDim.x + threadIdx.x;
    if (r >= B*N) return;
    float xr[H];
    #pragma unroll
    for (int j = 0; j < H; j++) xr[j] = xin[r*H+j];
    float raw[KM]; float mx = -1e30f;
    #pragma unroll
    for (int k = 0; k < KM; k++){
        float a = bb[k];
        #pragma unroll
        for (int j = 0; j < H; j++) a += xr[j]*W[j*KM+k];
        raw[k] = a; mx = fmaxf(mx, a);
    }
    float sum = 0.f;
    #pragma unroll
    for (int k = 0; k < KM; k++){ raw[k] = expf(raw[k]-mx); sum += raw[k]; }
    float inv = 1.f/sum, sq = 0.f;
    #pragma unroll
    for (int k = 0; k < KM; k++){
        float s = raw[k]*inv;
        g_smc[r*KM+k] = s; sq += s*s;
    }
    g_rowB[r] = g_dnew[r]*sq;
}

// t = A_new @ smc
__global__ void k_t16(int mode){
    int wid = (blockIdx.x*blockDim.x + threadIdx.x) >> 5;
    int lane = threadIdx.x & 31;
    if (wid >= B*N) return;
    int bN = (wid/N)*N;
    int deg = g_deg[wid];
    const int* cols = g_cols + wid*MAXD;
    float fn = g_srw[2*wid];
    float t = 0.f;
    for (int j = 0; j < deg; j++){
        int m = cols[j];
        float w;
        if (mode) w = g_wct[wid*MAXD + j];
        else { float d = fn - g_srw[2*(bN+m)]; w = 1.f - d*d; }
        if (lane < KM) t += w * g_smc[(bN+m)*KM + lane];
    }
    if (lane < KM) g_t16[wid*KM + lane] = t;
}

// per-batch: pooled x, pooled adj (normalized), pool losses
__global__ void k_poolred(const float* __restrict__ xin){
    int b = blockIdx.x, t = threadIdx.x;
    __shared__ float s_oa[KM*KM], s_ss[KM*KM];
    if (t < 256){
        int k = t >> 4, l = t & 15;
        float oa = 0.f, ssv = 0.f;
        for (int n = 0; n < N; n++){
            int r = b*N + n;
            float sk = g_smc[r*KM+k];
            oa  += sk * g_t16[r*KM+l];
            ssv += sk * g_smc[r*KM+l];
        }
        s_oa[t] = oa; s_ss[t] = ssv;
    }
    {
        int k = t >> 5, h = t & 31;
        float px = 0.f;
        for (int n = 0; n < N; n++){
            int r = b*N + n;
            px += g_smc[r*KM+k] * xin[r*H+h];
        }
        g_poolx[(b*KM+k)*H + h] = px;
    }
    __syncthreads();
    __shared__ float red[512];
    float dv = 0.f;
    for (int n = t; n < N; n += 512) dv += g_rowB[b*N+n];
    red[t] = dv; __syncthreads();
    for (int o = 256; o; o >>= 1){ if (t < o) red[t] += red[t+o]; __syncthreads(); }
    float den = red[0] + EPSV;
    __syncthreads();
    __shared__ float red2[256];
    if (t < 256) red2[t] = s_ss[t]*s_ss[t];
    __syncthreads();
    for (int o = 128; o; o >>= 1){ if (t < o && t < 256) red2[t] += red2[t+o]; __syncthreads(); }
    __shared__ float nrm_s;
    if (t == 0) nrm_s = sqrtf(red2[0]);
    __syncthreads();
    float nrm = nrm_s;
    if (t < 256){
        int k = t >> 4, l = t & 15;
        float d = s_ss[t]/nrm - ((k==l) ? 0.25f : 0.f);
        red2[t] = d*d;
    }
    __syncthreads();
    for (int o = 128; o; o >>= 1){ if (t < o && t < 256) red2[t] += red2[t+o]; __syncthreads(); }
    if (t == 0){
        float num = 0.f;
        #pragma unroll
        for (int k = 0; k < KM; k++) num += s_oa[k*KM+k];
        atomicAdd(&g_loss[0], -(num/den)/(float)B);
        atomicAdd(&g_loss[1], sqrtf(red2[0])/(float)B);
    }
    __syncthreads();
    __shared__ float dsq[KM];
    if (t < KM){
        float rs = 0.f;
        #pragma unroll
        for (int l = 0; l < KM; l++) rs += (l==t) ? 0.f : s_oa[t*KM+l];
        dsq[t] = sqrtf(rs) + EPSV;
    }
    __syncthreads();
    if (t < 256){
        int k = t >> 4, l = t & 15;
        float v = (k==l) ? 0.f : s_oa[t];
        g_pooladj[b*KM*KM + t] = v/(dsq[k]*dsq[l]);
    }
}

// pooled dgc: out = (pooladj@poolx)@Wrel + b + poolx@Wroot
__global__ void k_pooldgc(const float* __restrict__ Wrel, const float* __restrict__ brel,
                          const float* __restrict__ Wroot, float* __restrict__ out){
    int b = blockIdx.x, t = threadIdx.x;
    __shared__ float px[KM*H], pa[KM*KM], t2[KM*H];
    if (t < KM*KM) pa[t] = g_pooladj[b*KM*KM + t];
    px[t] = g_poolx[b*KM*H + t];
    __syncthreads();
    int k = t >> 5, h = t & 31;
    float a = 0.f;
    #pragma unroll
    for (int l = 0; l < KM; l++) a += pa[k*KM+l]*px[l*H+h];
    t2[t] = a;
    __syncthreads();
    float acc = brel[h];
    #pragma unroll
    for (int j = 0; j < H; j++) acc += t2[k*H+j]*Wrel[j*H+h] + px[k*H+j]*Wroot[j*H+h];
    out[b*KM*H + t] = acc;
}

__global__ void k_vol(){
    int b = blockIdx.x, t = threadIdx.x;
    __shared__ float red[256];
    float v = 0.f;
    for (int n = t; n < N; n += 256) v += (float)g_deg[b*N+n];
    red[t] = v; __syncthreads();
    for (int o = 128; o; o >>= 1){ if (t < o) red[t] += red[t+o]; __syncthreads(); }
    if (t == 0) g_vol[b] = red[0];
}

// CT softmax (warp per node), sq, den/sds partials
__global__ void k_sct(const float* __restrict__ W, const float* __restrict__ bb){
    int wid = (blockIdx.x*blockDim.x + threadIdx.x) >> 5;
    int lane = threadIdx.x & 31;
    if (wid >= B*N) return;
    const float* xr = g_xh + wid*H;
    float a = bb[lane];
    #pragma unroll
    for (int j = 0; j < H; j++) a += xr[j]*W[j*KC+lane];
    float m = a;
    #pragma unroll
    for (int o = 16; o; o >>= 1) m = fmaxf(m, __shfl_xor_sync(0xffffffffu, m, o));
    float e = expf(a - m);
    float s = e / wsum(e);
    g_sct[wid*KC + lane] = s;
    float sq = wsum(s*s);
    if (lane == 0){
        g_sqct[wid] = sq;
        g_rowB[wid] = sq;
        g_rowC[wid] = (float)g_deg[wid]*sq;
    }
}

// CT edge weights + per-row sas
__global__ void k_ct_edges(){
    int wid = (blockIdx.x*blockDim.x + threadIdx.x) >> 5;
    int lane = threadIdx.x & 31;
    if (wid >= B*N) return;
    int b = wid / N; int bN = b*N;
    int deg = g_deg[wid];
    const int* cols = g_cols + wid*MAXD;
    float sn = g_sct[wid*KC + lane];
    float sqn = g_sqct[wid];
    float invvol = 1.f/(g_vol[b] + EPSV);
    float t = 0.f;
    for (int j = 0; j < deg; j++){
        int m = cols[j];
        float sm = g_sct[(bN+m)*KC + lane];
        t += sm;
        float dot = wsum(sn*sm);
        float d2 = sqn + g_sqct[bN+m] - 2.f*dot;
        float dist = sqrtf(fmaxf(d2, 0.f) + 1e-12f);
        if (lane == 0) g_wct[wid*MAXD + j] = dist*invvol;
    }
    float sas = wsum(sn*t);
    if (lane == 0) g_rowA[wid] = sas;
}

// per-batch CT losses (ct_loss + ortho over 32x32 S^T S)
__global__ void k_loss_ct(){
    int b = blockIdx.x, t = threadIdx.x;
    int k = t >> 5, l = t & 31;
    float ssv = 0.f;
    for (int n = 0; n < N; n++){
        int r = b*N + n;
        ssv += g_sct[r*KC+k]*g_sct[r*KC+l];
    }
    __shared__ float ss[KC*KC];
    ss[t] = ssv;
    __syncthreads();
    __shared__ float red[1024];
    __shared__ float S[3];
    #pragma unroll
    for (int pass = 0; pass < 3; pass++){
        float v = (pass==0) ? g_rowA[b*N+t] : (pass==1) ? g_rowB[b*N+t] : g_rowC[b*N+t];
        red[t] = v; __syncthreads();
        for (int o = 512; o; o >>= 1){ if (t < o) red[t] += red[t+o]; __syncthreads(); }
        if (t == 0) S[pass] = red[0];
        __syncthreads();
    }
    red[t] = ss[t]*ss[t]; __syncthreads();
    for (int o = 512; o; o >>= 1){ if (t < o) red[t] += red[t+o]; __syncthreads(); }
    __shared__ float nrm_s;
    if (t == 0) nrm_s = sqrtf(red[0]);
    __syncthreads();
    float d = ss[t]/nrm_s - ((k==l) ? 0.17677669529663687f : 0.f);
    red[t] = d*d; __syncthreads();
    for (int o = 512; o; o >>= 1){ if (t < o) red[t] += red[t+o]; __syncthreads(); }
    if (t == 0){
        float sas = S[0], den = S[1] + EPSV, sds = S[2];
        atomicAdd(&g_loss[0], ((sds - sas)/den)/(float)B);
        atomicAdd(&g_loss[1], sqrtf(red[0])/(float)B);
    }
}

// readout: concat->relu->sum over clusters, MLP, log_softmax; block per batch
__global__ void k_readout(const float* __restrict__ Wcat, const float* __restrict__ bcat,
                          const float* __restrict__ W2,  const float* __restrict__ b2,
                          const float* __restrict__ W3,  const float* __restrict__ b3,
                          float* __restrict__ out){
    int b = blockIdx.x, h = threadIdx.x;
    __shared__ float h1[H], h2[H], lg[10];
    float acc = 0.f;
    for (int kk = 0; kk < KM; kk++){
        float z = bcat[h];
        #pragma unroll
        for (int j = 0; j < H; j++) z += g_x2gap[(b*KM+kk)*H+j]*Wcat[j*H+h];
        #pragma unroll
        for (int j = 0; j < H; j++) z += g_x2ct[(b*KM+kk)*H+j]*Wcat[(H+j)*H+h];
        acc += fmaxf(z, 0.f);
    }
    h1[h] = acc; __syncwarp();
    float z2 = b2[h];
    #pragma unroll
    for (int j = 0; j < H; j++) z2 += h1[j]*W2[j*H+h];
    h2[h] = fmaxf(z2, 0.f); __syncwarp();
    if (h < 10){
        float z = b3[h];
        #pragma unroll
        for (int j = 0; j < H; j++) z += h2[j]*W3[j*10+h];
        lg[h] = z;
    }
    __syncwarp();
    if (h < 10){
        float m = lg[0];
        #pragma unroll
        for (int i = 1; i < 10; i++) m = fmaxf(m, lg[i]);
        float s = 0.f;
        #pragma unroll
        for (int i = 0; i < 10; i++) s += expf(lg[i]-m);
        out[b*10 + h] = lg[h] - m - logf(s);
    }
    if (b == 0 && h == 31){
        out[B*10]     = g_loss[0];
        out[B*10 + 1] = g_loss[1];
    }
}

extern "C" void kernel_launch(void* const* d_in, const int* in_sizes, int n_in,
                              void* d_out, int out_size){
    const float* x     = (const float*)d_in[0];
    const float* adj   = (const float*)d_in[1];
    // d_in[2] = mask (all ones) — unused
    const float* W1    = (const float*)d_in[3];
    const float* b1    = (const float*)d_in[4];
    const float* Wrw   = (const float*)d_in[5];
    const float* brw   = (const float*)d_in[6];
    const float* Wg_rel= (const float*)d_in[7];
    const float* bg    = (const float*)d_in[8];
    const float* Wg_root=(const float*)d_in[9];
    const float* Wmcg  = (const float*)d_in[10];
    const float* bmcg  = (const float*)d_in[11];
    const float* W2g_rel=(const float*)d_in[12];
    const float* b2g   = (const float*)d_in[13];
    const float* W2g_root=(const float*)d_in[14];
    const float* Wct   = (const float*)d_in[15];
    const float* bct   = (const float*)d_in[16];
    const float* Wc_rel= (const float*)d_in[17];
    const float* bc    = (const float*)d_in[18];
    const float* Wc_root=(const float*)d_in[19];
    const float* Wmcc  = (const float*)d_in[20];
    const float* bmcc  = (const float*)d_in[21];
    const float* Wcat  = (const float*)d_in[22];
    const float* bcat  = (const float*)d_in[23];
    const float* W2    = (const float*)d_in[24];
    const float* b2    = (const float*)d_in[25];
    const float* W3    = (const float*)d_in[26];
    const float* b3    = (const float*)d_in[27];
    float* out = (float*)d_out;

    // *** THE FIX ***: device addresses of __device__ scratch symbols.
    // (Host-side symbol names are host shadows — passing them as kernel args
    //  silently routed data through host memory via ATS while k_readout read
    //  the never-written device copies.)
    void *p_xg = 0, *p_gap = 0, *p_ct = 0;
    cudaGetSymbolAddress(&p_xg,  g_xg);
    cudaGetSymbolAddress(&p_gap, g_x2gap);
    cudaGetSymbolAddress(&p_ct,  g_x2ct);
    float* d_xg  = (float*)p_xg;
    float* d_gap = (float*)p_gap;
    float* d_ct  = (float*)p_ct;

    const int WARP_GRID = (B*N)/8;      // 2048 blocks of 256 (8 warps)
    const int NODE_GRID = (B*N)/256;    // 64 blocks of 256 threads

    k_zero<<<1,1>>>();
    k_build<<<WARP_GRID,256>>>(adj);
    k_xh<<<WARP_GRID,256>>>(x, W1, b1);

    // ---- GAP branch ----
    k_srw<<<NODE_GRID,256>>>(Wrw, brw);
    k_numrw<<<WARP_GRID,256>>>();
    k_loss_rw<<<B,256>>>();
    k_agg<<<WARP_GRID,256>>>(0);
    k_lin<<<WARP_GRID,256>>>(Wg_rel, bg, Wg_root, d_xg);
    k_smc<<<NODE_GRID,256>>>(d_xg, Wmcg, bmcg);
    k_t16<<<WARP_GRID,256>>>(0);
    k_poolred<<<B,512>>>(d_xg);
    k_pooldgc<<<B,512>>>(W2g_rel, b2g, W2g_root, d_gap);

    // ---- CT branch ----
    k_vol<<<B,256>>>();
    k_sct<<<WARP_GRID,256>>>(Wct, bct);
    k_ct_edges<<<WARP_GRID,256>>>();
    k_loss_ct<<<B,1024>>>();
    k_agg<<<WARP_GRID,256>>>(1);
    k_lin<<<WARP_GRID,256>>>(Wc_rel, bc, Wc_root, d_xg);
    k_smc<<<NODE_GRID,256>>>(d_xg, Wmcc, bmcc);
    k_t16<<<WARP_GRID,256>>>(1);
    k_poolred<<<B,512>>>(d_xg);
    k_pooldgc<<<B,512>>>(W2g_rel, b2g, W2g_root, d_ct);

    // ---- readout ----
    k_readout<<<B,32>>>(Wcat, bcat, W2, b2, W3, b3, out);

    (void)in_sizes; (void)n_in; (void)out_size;
}

// round 4
// speedup vs baseline: 2.1693x; 2.1693x over previous
#include <cuda_runtime.h>
#include <math.h>
#include <stdint.h>

#define B 16
#define N 1024
#define BN (B*N)
#define IN 128
#define H 32
#define KC 32
#define KM 16
#define MAXD 128
#define EPSV 1e-15f
#define FULL 0xffffffffu

// ---------------- accumulator slab (atomically accumulated; zeroed per run) --
#define ACC_NUMRW 0                    // [B]
#define ACC_DENRW 16                   // [B]
#define ACC_S00   32                   // [B]
#define ACC_S01   48                   // [B]
#define ACC_S11   64                   // [B]
#define ACC_SAS   80                   // [B]
#define ACC_DENCT 96                   // [B]
#define ACC_SDS   112                  // [B]
#define ACC_VOL   128                  // [B]
#define ACC_SSCT  144                  // [B][32*32]
#define ACC_OA    (ACC_SSCT+B*1024)    // [2][B][256]
#define ACC_SSP   (ACC_OA+2*B*256)     // [2][B][256]
#define ACC_PX    (ACC_SSP+2*B*256)    // [2][B][512]
#define ACC_DENP  (ACC_PX+2*B*512)     // [2][B]
#define ACC_LOSS  (ACC_DENP+2*B)       // [2] main, ortho
#define ACC_TOTAL (ACC_LOSS+2)

__device__ float g_acc[ACC_TOTAL];

// ---------------- scratch ----------------------------------------------------
__device__ float g_xh[BN*H];
__device__ int   g_cols[BN*MAXD];
__device__ int   g_deg[BN];
__device__ float g_srw[BN*2];
__device__ float g_sct[BN*KC];
__device__ float g_sqct[BN];
__device__ float g_wgap[BN*MAXD];
__device__ float g_wct[BN*MAXD];
__device__ float g_y[2*BN*H];
__device__ float g_dnew[2*BN];
__device__ float g_xg[2*BN*H];
__device__ float g_smc[2*BN*KM];
__device__ float g_t16[2*BN*KM];
__device__ float g_x2[2*B*KM*H];

__device__ __forceinline__ float wsum(float v){
    #pragma unroll
    for(int o=16;o;o>>=1) v += __shfl_xor_sync(FULL, v, o);
    return v;
}
__device__ __forceinline__ float wsum16(float v){
    #pragma unroll
    for(int o=8;o;o>>=1) v += __shfl_xor_sync(FULL, v, o, 16);
    return v;
}

__global__ void k_init(){
    int i = blockIdx.x*blockDim.x + threadIdx.x;
    if (i < ACC_TOTAL) g_acc[i] = 0.f;
}

// neighbor lists via float4 + 4-way ballot compaction; vol accumulation
__global__ void k_build(const float* __restrict__ adj){
    int wid = (blockIdx.x*blockDim.x + threadIdx.x) >> 5;
    int lane = threadIdx.x & 31;
    if (wid >= BN) return;
    const float4* row = (const float4*)(adj + (size_t)wid * N);
    int* cols = g_cols + (size_t)wid * MAXD;
    int cnt = 0;
    #pragma unroll 2
    for (int c = 0; c < N; c += 128){
        float4 v = row[(c>>2) + lane];
        bool n0=v.x!=0.f, n1=v.y!=0.f, n2=v.z!=0.f, n3=v.w!=0.f;
        unsigned m0=__ballot_sync(FULL,n0), m1=__ballot_sync(FULL,n1);
        unsigned m2=__ballot_sync(FULL,n2), m3=__ballot_sync(FULL,n3);
        unsigned below = (1u<<lane) - 1u;
        int idx = cnt + __popc(m0&below)+__popc(m1&below)+__popc(m2&below)+__popc(m3&below);
        int col0 = c + lane*4;
        if(n0 && idx<MAXD){ cols[idx]=col0;   idx++; }
        if(n1 && idx<MAXD){ cols[idx]=col0+1; idx++; }
        if(n2 && idx<MAXD){ cols[idx]=col0+2; idx++; }
        if(n3 && idx<MAXD){ cols[idx]=col0+3; idx++; }
        cnt += __popc(m0)+__popc(m1)+__popc(m2)+__popc(m3);
    }
    int deg = cnt < MAXD ? cnt : MAXD;
    if (lane == 0) g_deg[wid] = deg;
    __shared__ float svol[8];
    if (lane == 0) svol[threadIdx.x>>5] = (float)deg;
    __syncthreads();
    if (threadIdx.x == 0){
        float s = 0.f;
        #pragma unroll
        for (int i = 0; i < 8; i++) s += svol[i];
        atomicAdd(&g_acc[ACC_VOL + (blockIdx.x >> 7)], s);
    }
}

// fused: xh = x@W1+b1 ; srw softmax(k=2) ; sct softmax(k=32) ; scalar partials
__global__ void k_xh_soft(const float* __restrict__ x,  const float* __restrict__ W1,
                          const float* __restrict__ b1, const float* __restrict__ Wrw,
                          const float* __restrict__ brw,const float* __restrict__ Wct,
                          const float* __restrict__ bct){
    int wid = (blockIdx.x*blockDim.x + threadIdx.x) >> 5;
    int lane = threadIdx.x & 31;
    if (wid >= BN) return;
    // xh (lane = h)
    float acc = b1[lane];
    const float* xr = x + (size_t)wid*IN;
    #pragma unroll
    for (int c = 0; c < 4; c++){
        float xv = xr[c*32 + lane];
        #pragma unroll
        for (int j = 0; j < 32; j++)
            acc += __shfl_sync(FULL, xv, j) * W1[(c*32+j)*H + lane];
    }
    g_xh[wid*H + lane] = acc;
    int deg = g_deg[wid];
    // rewiring softmax (k=2)
    float a0 = wsum(acc*Wrw[lane*2])   + brw[0];
    float a1 = wsum(acc*Wrw[lane*2+1]) + brw[1];
    float mm = fmaxf(a0,a1);
    float e0 = expf(a0-mm), e1 = expf(a1-mm);
    float inv = 1.f/(e0+e1);
    float s0 = e0*inv, s1 = e1*inv;
    if (lane == 0){ g_srw[2*wid]=s0; g_srw[2*wid+1]=s1; }
    // CT softmax (k=32, lane = k)
    float a = bct[lane];
    #pragma unroll
    for (int j = 0; j < 32; j++)
        a += __shfl_sync(FULL, acc, j) * Wct[j*KC + lane];
    float m = a;
    #pragma unroll
    for (int o = 16; o; o >>= 1) m = fmaxf(m, __shfl_xor_sync(FULL, m, o));
    float e = expf(a - m);
    float s = e / wsum(e);
    g_sct[wid*KC + lane] = s;
    float sq = wsum(s*s);
    if (lane == 0) g_sqct[wid] = sq;
    // scalar partials -> shared -> global (block is 8 nodes of one batch)
    __shared__ float sh[6];
    if (threadIdx.x < 6) sh[threadIdx.x] = 0.f;
    __syncthreads();
    if (lane == 0){
        atomicAdd(&sh[0], (float)deg*(s0*s0 + s1*s1)); // den_rw
        atomicAdd(&sh[1], s0*s0);                      // s00
        atomicAdd(&sh[2], s0*s1);                      // s01
        atomicAdd(&sh[3], s1*s1);                      // s11
        atomicAdd(&sh[4], sq);                         // den_ct
        atomicAdd(&sh[5], (float)deg*sq);              // sds
    }
    __syncthreads();
    if (threadIdx.x < 6){
        int b = blockIdx.x >> 7;
        const int dst[6] = {ACC_DENRW, ACC_S00, ACC_S01, ACC_S11, ACC_DENCT, ACC_SDS};
        atomicAdd(&g_acc[dst[threadIdx.x] + b], sh[threadIdx.x]);
    }
}

// per-edge: gap & CT weights (stored), num_rw and sas partials
__global__ void k_edges(){
    int wid = (blockIdx.x*blockDim.x + threadIdx.x) >> 5;
    int lane = threadIdx.x & 31;
    if (wid >= BN) return;
    int b = wid >> 10, bN = b << 10;
    int deg = g_deg[wid];
    const int* cols = g_cols + wid*MAXD;
    float f_n = g_srw[2*wid];
    float s1n = g_srw[2*wid+1];
    float sn  = g_sct[wid*KC + lane];
    float sqn = g_sqct[wid];
    float invvol = 1.f/(g_acc[ACC_VOL + b] + EPSV);
    float num_acc = 0.f, sas_acc = 0.f;
    for (int j = 0; j < deg; j++){
        int mcol = cols[j];
        float sm = g_sct[(bN+mcol)*KC + lane];
        float dot = wsum(sn*sm);
        float fm0 = g_srw[2*(bN+mcol)];
        float fm1 = g_srw[2*(bN+mcol)+1];
        float d = f_n - fm0;
        float d2 = sqn + g_sqct[bN+mcol] - 2.f*dot;
        float dist = sqrtf(fmaxf(d2, 0.f) + 1e-12f);
        if (lane == 0){
            g_wgap[wid*MAXD + j] = 1.f - d*d;
            g_wct [wid*MAXD + j] = dist*invvol;
        }
        num_acc += f_n*fm0 + s1n*fm1;
        sas_acc += dot;
    }
    __shared__ float sh[2];
    if (threadIdx.x < 2) sh[threadIdx.x] = 0.f;
    __syncthreads();
    if (lane == 0){
        atomicAdd(&sh[0], num_acc);
        atomicAdd(&sh[1], sas_acc);
    }
    __syncthreads();
    if (threadIdx.x < 2){
        const int dst[2] = {ACC_NUMRW, ACC_SAS};
        atomicAdd(&g_acc[dst[threadIdx.x] + (blockIdx.x>>7)], sh[threadIdx.x]);
    }
}

// y = A_w @ xh, dnew = rowsum(A_w); both branches (blockIdx.y)
__global__ void k_agg(){
    int wid = (blockIdx.x*blockDim.x + threadIdx.x) >> 5;
    int lane = threadIdx.x & 31;
    int br = blockIdx.y;
    if (wid >= BN) return;
    int bN = (wid >> 10) << 10;
    int deg = g_deg[wid];
    const int* cols = g_cols + wid*MAXD;
    const float* w_arr = (br ? g_wct : g_wgap) + wid*MAXD;
    float acc = 0.f, dsum = 0.f;
    for (int j = 0; j < deg; j++){
        int m = cols[j];
        float w = w_arr[j];
        acc  += w * g_xh[(bN+m)*H + lane];
        dsum += w;
    }
    g_y[br*BN*H + wid*H + lane] = acc;
    if (lane == 0) g_dnew[br*BN + wid] = dsum;
}

// xg = y@Wrel + brel + xh@Wroot; smc = softmax(xg@Wmc + bmc); den_pool partial
__global__ void k_linsmc(const float* __restrict__ Wr0, const float* __restrict__ br0,
                         const float* __restrict__ Wo0, const float* __restrict__ Wm0,
                         const float* __restrict__ bm0,
                         const float* __restrict__ Wr1, const float* __restrict__ br1,
                         const float* __restrict__ Wo1, const float* __restrict__ Wm1,
                         const float* __restrict__ bm1){
    int wid = (blockIdx.x*blockDim.x + threadIdx.x) >> 5;
    int lane = threadIdx.x & 31;
    int br = blockIdx.y;
    if (wid >= BN) return;
    const float* Wrel  = br ? Wr1 : Wr0;
    const float* brel  = br ? br1 : br0;
    const float* Wroot = br ? Wo1 : Wo0;
    const float* Wmc   = br ? Wm1 : Wm0;
    const float* bmc   = br ? bm1 : bm0;
    float y  = g_y[br*BN*H + wid*H + lane];
    float xh = g_xh[wid*H + lane];
    float acc = brel[lane];
    #pragma unroll
    for (int j = 0; j < 32; j++){
        acc += __shfl_sync(FULL, y,  j) * Wrel [j*H + lane];
        acc += __shfl_sync(FULL, xh, j) * Wroot[j*H + lane];
    }
    g_xg[br*BN*H + wid*H + lane] = acc;
    // pool softmax (16 clusters on lanes 0..15)
    float a = (lane < KM) ? bmc[lane] : 0.f;
    #pragma unroll
    for (int j = 0; j < 32; j++){
        float xj = __shfl_sync(FULL, acc, j);
        if (lane < KM) a += xj * Wmc[j*KM + lane];
    }
    float mm = a;
    #pragma unroll
    for (int o = 8; o; o >>= 1) mm = fmaxf(mm, __shfl_xor_sync(FULL, mm, o, 16));
    float e = (lane < KM) ? expf(a - mm) : 0.f;
    float es = wsum16(e);
    float s = e/es;
    if (lane < KM) g_smc[br*BN*KM + wid*KM + lane] = s;
    float sq = wsum16(s*s);
    __shared__ float sh;
    if (threadIdx.x == 0) sh = 0.f;
    __syncthreads();
    if (lane == 0) atomicAdd(&sh, g_dnew[br*BN + wid]*sq);
    __syncthreads();
    if (threadIdx.x == 0)
        atomicAdd(&g_acc[ACC_DENP + br*B + (blockIdx.x>>7)], sh);
}

// t16 = A_w @ smc (both branches)
__global__ void k_t16(){
    int wid = (blockIdx.x*blockDim.x + threadIdx.x) >> 5;
    int lane = threadIdx.x & 31;
    int br = blockIdx.y;
    if (wid >= BN) return;
    int bN = (wid >> 10) << 10;
    int deg = g_deg[wid];
    const int* cols = g_cols + wid*MAXD;
    const float* w_arr = (br ? g_wct : g_wgap) + wid*MAXD;
    const float* smc = g_smc + br*BN*KM;
    float t = 0.f;
    for (int j = 0; j < deg; j++){
        int m = cols[j];
        float w = w_arr[j];
        if (lane < KM) t += w * smc[(bN+m)*KM + lane];
    }
    if (lane < KM) g_t16[br*BN*KM + wid*KM + lane] = t;
}

// partial pooled matrices over 128-node chunks
__global__ void k_poolpart(){
    int c = blockIdx.x, b = blockIdx.y, br = blockIdx.z;
    int t = threadIdx.x;                 // 256
    int n0 = b*N + c*128;
    const float* smc = g_smc + br*BN*KM;
    const float* t16 = g_t16 + br*BN*KM;
    const float* xg  = g_xg  + br*BN*H;
    int k = t >> 4, l = t & 15;
    float oa = 0.f, ssv = 0.f;
    for (int n = 0; n < 128; n++){
        int r = n0 + n;
        float sk = smc[r*KM + k];
        oa  += sk * t16[r*KM + l];
        ssv += sk * smc[r*KM + l];
    }
    int base = (br*B + b)*256;
    atomicAdd(&g_acc[ACC_OA  + base + t], oa);
    atomicAdd(&g_acc[ACC_SSP + base + t], ssv);
    int k0 = t >> 5, h0 = t & 31;
    int k1 = (t+256) >> 5;
    float p0 = 0.f, p1 = 0.f;
    for (int n = 0; n < 128; n++){
        int r = n0 + n;
        float xv = xg[r*H + h0];
        p0 += smc[r*KM + k0]*xv;
        p1 += smc[r*KM + k1]*xv;
    }
    int pbase = (br*B + b)*512;
    atomicAdd(&g_acc[ACC_PX + pbase + t],       p0);
    atomicAdd(&g_acc[ACC_PX + pbase + t + 256], p1);
}

// finalize pool: losses + normalized pooladj + pooled DGC (conv2gap weights)
__global__ void k_poolfin(const float* __restrict__ W2g_rel, const float* __restrict__ b2g,
                          const float* __restrict__ W2g_root){
    int b = blockIdx.x, br = blockIdx.y, t = threadIdx.x;   // 512
    __shared__ float oa[256], ssm[256], px[512], t2[512], pa[256], red[512], nrm_s;
    int base = (br*B + b)*256;
    if (t < 256){ oa[t] = g_acc[ACC_OA + base + t]; ssm[t] = g_acc[ACC_SSP + base + t]; }
    px[t] = g_acc[ACC_PX + (br*B + b)*512 + t];
    __syncthreads();
    red[t] = (t < 256) ? ssm[t]*ssm[t] : 0.f;
    __syncthreads();
    for (int o = 256; o; o >>= 1){ if (t < o) red[t] += red[t+o]; __syncthreads(); }
    if (t == 0) nrm_s = sqrtf(red[0]);
    __syncthreads();
    if (t < 256){
        int k = t >> 4, l = t & 15;
        float d = ssm[t]/nrm_s - ((k == l) ? 0.25f : 0.f);
        red[t] = d*d;
    } else red[t] = 0.f;
    __syncthreads();
    for (int o = 256; o; o >>= 1){ if (t < o) red[t] += red[t+o]; __syncthreads(); }
    if (t == 0){
        float num = 0.f;
        #pragma unroll
        for (int k = 0; k < KM; k++) num += oa[k*KM + k];
        float den = g_acc[ACC_DENP + br*B + b] + EPSV;
        atomicAdd(&g_acc[ACC_LOSS],   -(num/den)/(float)B);
        atomicAdd(&g_acc[ACC_LOSS+1], sqrtf(red[0])/(float)B);
    }
    __shared__ float dsq[KM];
    if (t < KM){
        float rs = 0.f;
        #pragma unroll
        for (int l = 0; l < KM; l++) rs += (l == t) ? 0.f : oa[t*KM + l];
        dsq[t] = sqrtf(rs) + EPSV;
    }
    __syncthreads();
    if (t < 256){
        int k = t >> 4, l = t & 15;
        pa[t] = (k == l) ? 0.f : oa[t]/(dsq[k]*dsq[l]);
    }
    __syncthreads();
    int k = t >> 5, h = t & 31;
    float a = 0.f;
    #pragma unroll
    for (int l = 0; l < KM; l++) a += pa[k*KM + l]*px[l*H + h];
    t2[t] = a;
    __syncthreads();
    float accv = b2g[h];
    #pragma unroll
    for (int j = 0; j < H; j++)
        accv += t2[k*H + j]*W2g_rel[j*H + h] + px[k*H + j]*W2g_root[j*H + h];
    g_x2[br*B*KM*H + b*KM*H + t] = accv;
}

// partial S^T S (32x32) for CT ortho
__global__ void k_ctpart(){
    int b = blockIdx.x, c = blockIdx.y, t = threadIdx.x;    // 1024
    int k = t >> 5, l = t & 31;
    int n0 = b*N + c*128;
    float ssv = 0.f;
    for (int n = 0; n < 128; n++){
        int r = n0 + n;
        ssv += g_sct[r*KC + k]*g_sct[r*KC + l];
    }
    atomicAdd(&g_acc[ACC_SSCT + b*1024 + t], ssv);
}

__global__ void k_ctfin(){
    int b = blockIdx.x, t = threadIdx.x;   // 1024
    __shared__ float ss[1024], red[1024], nrm_s;
    ss[t] = g_acc[ACC_SSCT + b*1024 + t];
    __syncthreads();
    red[t] = ss[t]*ss[t];
    __syncthreads();
    for (int o = 512; o; o >>= 1){ if (t < o) red[t] += red[t+o]; __syncthreads(); }
    if (t == 0) nrm_s = sqrtf(red[0]);
    __syncthreads();
    int k = t >> 5, l = t & 31;
    float d = ss[t]/nrm_s - ((k == l) ? 0.17677669529663687f : 0.f);
    red[t] = d*d;
    __syncthreads();
    for (int o = 512; o; o >>= 1){ if (t < o) red[t] += red[t+o]; __syncthreads(); }
    if (t == 0){
        float sas = g_acc[ACC_SAS + b];
        float den = g_acc[ACC_DENCT + b] + EPSV;
        float sds = g_acc[ACC_SDS + b];
        atomicAdd(&g_acc[ACC_LOSS],   ((sds - sas)/den)/(float)B);
        atomicAdd(&g_acc[ACC_LOSS+1], sqrtf(red[0])/(float)B);
    }
}

__global__ void k_rwfin(){
    int lane = threadIdx.x;
    float lm = 0.f, lo = 0.f;
    if (lane < B){
        float num = g_acc[ACC_NUMRW + lane];
        float den = g_acc[ACC_DENRW + lane] + EPSV;
        float s00 = g_acc[ACC_S00 + lane];
        float s01 = g_acc[ACC_S01 + lane];
        float s11 = g_acc[ACC_S11 + lane];
        float nrm = sqrtf(s00*s00 + 2.f*s01*s01 + s11*s11);
        const float isk = 0.70710678118654752f;
        float d00 = s00/nrm - isk, d01 = s01/nrm, d11 = s11/nrm - isk;
        lm = -(num/den)/(float)B;
        lo = sqrtf(d00*d00 + 2.f*d01*d01 + d11*d11)/(float)B;
    }
    lm = wsum(lm); lo = wsum(lo);
    if (lane == 0){
        atomicAdd(&g_acc[ACC_LOSS],   lm);
        atomicAdd(&g_acc[ACC_LOSS+1], lo);
    }
}

__global__ void k_readout(const float* __restrict__ Wcat, const float* __restrict__ bcat,
                          const float* __restrict__ W2,  const float* __restrict__ b2,
                          const float* __restrict__ W3,  const float* __restrict__ b3,
                          float* __restrict__ out){
    int b = blockIdx.x, h = threadIdx.x;   // 32
    __shared__ float h1[H], h2[H], lg[10];
    float acc = 0.f;
    for (int kk = 0; kk < KM; kk++){
        float z = bcat[h];
        #pragma unroll
        for (int j = 0; j < H; j++) z += g_x2[b*KM*H + kk*H + j]*Wcat[j*H + h];
        #pragma unroll
        for (int j = 0; j < H; j++) z += g_x2[B*KM*H + b*KM*H + kk*H + j]*Wcat[(H+j)*H + h];
        acc += fmaxf(z, 0.f);
    }
    h1[h] = acc; __syncwarp();
    float z2 = b2[h];
    #pragma unroll
    for (int j = 0; j < H; j++) z2 += h1[j]*W2[j*H + h];
    h2[h] = fmaxf(z2, 0.f); __syncwarp();
    if (h < 10){
        float z = b3[h];
        #pragma unroll
        for (int j = 0; j < H; j++) z += h2[j]*W3[j*10 + h];
        lg[h] = z;
    }
    __syncwarp();
    if (h < 10){
        float m = lg[0];
        #pragma unroll
        for (int i = 1; i < 10; i++) m = fmaxf(m, lg[i]);
        float s = 0.f;
        #pragma unroll
        for (int i = 0; i < 10; i++) s += expf(lg[i] - m);
        out[b*10 + h] = lg[h] - m - logf(s);
    }
    if (b == 0 && h == 31){
        out[B*10]     = g_acc[ACC_LOSS];
        out[B*10 + 1] = g_acc[ACC_LOSS+1];
    }
}

extern "C" void kernel_launch(void* const* d_in, const int* in_sizes, int n_in,
                              void* d_out, int out_size){
    const float* x      = (const float*)d_in[0];
    const float* adj    = (const float*)d_in[1];
    const float* W1     = (const float*)d_in[3];
    const float* b1     = (const float*)d_in[4];
    const float* Wrw    = (const float*)d_in[5];
    const float* brw    = (const float*)d_in[6];
    const float* Wg_rel = (const float*)d_in[7];
    const float* bg     = (const float*)d_in[8];
    const float* Wg_root= (const float*)d_in[9];
    const float* Wmcg   = (const float*)d_in[10];
    const float* bmcg   = (const float*)d_in[11];
    const float* W2g_rel= (const float*)d_in[12];
    const float* b2g    = (const float*)d_in[13];
    const float* W2g_root=(const float*)d_in[14];
    const float* Wct    = (const float*)d_in[15];
    const float* bct    = (const float*)d_in[16];
    const float* Wc_rel = (const float*)d_in[17];
    const float* bc     = (const float*)d_in[18];
    const float* Wc_root= (const float*)d_in[19];
    const float* Wmcc   = (const float*)d_in[20];
    const float* bmcc   = (const float*)d_in[21];
    const float* Wcat   = (const float*)d_in[22];
    const float* bcat   = (const float*)d_in[23];
    const float* W2     = (const float*)d_in[24];
    const float* b2     = (const float*)d_in[25];
    const float* W3     = (const float*)d_in[26];
    const float* b3     = (const float*)d_in[27];
    float* out = (float*)d_out;

    const int WG = BN/8;   // 2048 blocks of 8 warps (k_build)
    const int SG = BN/8;   // warp-per-node kernels: 2048? No — 8 warps/block -> BN/8 blocks
    (void)SG;

    k_init<<<(ACC_TOTAL+511)/512, 512>>>();
    k_build<<<WG, 256>>>(adj);
    k_xh_soft<<<BN/8, 256>>>(x, W1, b1, Wrw, brw, Wct, bct);
    k_ctpart<<<dim3(B, 8), 1024>>>();
    k_edges<<<BN/8, 256>>>();
    k_rwfin<<<1, 32>>>();
    k_ctfin<<<B, 1024>>>();
    k_agg<<<dim3(BN/8, 2), 256>>>();
    k_linsmc<<<dim3(BN/8, 2), 256>>>(Wg_rel, bg, Wg_root, Wmcg, bmcg,
                                     Wc_rel, bc, Wc_root, Wmcc, bmcc);
    k_t16<<<dim3(BN/8, 2), 256>>>();
    k_poolpart<<<dim3(8, B, 2), 256>>>();
    k_poolfin<<<dim3(B, 2), 512>>>(W2g_rel, b2g, W2g_root);
    k_readout<<<B, 32>>>(Wcat, bcat, W2, b2, W3, b3, out);

    (void)in_sizes; (void)n_in; (void)out_size;
}

// round 5
// speedup vs baseline: 2.4590x; 1.1335x over previous
#include <cuda_runtime.h>
#include <math.h>
#include <stdint.h>

#define B 16
#define N 1024
#define BN (B*N)
#define IN 128
#define H 32
#define KC 32
#define KM 16
#define MAXD 128
#define EPSV 1e-15f
#define FULL 0xffffffffu

// ---------------- accumulator slab (atomically accumulated; zeroed per run) --
#define ACC_NUMRW 0                    // [B]
#define ACC_DENRW 16                   // [B]
#define ACC_S00   32                   // [B]
#define ACC_S01   48                   // [B]
#define ACC_S11   64                   // [B]
#define ACC_SAS   80                   // [B]
#define ACC_DENCT 96                   // [B]
#define ACC_SDS   112                  // [B]
#define ACC_VOL   128                  // [B]
#define ACC_SSCT  144                  // [B][32*32]
#define ACC_OA    (ACC_SSCT+B*1024)    // [2][B][256]
#define ACC_SSP   (ACC_OA+2*B*256)     // [2][B][256]
#define ACC_PX    (ACC_SSP+2*B*256)    // [2][B][512]
#define ACC_DENP  (ACC_PX+2*B*512)     // [2][B]
#define ACC_LOSS  (ACC_DENP+2*B)       // [2] main, ortho
#define ACC_TOTAL (ACC_LOSS+2)

__device__ float g_acc[ACC_TOTAL];

// ---------------- scratch ----------------------------------------------------
__device__ float g_xh[BN*H];
__device__ int   g_cols[BN*MAXD];
__device__ int   g_deg[BN];
__device__ float g_srw[BN*2];
__device__ float g_sct[BN*KC];
__device__ float g_sqct[BN];
__device__ float g_wgap[BN*MAXD];
__device__ float g_wct[BN*MAXD];
__device__ float g_xg[2*BN*H];
__device__ float g_smc[2*BN*KM];
__device__ float g_x2[2*B*KM*H];

__device__ __forceinline__ float wsum(float v){
    #pragma unroll
    for(int o=16;o;o>>=1) v += __shfl_xor_sync(FULL, v, o);
    return v;
}
__device__ __forceinline__ float wsum16(float v){
    #pragma unroll
    for(int o=8;o;o>>=1) v += __shfl_xor_sync(FULL, v, o, 16);
    return v;
}

__global__ void k_init(){
    int i = blockIdx.x*blockDim.x + threadIdx.x;
    if (i < ACC_TOTAL) g_acc[i] = 0.f;
}

// fused: neighbor lists (float4 ballot compaction) + vol + xh=x@W1+b1 +
//        rewiring softmax(k=2) + CT softmax(k=32) + per-batch scalar partials
__global__ void k_build_soft(const float* __restrict__ adj, const float* __restrict__ x,
                             const float* __restrict__ W1,  const float* __restrict__ b1,
                             const float* __restrict__ Wrw, const float* __restrict__ brw,
                             const float* __restrict__ Wct, const float* __restrict__ bct){
    __shared__ float W1s[IN*H];      // 16 KB
    __shared__ float Wcts[H*KC];     // 4 KB
    __shared__ float svol[8];
    __shared__ float sh[6];
    for (int i = threadIdx.x; i < IN*H; i += blockDim.x) W1s[i] = W1[i];
    for (int i = threadIdx.x; i < H*KC; i += blockDim.x) Wcts[i] = Wct[i];
    if (threadIdx.x < 6) sh[threadIdx.x] = 0.f;
    __syncthreads();

    int wid = (blockIdx.x*blockDim.x + threadIdx.x) >> 5;
    int lane = threadIdx.x & 31;
    int wz = threadIdx.x >> 5;

    // ---- neighbor list ----
    const float4* row = (const float4*)(adj + (size_t)wid * N);
    int* cols = g_cols + (size_t)wid * MAXD;
    int cnt = 0;
    #pragma unroll 2
    for (int c = 0; c < N; c += 128){
        float4 v = row[(c>>2) + lane];
        bool n0=v.x!=0.f, n1=v.y!=0.f, n2=v.z!=0.f, n3=v.w!=0.f;
        unsigned m0=__ballot_sync(FULL,n0), m1=__ballot_sync(FULL,n1);
        unsigned m2=__ballot_sync(FULL,n2), m3=__ballot_sync(FULL,n3);
        unsigned below = (1u<<lane) - 1u;
        int idx = cnt + __popc(m0&below)+__popc(m1&below)+__popc(m2&below)+__popc(m3&below);
        int col0 = c + lane*4;
        if(n0 && idx<MAXD){ cols[idx]=col0;   idx++; }
        if(n1 && idx<MAXD){ cols[idx]=col0+1; idx++; }
        if(n2 && idx<MAXD){ cols[idx]=col0+2; idx++; }
        if(n3 && idx<MAXD){ cols[idx]=col0+3; idx++; }
        cnt += __popc(m0)+__popc(m1)+__popc(m2)+__popc(m3);
    }
    int deg = cnt < MAXD ? cnt : MAXD;
    if (lane == 0){ g_deg[wid] = deg; svol[wz] = (float)deg; }

    // ---- xh = x @ W1 + b1 (lane = h) ----
    float acc = b1[lane];
    const float* xr = x + (size_t)wid*IN;
    #pragma unroll
    for (int c = 0; c < 4; c++){
        float xv = xr[c*32 + lane];
        #pragma unroll
        for (int j = 0; j < 32; j++)
            acc += __shfl_sync(FULL, xv, j) * W1s[(c*32+j)*H + lane];
    }
    g_xh[wid*H + lane] = acc;

    // ---- rewiring softmax (k=2) ----
    float a0 = wsum(acc*Wrw[lane*2])   + brw[0];
    float a1 = wsum(acc*Wrw[lane*2+1]) + brw[1];
    float mm = fmaxf(a0,a1);
    float e0 = expf(a0-mm), e1 = expf(a1-mm);
    float inv = 1.f/(e0+e1);
    float s0 = e0*inv, s1 = e1*inv;
    if (lane == 0){ g_srw[2*wid]=s0; g_srw[2*wid+1]=s1; }

    // ---- CT softmax (k=32, lane = k) ----
    float a = bct[lane];
    #pragma unroll
    for (int j = 0; j < 32; j++)
        a += __shfl_sync(FULL, acc, j) * Wcts[j*KC + lane];
    float m = a;
    #pragma unroll
    for (int o = 16; o; o >>= 1) m = fmaxf(m, __shfl_xor_sync(FULL, m, o));
    float e = expf(a - m);
    float s = e / wsum(e);
    g_sct[wid*KC + lane] = s;
    float sq = wsum(s*s);
    if (lane == 0) g_sqct[wid] = sq;

    // ---- per-batch scalar partials ----
    if (lane == 0){
        atomicAdd(&sh[0], (float)deg*(s0*s0 + s1*s1)); // den_rw
        atomicAdd(&sh[1], s0*s0);                      // s00
        atomicAdd(&sh[2], s0*s1);                      // s01
        atomicAdd(&sh[3], s1*s1);                      // s11
        atomicAdd(&sh[4], sq);                         // den_ct
        atomicAdd(&sh[5], (float)deg*sq);              // sds
    }
    __syncthreads();
    int b = blockIdx.x >> 7;
    if (threadIdx.x < 6){
        const int dst[6] = {ACC_DENRW, ACC_S00, ACC_S01, ACC_S11, ACC_DENCT, ACC_SDS};
        atomicAdd(&g_acc[dst[threadIdx.x] + b], sh[threadIdx.x]);
    }
    if (threadIdx.x == 0){
        float vs = 0.f;
        #pragma unroll
        for (int i = 0; i < 8; i++) vs += svol[i];
        atomicAdd(&g_acc[ACC_VOL + b], vs);
    }
}

// S^T S partials from smem tiles (128-node chunks)
__global__ void k_ctpart(){
    int b = blockIdx.x >> 3, c = blockIdx.x & 7;
    int t = threadIdx.x;   // 1024
    __shared__ float S[128][33];
    int n0 = (b*N + c*128)*KC;
    #pragma unroll
    for (int i = 0; i < 4; i++){
        int idx = t + i*1024;
        S[idx>>5][idx&31] = g_sct[n0 + idx];
    }
    __syncthreads();
    int k = t >> 5, l = t & 31;
    float ssv = 0.f;
    #pragma unroll 8
    for (int n = 0; n < 128; n++)
        ssv += S[n][k]*S[n][l];
    atomicAdd(&g_acc[ACC_SSCT + b*1024 + t], ssv);
}

// per-edge: gap & CT weights (stored), num_rw and sas partials; 2x unroll for ILP
__global__ void k_edges(){
    int wid = (blockIdx.x*blockDim.x + threadIdx.x) >> 5;
    int lane = threadIdx.x & 31;
    int b = wid >> 10, bN = b << 10;
    int deg = g_deg[wid];
    const int* cols = g_cols + wid*MAXD;
    float f_n = g_srw[2*wid];
    float s1n = g_srw[2*wid+1];
    float sn  = g_sct[wid*KC + lane];
    float sqn = g_sqct[wid];
    float invvol = 1.f/(g_acc[ACC_VOL + b] + EPSV);
    float num_acc = 0.f, sas_acc = 0.f;
    int j = 0;
    for (; j + 1 < deg; j += 2){
        int mc0 = cols[j], mc1 = cols[j+1];
        float sm0 = g_sct[(bN+mc0)*KC + lane];
        float sm1 = g_sct[(bN+mc1)*KC + lane];
        float p0 = sn*sm0, p1 = sn*sm1;
        #pragma unroll
        for (int o = 16; o; o >>= 1){
            p0 += __shfl_xor_sync(FULL, p0, o);
            p1 += __shfl_xor_sync(FULL, p1, o);
        }
        float fa0 = g_srw[2*(bN+mc0)], fb0 = g_srw[2*(bN+mc0)+1];
        float fa1 = g_srw[2*(bN+mc1)], fb1 = g_srw[2*(bN+mc1)+1];
        float d0 = f_n - fa0, d1 = f_n - fa1;
        float q0 = sqn + g_sqct[bN+mc0] - 2.f*p0;
        float q1 = sqn + g_sqct[bN+mc1] - 2.f*p1;
        float dist0 = sqrtf(fmaxf(q0, 0.f) + 1e-12f);
        float dist1 = sqrtf(fmaxf(q1, 0.f) + 1e-12f);
        if (lane == 0){
            g_wgap[wid*MAXD + j]     = 1.f - d0*d0;
            g_wgap[wid*MAXD + j + 1] = 1.f - d1*d1;
            g_wct [wid*MAXD + j]     = dist0*invvol;
            g_wct [wid*MAXD + j + 1] = dist1*invvol;
        }
        num_acc += f_n*fa0 + s1n*fb0 + f_n*fa1 + s1n*fb1;
        sas_acc += p0 + p1;
    }
    if (j < deg){
        int mc = cols[j];
        float sm = g_sct[(bN+mc)*KC + lane];
        float dot = wsum(sn*sm);
        float fa = g_srw[2*(bN+mc)], fb = g_srw[2*(bN+mc)+1];
        float d = f_n - fa;
        float q = sqn + g_sqct[bN+mc] - 2.f*dot;
        if (lane == 0){
            g_wgap[wid*MAXD + j] = 1.f - d*d;
            g_wct [wid*MAXD + j] = sqrtf(fmaxf(q, 0.f) + 1e-12f)*invvol;
        }
        num_acc += f_n*fa + s1n*fb;
        sas_acc += dot;
    }
    __shared__ float sh[2];
    if (threadIdx.x < 2) sh[threadIdx.x] = 0.f;
    __syncthreads();
    if (lane == 0){
        atomicAdd(&sh[0], num_acc);
        atomicAdd(&sh[1], sas_acc);
    }
    __syncthreads();
    if (threadIdx.x < 2){
        const int dst[2] = {ACC_NUMRW, ACC_SAS};
        atomicAdd(&g_acc[dst[threadIdx.x] + (blockIdx.x>>7)], sh[threadIdx.x]);
    }
}

// CT losses (ortho over 32x32 S^T S + ct term) + rewiring losses (fused)
__global__ void k_ctfin(){
    int b = blockIdx.x, t = threadIdx.x;   // 1024
    __shared__ float ss[1024], red[1024], nrm_s;
    ss[t] = g_acc[ACC_SSCT + b*1024 + t];
    __syncthreads();
    red[t] = ss[t]*ss[t];
    __syncthreads();
    for (int o = 512; o; o >>= 1){ if (t < o) red[t] += red[t+o]; __syncthreads(); }
    if (t == 0) nrm_s = sqrtf(red[0]);
    __syncthreads();
    int k = t >> 5, l = t & 31;
    float d = ss[t]/nrm_s - ((k == l) ? 0.17677669529663687f : 0.f);
    red[t] = d*d;
    __syncthreads();
    for (int o = 512; o; o >>= 1){ if (t < o) red[t] += red[t+o]; __syncthreads(); }
    if (t == 0){
        float sas = g_acc[ACC_SAS + b];
        float den = g_acc[ACC_DENCT + b] + EPSV;
        float sds = g_acc[ACC_SDS + b];
        float lm = ((sds - sas)/den)/(float)B;
        float lo = sqrtf(red[0])/(float)B;
        // fused rewiring losses for this batch
        float num = g_acc[ACC_NUMRW + b];
        float dnr = g_acc[ACC_DENRW + b] + EPSV;
        float s00 = g_acc[ACC_S00 + b];
        float s01 = g_acc[ACC_S01 + b];
        float s11 = g_acc[ACC_S11 + b];
        float nrm = sqrtf(s00*s00 + 2.f*s01*s01 + s11*s11);
        const float isk = 0.70710678118654752f;
        float d00 = s00/nrm - isk, d01 = s01/nrm, d11 = s11/nrm - isk;
        lm += -(num/dnr)/(float)B;
        lo += sqrtf(d00*d00 + 2.f*d01*d01 + d11*d11)/(float)B;
        atomicAdd(&g_acc[ACC_LOSS],   lm);
        atomicAdd(&g_acc[ACC_LOSS+1], lo);
    }
}

// fused: y = A_w @ xh ; xg = y@Wrel + brel + xh@Wroot ; smc = softmax(xg@Wmc+bmc)
//        den_pool partial (dnew * ||s||^2). Both branches via blockIdx.y.
__global__ void k_agglin(const float* __restrict__ Wr0, const float* __restrict__ br0,
                         const float* __restrict__ Wo0, const float* __restrict__ Wm0,
                         const float* __restrict__ bm0,
                         const float* __restrict__ Wr1, const float* __restrict__ br1,
                         const float* __restrict__ Wo1, const float* __restrict__ Wm1,
                         const float* __restrict__ bm1){
    int br = blockIdx.y;
    __shared__ float Wrs[H*H], Wos[H*H], Wms[H*KM];
    __shared__ float shden;
    {
        const float* Wrel  = br ? Wr1 : Wr0;
        const float* Wroot = br ? Wo1 : Wo0;
        const float* Wmc   = br ? Wm1 : Wm0;
        for (int i = threadIdx.x; i < H*H; i += blockDim.x){ Wrs[i]=Wrel[i]; Wos[i]=Wroot[i]; }
        for (int i = threadIdx.x; i < H*KM; i += blockDim.x) Wms[i]=Wmc[i];
        if (threadIdx.x == 0) shden = 0.f;
    }
    __syncthreads();
    const float* brel = br ? br1 : br0;
    const float* bmc  = br ? bm1 : bm0;

    int wid = (blockIdx.x*blockDim.x + threadIdx.x) >> 5;
    int lane = threadIdx.x & 31;
    int bN = (wid >> 10) << 10;
    int deg = g_deg[wid];
    const int* cols = g_cols + wid*MAXD;
    const float* w_arr = (br ? g_wct : g_wgap) + wid*MAXD;

    float y = 0.f, dsum = 0.f;
    for (int j = 0; j < deg; j++){
        int m = cols[j];
        float w = w_arr[j];
        y    += w * g_xh[(bN+m)*H + lane];
        dsum += w;
    }
    float xh = g_xh[wid*H + lane];
    float acc = brel[lane];
    #pragma unroll
    for (int j = 0; j < 32; j++){
        acc += __shfl_sync(FULL, y,  j) * Wrs[j*H + lane];
        acc += __shfl_sync(FULL, xh, j) * Wos[j*H + lane];
    }
    g_xg[br*BN*H + wid*H + lane] = acc;

    float a = (lane < KM) ? bmc[lane] : 0.f;
    #pragma unroll
    for (int j = 0; j < 32; j++){
        float xj = __shfl_sync(FULL, acc, j);
        if (lane < KM) a += xj * Wms[j*KM + lane];
    }
    float mm = a;
    #pragma unroll
    for (int o = 8; o; o >>= 1) mm = fmaxf(mm, __shfl_xor_sync(FULL, mm, o, 16));
    float e = (lane < KM) ? expf(a - mm) : 0.f;
    float es = wsum16(e);
    float s = e/es;
    if (lane < KM) g_smc[br*BN*KM + wid*KM + lane] = s;
    float sq = wsum16(s*s);
    if (lane == 0) atomicAdd(&shden, dsum*sq);
    __syncthreads();
    if (threadIdx.x == 0)
        atomicAdd(&g_acc[ACC_DENP + br*B + (blockIdx.x>>7)], shden);
}

// fused t16 + pooled partials over 32-node chunks
__global__ void k_pool(){
    int c = blockIdx.x, b = blockIdx.y, br = blockIdx.z;
    int t = threadIdx.x;              // 1024 = 32 warps
    int w = t >> 5, lane = t & 31;
    __shared__ float ssmc[32][17];    // [node][cluster] (pad)
    __shared__ float st16[32][17];
    __shared__ float sxg[32][33];     // [node][h]
    const float* smc = g_smc + br*BN*KM;
    const float* xg  = g_xg  + br*BN*H;
    int bN = b*N;
    int r = bN + c*32 + w;            // warp w handles node r
    // phase 1: load smc/xg rows, compute t16 row inline
    if (lane < KM) ssmc[w][lane] = smc[r*KM + lane];
    sxg[w][lane] = xg[r*H + lane];
    {
        int deg = g_deg[r];
        const int* cols = g_cols + r*MAXD;
        const float* w_arr = (br ? g_wct : g_wgap) + r*MAXD;
        float tacc = 0.f;
        for (int j = 0; j < deg; j++){
            int m = cols[j];
            float wv = w_arr[j];
            if (lane < KM) tacc += wv * smc[(bN+m)*KM + lane];
        }
        if (lane < KM) st16[w][lane] = tacc;
    }
    __syncthreads();
    // phase 2
    int base = (br*B + b)*256;
    if (t < 256){
        int k = t >> 4, l = t & 15;
        float oa = 0.f;
        #pragma unroll 8
        for (int n = 0; n < 32; n++) oa += ssmc[n][k]*st16[n][l];
        atomicAdd(&g_acc[ACC_OA + base + t], oa);
    } else if (t < 512){
        int k = (t-256) >> 4, l = t & 15;
        float ssv = 0.f;
        #pragma unroll 8
        for (int n = 0; n < 32; n++) ssv += ssmc[n][k]*ssmc[n][l];
        atomicAdd(&g_acc[ACC_SSP + base + (t-256)], ssv);
    } else {
        int kk = (t-512) >> 5, h = t & 31;
        float px = 0.f;
        #pragma unroll 8
        for (int n = 0; n < 32; n++) px += ssmc[n][kk]*sxg[n][h];
        atomicAdd(&g_acc[ACC_PX + (br*B + b)*512 + (t-512)], px);
    }
}

// finalize pool: losses + normalized pooladj + pooled DGC (conv2gap weights)
__global__ void k_poolfin(const float* __restrict__ W2g_rel, const float* __restrict__ b2g,
                          const float* __restrict__ W2g_root){
    int b = blockIdx.x, br = blockIdx.y, t = threadIdx.x;   // 512
    __shared__ float oa[256], ssm[256], px[512], t2[512], pa[256], red[512], nrm_s;
    int base = (br*B + b)*256;
    if (t < 256){ oa[t] = g_acc[ACC_OA + base + t]; ssm[t] = g_acc[ACC_SSP + base + t]; }
    px[t] = g_acc[ACC_PX + (br*B + b)*512 + t];
    __syncthreads();
    red[t] = (t < 256) ? ssm[t]*ssm[t] : 0.f;
    __syncthreads();
    for (int o = 256; o; o >>= 1){ if (t < o) red[t] += red[t+o]; __syncthreads(); }
    if (t == 0) nrm_s = sqrtf(red[0]);
    __syncthreads();
    if (t < 256){
        int k = t >> 4, l = t & 15;
        float d = ssm[t]/nrm_s - ((k == l) ? 0.25f : 0.f);
        red[t] = d*d;
    } else red[t] = 0.f;
    __syncthreads();
    for (int o = 256; o; o >>= 1){ if (t < o) red[t] += red[t+o]; __syncthreads(); }
    if (t == 0){
        float num = 0.f;
        #pragma unroll
        for (int k = 0; k < KM; k++) num += oa[k*KM + k];
        float den = g_acc[ACC_DENP + br*B + b] + EPSV;
        atomicAdd(&g_acc[ACC_LOSS],   -(num/den)/(float)B);
        atomicAdd(&g_acc[ACC_LOSS+1], sqrtf(red[0])/(float)B);
    }
    __shared__ float dsq[KM];
    if (t < KM){
        float rs = 0.f;
        #pragma unroll
        for (int l = 0; l < KM; l++) rs += (l == t) ? 0.f : oa[t*KM + l];
        dsq[t] = sqrtf(rs) + EPSV;
    }
    __syncthreads();
    if (t < 256){
        int k = t >> 4, l = t & 15;
        pa[t] = (k == l) ? 0.f : oa[t]/(dsq[k]*dsq[l]);
    }
    __syncthreads();
    int k = t >> 5, h = t & 31;
    float a = 0.f;
    #pragma unroll
    for (int l = 0; l < KM; l++) a += pa[k*KM + l]*px[l*H + h];
    t2[t] = a;
    __syncthreads();
    float accv = b2g[h];
    #pragma unroll
    for (int j = 0; j < H; j++)
        accv += t2[k*H + j]*W2g_rel[j*H + h] + px[k*H + j]*W2g_root[j*H + h];
    g_x2[br*B*KM*H + b*KM*H + t] = accv;
}

__global__ void k_readout(const float* __restrict__ Wcat, const float* __restrict__ bcat,
                          const float* __restrict__ W2,  const float* __restrict__ b2,
                          const float* __restrict__ W3,  const float* __restrict__ b3,
                          float* __restrict__ out){
    int b = blockIdx.x, h = threadIdx.x;   // 32
    __shared__ float h1[H], h2[H], lg[10];
    float acc = 0.f;
    for (int kk = 0; kk < KM; kk++){
        float z = bcat[h];
        #pragma unroll
        for (int j = 0; j < H; j++) z += g_x2[b*KM*H + kk*H + j]*Wcat[j*H + h];
        #pragma unroll
        for (int j = 0; j < H; j++) z += g_x2[B*KM*H + b*KM*H + kk*H + j]*Wcat[(H+j)*H + h];
        acc += fmaxf(z, 0.f);
    }
    h1[h] = acc; __syncwarp();
    float z2 = b2[h];
    #pragma unroll
    for (int j = 0; j < H; j++) z2 += h1[j]*W2[j*H + h];
    h2[h] = fmaxf(z2, 0.f); __syncwarp();
    if (h < 10){
        float z = b3[h];
        #pragma unroll
        for (int j = 0; j < H; j++) z += h2[j]*W3[j*10 + h];
        lg[h] = z;
    }
    __syncwarp();
    if (h < 10){
        float m = lg[0];
        #pragma unroll
        for (int i = 1; i < 10; i++) m = fmaxf(m, lg[i]);
        float s = 0.f;
        #pragma unroll
        for (int i = 0; i < 10; i++) s += expf(lg[i] - m);
        out[b*10 + h] = lg[h] - m - logf(s);
    }
    if (b == 0 && h == 31){
        out[B*10]     = g_acc[ACC_LOSS];
        out[B*10 + 1] = g_acc[ACC_LOSS+1];
    }
}

extern "C" void kernel_launch(void* const* d_in, const int* in_sizes, int n_in,
                              void* d_out, int out_size){
    const float* x      = (const float*)d_in[0];
    const float* adj    = (const float*)d_in[1];
    const float* W1     = (const float*)d_in[3];
    const float* b1     = (const float*)d_in[4];
    const float* Wrw    = (const float*)d_in[5];
    const float* brw    = (const float*)d_in[6];
    const float* Wg_rel = (const float*)d_in[7];
    const float* bg     = (const float*)d_in[8];
    const float* Wg_root= (const float*)d_in[9];
    const float* Wmcg   = (const float*)d_in[10];
    const float* bmcg   = (const float*)d_in[11];
    const float* W2g_rel= (const float*)d_in[12];
    const float* b2g    = (const float*)d_in[13];
    const float* W2g_root=(const float*)d_in[14];
    const float* Wct    = (const float*)d_in[15];
    const float* bct    = (const float*)d_in[16];
    const float* Wc_rel = (const float*)d_in[17];
    const float* bc     = (const float*)d_in[18];
    const float* Wc_root= (const float*)d_in[19];
    const float* Wmcc   = (const float*)d_in[20];
    const float* bmcc   = (const float*)d_in[21];
    const float* Wcat   = (const float*)d_in[22];
    const float* bcat   = (const float*)d_in[23];
    const float* W2     = (const float*)d_in[24];
    const float* b2     = (const float*)d_in[25];
    const float* W3     = (const float*)d_in[26];
    const float* b3     = (const float*)d_in[27];
    float* out = (float*)d_out;

    k_init<<<(ACC_TOTAL+511)/512, 512>>>();
    k_build_soft<<<BN/8, 256>>>(adj, x, W1, b1, Wrw, brw, Wct, bct);
    k_ctpart<<<B*8, 1024>>>();
    k_edges<<<BN/8, 256>>>();
    k_ctfin<<<B, 1024>>>();
    k_agglin<<<dim3(BN/8, 2), 256>>>(Wg_rel, bg, Wg_root, Wmcg, bmcg,
                                     Wc_rel, bc, Wc_root, Wmcc, bmcc);
    k_pool<<<dim3(32, B, 2), 1024>>>();
    k_poolfin<<<dim3(B, 2), 512>>>(W2g_rel, b2g, W2g_root);
    k_readout<<<B, 32>>>(Wcat, bcat, W2, b2, W3, b3, out);

    (void)in_sizes; (void)n_in; (void)out_size;
}

// round 6
// speedup vs baseline: 2.6819x; 1.0906x over previous
#include <cuda_runtime.h>
#include <math.h>
#include <stdint.h>

#define B 16
#define N 1024
#define BN (B*N)
#define IN 128
#define H 32
#define KC 32
#define KM 16
#define MAXD 128
#define EPSV 1e-15f
#define FULL 0xffffffffu

// ---------------- accumulator slab (atomically accumulated; zeroed per run) --
#define ACC_NUMRW 0                    // [B]
#define ACC_DENRW 16                   // [B]
#define ACC_S00   32                   // [B]
#define ACC_S01   48                   // [B]
#define ACC_S11   64                   // [B]
#define ACC_SAS   80                   // [B]
#define ACC_DENCT 96                   // [B]
#define ACC_SDS   112                  // [B]
#define ACC_VOL   128                  // [B]
#define ACC_SSCT  144                  // [B][32*32]
#define ACC_OA    (ACC_SSCT+B*1024)    // [2][B][256]
#define ACC_SSP   (ACC_OA+2*B*256)     // [2][B][256]
#define ACC_PX    (ACC_SSP+2*B*256)    // [2][B][512]
#define ACC_DENP  (ACC_PX+2*B*512)     // [2][B]
#define ACC_LOSS  (ACC_DENP+2*B)       // [2] main, ortho
#define ACC_TOTAL (ACC_LOSS+2)

__device__ float g_acc[ACC_TOTAL];

// ---------------- scratch ----------------------------------------------------
__device__ float g_xh[BN*H];
__device__ int   g_cols[BN*MAXD];
__device__ int   g_deg[BN];
__device__ float g_srw[BN*2];
__device__ float g_sct[BN*KC];
__device__ float g_sqct[BN];
__device__ float g_wgap[BN*MAXD];
__device__ float g_wct[BN*MAXD];
__device__ float g_xg[2*BN*H];
__device__ float g_smc[2*BN*KM];
__device__ float g_x2[2*B*KM*H];

__device__ __forceinline__ float wsum(float v){
    #pragma unroll
    for(int o=16;o;o>>=1) v += __shfl_xor_sync(FULL, v, o);
    return v;
}
__device__ __forceinline__ float wsum16(float v){
    #pragma unroll
    for(int o=8;o;o>>=1) v += __shfl_xor_sync(FULL, v, o, 16);
    return v;
}

__global__ void k_init(){
    int i = blockIdx.x*blockDim.x + threadIdx.x;
    if (i < ACC_TOTAL) g_acc[i] = 0.f;
}

// fused: neighbor lists (float4 ballot compaction) + vol + xh=x@W1+b1 +
//        rewiring softmax(k=2) + CT softmax(k=32) + per-batch scalar partials
__global__ void k_build_soft(const float* __restrict__ adj, const float* __restrict__ x,
                             const float* __restrict__ W1,  const float* __restrict__ b1,
                             const float* __restrict__ Wrw, const float* __restrict__ brw,
                             const float* __restrict__ Wct, const float* __restrict__ bct){
    __shared__ float W1s[IN*H];      // 16 KB
    __shared__ float Wcts[H*KC];     // 4 KB
    __shared__ float svol[8];
    __shared__ float sh[6];
    for (int i = threadIdx.x; i < IN*H; i += blockDim.x) W1s[i] = W1[i];
    for (int i = threadIdx.x; i < H*KC; i += blockDim.x) Wcts[i] = Wct[i];
    if (threadIdx.x < 6) sh[threadIdx.x] = 0.f;
    __syncthreads();

    int wid = (blockIdx.x*blockDim.x + threadIdx.x) >> 5;
    int lane = threadIdx.x & 31;
    int wz = threadIdx.x >> 5;

    // ---- neighbor list ----
    const float4* row = (const float4*)(adj + (size_t)wid * N);
    int* cols = g_cols + (size_t)wid * MAXD;
    int cnt = 0;
    #pragma unroll 2
    for (int c = 0; c < N; c += 128){
        float4 v = row[(c>>2) + lane];
        bool n0=v.x!=0.f, n1=v.y!=0.f, n2=v.z!=0.f, n3=v.w!=0.f;
        unsigned m0=__ballot_sync(FULL,n0), m1=__ballot_sync(FULL,n1);
        unsigned m2=__ballot_sync(FULL,n2), m3=__ballot_sync(FULL,n3);
        unsigned below = (1u<<lane) - 1u;
        int idx = cnt + __popc(m0&below)+__popc(m1&below)+__popc(m2&below)+__popc(m3&below);
        int col0 = c + lane*4;
        if(n0 && idx<MAXD){ cols[idx]=col0;   idx++; }
        if(n1 && idx<MAXD){ cols[idx]=col0+1; idx++; }
        if(n2 && idx<MAXD){ cols[idx]=col0+2; idx++; }
        if(n3 && idx<MAXD){ cols[idx]=col0+3; idx++; }
        cnt += __popc(m0)+__popc(m1)+__popc(m2)+__popc(m3);
    }
    int deg = cnt < MAXD ? cnt : MAXD;
    if (lane == 0){ g_deg[wid] = deg; svol[wz] = (float)deg; }

    // ---- xh = x @ W1 + b1 (lane = h) ----
    float acc = b1[lane];
    const float* xr = x + (size_t)wid*IN;
    #pragma unroll
    for (int c = 0; c < 4; c++){
        float xv = xr[c*32 + lane];
        #pragma unroll
        for (int j = 0; j < 32; j++)
            acc += __shfl_sync(FULL, xv, j) * W1s[(c*32+j)*H + lane];
    }
    g_xh[wid*H + lane] = acc;

    // ---- rewiring softmax (k=2) ----
    float a0 = wsum(acc*Wrw[lane*2])   + brw[0];
    float a1 = wsum(acc*Wrw[lane*2+1]) + brw[1];
    float mm = fmaxf(a0,a1);
    float e0 = expf(a0-mm), e1 = expf(a1-mm);
    float inv = 1.f/(e0+e1);
    float s0 = e0*inv, s1 = e1*inv;
    if (lane == 0){ g_srw[2*wid]=s0; g_srw[2*wid+1]=s1; }

    // ---- CT softmax (k=32, lane = k) ----
    float a = bct[lane];
    #pragma unroll
    for (int j = 0; j < 32; j++)
        a += __shfl_sync(FULL, acc, j) * Wcts[j*KC + lane];
    float m = a;
    #pragma unroll
    for (int o = 16; o; o >>= 1) m = fmaxf(m, __shfl_xor_sync(FULL, m, o));
    float e = expf(a - m);
    float s = e / wsum(e);
    g_sct[wid*KC + lane] = s;
    float sq = wsum(s*s);
    if (lane == 0) g_sqct[wid] = sq;

    // ---- per-batch scalar partials ----
    if (lane == 0){
        atomicAdd(&sh[0], (float)deg*(s0*s0 + s1*s1)); // den_rw
        atomicAdd(&sh[1], s0*s0);                      // s00
        atomicAdd(&sh[2], s0*s1);                      // s01
        atomicAdd(&sh[3], s1*s1);                      // s11
        atomicAdd(&sh[4], sq);                         // den_ct
        atomicAdd(&sh[5], (float)deg*sq);              // sds
    }
    __syncthreads();
    int b = blockIdx.x >> 7;
    if (threadIdx.x < 6){
        const int dst[6] = {ACC_DENRW, ACC_S00, ACC_S01, ACC_S11, ACC_DENCT, ACC_SDS};
        atomicAdd(&g_acc[dst[threadIdx.x] + b], sh[threadIdx.x]);
    }
    if (threadIdx.x == 0){
        float vs = 0.f;
        #pragma unroll
        for (int i = 0; i < 8; i++) vs += svol[i];
        atomicAdd(&g_acc[ACC_VOL + b], vs);
    }
}

// S^T S partials from smem tiles (128-node chunks)
__global__ void k_ctpart(){
    int b = blockIdx.x >> 3, c = blockIdx.x & 7;
    int t = threadIdx.x;   // 1024
    __shared__ float S[128][33];
    int n0 = (b*N + c*128)*KC;
    #pragma unroll
    for (int i = 0; i < 4; i++){
        int idx = t + i*1024;
        S[idx>>5][idx&31] = g_sct[n0 + idx];
    }
    __syncthreads();
    int k = t >> 5, l = t & 31;
    float ssv = 0.f;
    #pragma unroll 8
    for (int n = 0; n < 128; n++)
        ssv += S[n][k]*S[n][l];
    atomicAdd(&g_acc[ACC_SSCT + b*1024 + t], ssv);
}

// per-edge: gap & CT weights + num_rw/sas partials. LANE-PER-EDGE layout:
// warp = node, lane j = edge j; the 32-dim CT dot is serial per lane
// (8x float4 loads + 32 independent shfl broadcasts), no dependent
// reduction chain; weight stores are coalesced.
__global__ void k_edges(){
    int wid = (blockIdx.x*blockDim.x + threadIdx.x) >> 5;
    int lane = threadIdx.x & 31;
    int b = wid >> 10, bN = b << 10;
    int deg = g_deg[wid];
    const int* cols = g_cols + wid*MAXD;
    float f_n = g_srw[2*wid];
    float s1n = g_srw[2*wid+1];
    float sn  = g_sct[wid*KC + lane];     // lane holds s_n[lane]
    float sqn = g_sqct[wid];
    float invvol = 1.f/(g_acc[ACC_VOL + b] + EPSV);
    float num_acc = 0.f, sas_acc = 0.f;

    for (int j0 = 0; j0 < deg; j0 += 32){
        int j = j0 + lane;
        bool act = j < deg;
        int mc = act ? cols[j] : 0;
        int rm = bN + mc;
        const float4* smrow = (const float4*)(g_sct + (size_t)rm*KC);
        float dot = 0.f;
        #pragma unroll
        for (int q = 0; q < 8; q++){
            float4 v = act ? smrow[q] : make_float4(0.f,0.f,0.f,0.f);
            dot += __shfl_sync(FULL, sn, 4*q+0) * v.x;
            dot += __shfl_sync(FULL, sn, 4*q+1) * v.y;
            dot += __shfl_sync(FULL, sn, 4*q+2) * v.z;
            dot += __shfl_sync(FULL, sn, 4*q+3) * v.w;
        }
        if (act){
            float fa = g_srw[2*rm];
            float fb = g_srw[2*rm+1];
            float sq2 = g_sqct[rm];
            float d = f_n - fa;
            float q2 = sqn + sq2 - 2.f*dot;
            g_wgap[wid*MAXD + j] = 1.f - d*d;
            g_wct [wid*MAXD + j] = sqrtf(fmaxf(q2, 0.f) + 1e-12f)*invvol;
            num_acc += f_n*fa + s1n*fb;
            sas_acc += dot;
        }
    }
    num_acc = wsum(num_acc);
    sas_acc = wsum(sas_acc);

    __shared__ float sh[2];
    if (threadIdx.x < 2) sh[threadIdx.x] = 0.f;
    __syncthreads();
    if (lane == 0){
        atomicAdd(&sh[0], num_acc);
        atomicAdd(&sh[1], sas_acc);
    }
    __syncthreads();
    if (threadIdx.x < 2){
        const int dst[2] = {ACC_NUMRW, ACC_SAS};
        atomicAdd(&g_acc[dst[threadIdx.x] + (blockIdx.x>>7)], sh[threadIdx.x]);
    }
}

// CT losses (ortho over 32x32 S^T S + ct term) + rewiring losses (fused)
__global__ void k_ctfin(){
    int b = blockIdx.x, t = threadIdx.x;   // 1024
    __shared__ float ss[1024], red[1024], nrm_s;
    ss[t] = g_acc[ACC_SSCT + b*1024 + t];
    __syncthreads();
    red[t] = ss[t]*ss[t];
    __syncthreads();
    for (int o = 512; o; o >>= 1){ if (t < o) red[t] += red[t+o]; __syncthreads(); }
    if (t == 0) nrm_s = sqrtf(red[0]);
    __syncthreads();
    int k = t >> 5, l = t & 31;
    float d = ss[t]/nrm_s - ((k == l) ? 0.17677669529663687f : 0.f);
    red[t] = d*d;
    __syncthreads();
    for (int o = 512; o; o >>= 1){ if (t < o) red[t] += red[t+o]; __syncthreads(); }
    if (t == 0){
        float sas = g_acc[ACC_SAS + b];
        float den = g_acc[ACC_DENCT + b] + EPSV;
        float sds = g_acc[ACC_SDS + b];
        float lm = ((sds - sas)/den)/(float)B;
        float lo = sqrtf(red[0])/(float)B;
        float num = g_acc[ACC_NUMRW + b];
        float dnr = g_acc[ACC_DENRW + b] + EPSV;
        float s00 = g_acc[ACC_S00 + b];
        float s01 = g_acc[ACC_S01 + b];
        float s11 = g_acc[ACC_S11 + b];
        float nrm = sqrtf(s00*s00 + 2.f*s01*s01 + s11*s11);
        const float isk = 0.70710678118654752f;
        float d00 = s00/nrm - isk, d01 = s01/nrm, d11 = s11/nrm - isk;
        lm += -(num/dnr)/(float)B;
        lo += sqrtf(d00*d00 + 2.f*d01*d01 + d11*d11)/(float)B;
        atomicAdd(&g_acc[ACC_LOSS],   lm);
        atomicAdd(&g_acc[ACC_LOSS+1], lo);
    }
}

// fused: y = A_w @ xh ; xg = y@Wrel + brel + xh@Wroot ; smc = softmax(xg@Wmc+bmc)
//        den_pool partial (dnew * ||s||^2). Both branches via blockIdx.y.
__global__ void k_agglin(const float* __restrict__ Wr0, const float* __restrict__ br0,
                         const float* __restrict__ Wo0, const float* __restrict__ Wm0,
                         const float* __restrict__ bm0,
                         const float* __restrict__ Wr1, const float* __restrict__ br1,
                         const float* __restrict__ Wo1, const float* __restrict__ Wm1,
                         const float* __restrict__ bm1){
    int br = blockIdx.y;
    __shared__ float Wrs[H*H], Wos[H*H], Wms[H*KM];
    __shared__ float shden;
    {
        const float* Wrel  = br ? Wr1 : Wr0;
        const float* Wroot = br ? Wo1 : Wo0;
        const float* Wmc   = br ? Wm1 : Wm0;
        for (int i = threadIdx.x; i < H*H; i += blockDim.x){ Wrs[i]=Wrel[i]; Wos[i]=Wroot[i]; }
        for (int i = threadIdx.x; i < H*KM; i += blockDim.x) Wms[i]=Wmc[i];
        if (threadIdx.x == 0) shden = 0.f;
    }
    __syncthreads();
    const float* brel = br ? br1 : br0;
    const float* bmc  = br ? bm1 : bm0;

    int wid = (blockIdx.x*blockDim.x + threadIdx.x) >> 5;
    int lane = threadIdx.x & 31;
    int bN = (wid >> 10) << 10;
    int deg = g_deg[wid];
    const int* cols = g_cols + wid*MAXD;
    const float* w_arr = (br ? g_wct : g_wgap) + wid*MAXD;

    float y = 0.f, dsum = 0.f;
    for (int j = 0; j < deg; j++){
        int m = cols[j];
        float w = w_arr[j];
        y    += w * g_xh[(bN+m)*H + lane];
        dsum += w;
    }
    float xh = g_xh[wid*H + lane];
    float acc = brel[lane];
    #pragma unroll
    for (int j = 0; j < 32; j++){
        acc += __shfl_sync(FULL, y,  j) * Wrs[j*H + lane];
        acc += __shfl_sync(FULL, xh, j) * Wos[j*H + lane];
    }
    g_xg[br*BN*H + wid*H + lane] = acc;

    float a = (lane < KM) ? bmc[lane] : 0.f;
    #pragma unroll
    for (int j = 0; j < 32; j++){
        float xj = __shfl_sync(FULL, acc, j);
        if (lane < KM) a += xj * Wms[j*KM + lane];
    }
    float mm = a;
    #pragma unroll
    for (int o = 8; o; o >>= 1) mm = fmaxf(mm, __shfl_xor_sync(FULL, mm, o, 16));
    float e = (lane < KM) ? expf(a - mm) : 0.f;
    float es = wsum16(e);
    float s = e/es;
    if (lane < KM) g_smc[br*BN*KM + wid*KM + lane] = s;
    float sq = wsum16(s*s);
    if (lane == 0) atomicAdd(&shden, dsum*sq);
    __syncthreads();
    if (threadIdx.x == 0)
        atomicAdd(&g_acc[ACC_DENP + br*B + (blockIdx.x>>7)], shden);
}

// fused t16 + pooled partials over 32-node chunks
__global__ void k_pool(){
    int c = blockIdx.x, b = blockIdx.y, br = blockIdx.z;
    int t = threadIdx.x;              // 1024 = 32 warps
    int w = t >> 5, lane = t & 31;
    __shared__ float ssmc[32][17];    // [node][cluster] (pad)
    __shared__ float st16[32][17];
    __shared__ float sxg[32][33];     // [node][h]
    const float* smc = g_smc + br*BN*KM;
    const float* xg  = g_xg  + br*BN*H;
    int bN = b*N;
    int r = bN + c*32 + w;            // warp w handles node r
    if (lane < KM) ssmc[w][lane] = smc[r*KM + lane];
    sxg[w][lane] = xg[r*H + lane];
    {
        int deg = g_deg[r];
        const int* cols = g_cols + r*MAXD;
        const float* w_arr = (br ? g_wct : g_wgap) + r*MAXD;
        float tacc = 0.f;
        for (int j = 0; j < deg; j++){
            int m = cols[j];
            float wv = w_arr[j];
            if (lane < KM) tacc += wv * smc[(bN+m)*KM + lane];
        }
        if (lane < KM) st16[w][lane] = tacc;
    }
    __syncthreads();
    int base = (br*B + b)*256;
    if (t < 256){
        int k = t >> 4, l = t & 15;
        float oa = 0.f;
        #pragma unroll 8
        for (int n = 0; n < 32; n++) oa += ssmc[n][k]*st16[n][l];
        atomicAdd(&g_acc[ACC_OA + base + t], oa);
    } else if (t < 512){
        int k = (t-256) >> 4, l = t & 15;
        float ssv = 0.f;
        #pragma unroll 8
        for (int n = 0; n < 32; n++) ssv += ssmc[n][k]*ssmc[n][l];
        atomicAdd(&g_acc[ACC_SSP + base + (t-256)], ssv);
    } else {
        int kk = (t-512) >> 5, h = t & 31;
        float px = 0.f;
        #pragma unroll 8
        for (int n = 0; n < 32; n++) px += ssmc[n][kk]*sxg[n][h];
        atomicAdd(&g_acc[ACC_PX + (br*B + b)*512 + (t-512)], px);
    }
}

// finalize pool: losses + normalized pooladj + pooled DGC (conv2gap weights)
__global__ void k_poolfin(const float* __restrict__ W2g_rel, const float* __restrict__ b2g,
                          const float* __restrict__ W2g_root){
    int b = blockIdx.x, br = blockIdx.y, t = threadIdx.x;   // 512
    __shared__ float oa[256], ssm[256], px[512], t2[512], pa[256], red[512], nrm_s;
    int base = (br*B + b)*256;
    if (t < 256){ oa[t] = g_acc[ACC_OA + base + t]; ssm[t] = g_acc[ACC_SSP + base + t]; }
    px[t] = g_acc[ACC_PX + (br*B + b)*512 + t];
    __syncthreads();
    red[t] = (t < 256) ? ssm[t]*ssm[t] : 0.f;
    __syncthreads();
    for (int o = 256; o; o >>= 1){ if (t < o) red[t] += red[t+o]; __syncthreads(); }
    if (t == 0) nrm_s = sqrtf(red[0]);
    __syncthreads();
    if (t < 256){
        int k = t >> 4, l = t & 15;
        float d = ssm[t]/nrm_s - ((k == l) ? 0.25f : 0.f);
        red[t] = d*d;
    } else red[t] = 0.f;
    __syncthreads();
    for (int o = 256; o; o >>= 1){ if (t < o) red[t] += red[t+o]; __syncthreads(); }
    if (t == 0){
        float num = 0.f;
        #pragma unroll
        for (int k = 0; k < KM; k++) num += oa[k*KM + k];
        float den = g_acc[ACC_DENP + br*B + b] + EPSV;
        atomicAdd(&g_acc[ACC_LOSS],   -(num/den)/(float)B);
        atomicAdd(&g_acc[ACC_LOSS+1], sqrtf(red[0])/(float)B);
    }
    __shared__ float dsq[KM];
    if (t < KM){
        float rs = 0.f;
        #pragma unroll
        for (int l = 0; l < KM; l++) rs += (l == t) ? 0.f : oa[t*KM + l];
        dsq[t] = sqrtf(rs) + EPSV;
    }
    __syncthreads();
    if (t < 256){
        int k = t >> 4, l = t & 15;
        pa[t] = (k == l) ? 0.f : oa[t]/(dsq[k]*dsq[l]);
    }
    __syncthreads();
    int k = t >> 5, h = t & 31;
    float a = 0.f;
    #pragma unroll
    for (int l = 0; l < KM; l++) a += pa[k*KM + l]*px[l*H + h];
    t2[t] = a;
    __syncthreads();
    float accv = b2g[h];
    #pragma unroll
    for (int j = 0; j < H; j++)
        accv += t2[k*H + j]*W2g_rel[j*H + h] + px[k*H + j]*W2g_root[j*H + h];
    g_x2[br*B*KM*H + b*KM*H + t] = accv;
}

__global__ void k_readout(const float* __restrict__ Wcat, const float* __restrict__ bcat,
                          const float* __restrict__ W2,  const float* __restrict__ b2,
                          const float* __restrict__ W3,  const float* __restrict__ b3,
                          float* __restrict__ out){
    int b = blockIdx.x, h = threadIdx.x;   // 32
    __shared__ float h1[H], h2[H], lg[10];
    float acc = 0.f;
    for (int kk = 0; kk < KM; kk++){
        float z = bcat[h];
        #pragma unroll
        for (int j = 0; j < H; j++) z += g_x2[b*KM*H + kk*H + j]*Wcat[j*H + h];
        #pragma unroll
        for (int j = 0; j < H; j++) z += g_x2[B*KM*H + b*KM*H + kk*H + j]*Wcat[(H+j)*H + h];
        acc += fmaxf(z, 0.f);
    }
    h1[h] = acc; __syncwarp();
    float z2 = b2[h];
    #pragma unroll
    for (int j = 0; j < H; j++) z2 += h1[j]*W2[j*H + h];
    h2[h] = fmaxf(z2, 0.f); __syncwarp();
    if (h < 10){
        float z = b3[h];
        #pragma unroll
        for (int j = 0; j < H; j++) z += h2[j]*W3[j*10 + h];
        lg[h] = z;
    }
    __syncwarp();
    if (h < 10){
        float m = lg[0];
        #pragma unroll
        for (int i = 1; i < 10; i++) m = fmaxf(m, lg[i]);
        float s = 0.f;
        #pragma unroll
        for (int i = 0; i < 10; i++) s += expf(lg[i] - m);
        out[b*10 + h] = lg[h] - m - logf(s);
    }
    if (b == 0 && h == 31){
        out[B*10]     = g_acc[ACC_LOSS];
        out[B*10 + 1] = g_acc[ACC_LOSS+1];
    }
}

extern "C" void kernel_launch(void* const* d_in, const int* in_sizes, int n_in,
                              void* d_out, int out_size){
    const float* x      = (const float*)d_in[0];
    const float* adj    = (const float*)d_in[1];
    const float* W1     = (const float*)d_in[3];
    const float* b1     = (const float*)d_in[4];
    const float* Wrw    = (const float*)d_in[5];
    const float* brw    = (const float*)d_in[6];
    const float* Wg_rel = (const float*)d_in[7];
    const float* bg     = (const float*)d_in[8];
    const float* Wg_root= (const float*)d_in[9];
    const float* Wmcg   = (const float*)d_in[10];
    const float* bmcg   = (const float*)d_in[11];
    const float* W2g_rel= (const float*)d_in[12];
    const float* b2g    = (const float*)d_in[13];
    const float* W2g_root=(const float*)d_in[14];
    const float* Wct    = (const float*)d_in[15];
    const float* bct    = (const float*)d_in[16];
    const float* Wc_rel = (const float*)d_in[17];
    const float* bc     = (const float*)d_in[18];
    const float* Wc_root= (const float*)d_in[19];
    const float* Wmcc   = (const float*)d_in[20];
    const float* bmcc   = (const float*)d_in[21];
    const float* Wcat   = (const float*)d_in[22];
    const float* bcat   = (const float*)d_in[23];
    const float* W2     = (const float*)d_in[24];
    const float* b2     = (const float*)d_in[25];
    const float* W3     = (const float*)d_in[26];
    const float* b3     = (const float*)d_in[27];
    float* out = (float*)d_out;

    k_init<<<(ACC_TOTAL+511)/512, 512>>>();
    k_build_soft<<<BN/8, 256>>>(adj, x, W1, b1, Wrw, brw, Wct, bct);
    k_ctpart<<<B*8, 1024>>>();
    k_edges<<<BN/8, 256>>>();
    k_ctfin<<<B, 1024>>>();
    k_agglin<<<dim3(BN/8, 2), 256>>>(Wg_rel, bg, Wg_root, Wmcg, bmcg,
                                     Wc_rel, bc, Wc_root, Wmcc, bmcc);
    k_pool<<<dim3(32, B, 2), 1024>>>();
    k_poolfin<<<dim3(B, 2), 512>>>(W2g_rel, b2g, W2g_root);
    k_readout<<<B, 32>>>(Wcat, bcat, W2, b2, W3, b3, out);

    (void)in_sizes; (void)n_in; (void)out_size;
}

// round 7
// speedup vs baseline: 2.8474x; 1.0617x over previous
#include <cuda_runtime.h>
#include <math.h>
#include <stdint.h>

#define B 16
#define N 1024
#define BN (B*N)
#define IN 128
#define H 32
#define KC 32
#define KM 16
#define MAXD 128
#define EPSV 1e-15f
#define FULL 0xffffffffu

// ---------------- accumulator slab (atomically accumulated; zeroed per run) --
#define ACC_NUMRW 0                    // [B]
#define ACC_DENRW 16                   // [B]
#define ACC_S00   32                   // [B]
#define ACC_S01   48                   // [B]
#define ACC_S11   64                   // [B]
#define ACC_SAS   80                   // [B]
#define ACC_DENCT 96                   // [B]
#define ACC_SDS   112                  // [B]
#define ACC_VOL   128                  // [B]
#define ACC_SSCT  144                  // [B][32*32]
#define ACC_OA    (ACC_SSCT+B*1024)    // [2][B][256]
#define ACC_SSP   (ACC_OA+2*B*256)     // [2][B][256]
#define ACC_PX    (ACC_SSP+2*B*256)    // [2][B][512]
#define ACC_DENP  (ACC_PX+2*B*512)     // [2][B]
#define ACC_LOSS  (ACC_DENP+2*B)       // [2] main, ortho
#define ACC_TOTAL (ACC_LOSS+2)

__device__ float g_acc[ACC_TOTAL];

// ---------------- scratch ----------------------------------------------------
__device__ float g_xh[BN*H];
__device__ int   g_cols[BN*MAXD];
__device__ int   g_deg[BN];
__device__ float g_srw[BN*2];
__device__ float4 g_ninfo[BN];        // {srw0, srw1, sqct, 0} packed per node
__device__ float g_sct[BN*KC];
__device__ float g_sqct[BN];
__device__ float g_wgap[BN*MAXD];
__device__ float g_wct[BN*MAXD];
__device__ float g_xg[2*BN*H];
__device__ float g_smc[2*BN*KM];
__device__ float g_x2[2*B*KM*H];

__device__ __forceinline__ float wsum(float v){
    #pragma unroll
    for(int o=16;o;o>>=1) v += __shfl_xor_sync(FULL, v, o);
    return v;
}
__device__ __forceinline__ float wsum16(float v){
    #pragma unroll
    for(int o=8;o;o>>=1) v += __shfl_xor_sync(FULL, v, o, 16);
    return v;
}

__global__ void k_init(){
    int i = blockIdx.x*blockDim.x + threadIdx.x;
    if (i < ACC_TOTAL) g_acc[i] = 0.f;
}

// fused: neighbor lists (float4 ballot compaction) + vol + xh=x@W1+b1 +
//        rewiring softmax(k=2) + CT softmax(k=32) + per-batch scalar partials
__global__ void k_build_soft(const float* __restrict__ adj, const float* __restrict__ x,
                             const float* __restrict__ W1,  const float* __restrict__ b1,
                             const float* __restrict__ Wrw, const float* __restrict__ brw,
                             const float* __restrict__ Wct, const float* __restrict__ bct){
    __shared__ float W1s[IN*H];      // 16 KB
    __shared__ float Wcts[H*KC];     // 4 KB
    __shared__ float svol[8];
    __shared__ float sh[6];
    for (int i = threadIdx.x; i < IN*H; i += blockDim.x) W1s[i] = W1[i];
    for (int i = threadIdx.x; i < H*KC; i += blockDim.x) Wcts[i] = Wct[i];
    if (threadIdx.x < 6) sh[threadIdx.x] = 0.f;
    __syncthreads();

    int wid = (blockIdx.x*blockDim.x + threadIdx.x) >> 5;
    int lane = threadIdx.x & 31;
    int wz = threadIdx.x >> 5;

    // ---- neighbor list ----
    const float4* row = (const float4*)(adj + (size_t)wid * N);
    int* cols = g_cols + (size_t)wid * MAXD;
    int cnt = 0;
    #pragma unroll 2
    for (int c = 0; c < N; c += 128){
        float4 v = row[(c>>2) + lane];
        bool n0=v.x!=0.f, n1=v.y!=0.f, n2=v.z!=0.f, n3=v.w!=0.f;
        unsigned m0=__ballot_sync(FULL,n0), m1=__ballot_sync(FULL,n1);
        unsigned m2=__ballot_sync(FULL,n2), m3=__ballot_sync(FULL,n3);
        unsigned below = (1u<<lane) - 1u;
        int idx = cnt + __popc(m0&below)+__popc(m1&below)+__popc(m2&below)+__popc(m3&below);
        int col0 = c + lane*4;
        if(n0 && idx<MAXD){ cols[idx]=col0;   idx++; }
        if(n1 && idx<MAXD){ cols[idx]=col0+1; idx++; }
        if(n2 && idx<MAXD){ cols[idx]=col0+2; idx++; }
        if(n3 && idx<MAXD){ cols[idx]=col0+3; idx++; }
        cnt += __popc(m0)+__popc(m1)+__popc(m2)+__popc(m3);
    }
    int deg = cnt < MAXD ? cnt : MAXD;
    if (lane == 0){ g_deg[wid] = deg; svol[wz] = (float)deg; }

    // ---- xh = x @ W1 + b1 (lane = h) ----
    float acc = b1[lane];
    const float* xr = x + (size_t)wid*IN;
    #pragma unroll
    for (int c = 0; c < 4; c++){
        float xv = xr[c*32 + lane];
        #pragma unroll
        for (int j = 0; j < 32; j++)
            acc += __shfl_sync(FULL, xv, j) * W1s[(c*32+j)*H + lane];
    }
    g_xh[wid*H + lane] = acc;

    // ---- rewiring softmax (k=2) ----
    float a0 = wsum(acc*Wrw[lane*2])   + brw[0];
    float a1 = wsum(acc*Wrw[lane*2+1]) + brw[1];
    float mm = fmaxf(a0,a1);
    float e0 = expf(a0-mm), e1 = expf(a1-mm);
    float inv = 1.f/(e0+e1);
    float s0 = e0*inv, s1 = e1*inv;
    if (lane == 0){ g_srw[2*wid]=s0; g_srw[2*wid+1]=s1; }

    // ---- CT softmax (k=32, lane = k) ----
    float a = bct[lane];
    #pragma unroll
    for (int j = 0; j < 32; j++)
        a += __shfl_sync(FULL, acc, j) * Wcts[j*KC + lane];
    float m = a;
    #pragma unroll
    for (int o = 16; o; o >>= 1) m = fmaxf(m, __shfl_xor_sync(FULL, m, o));
    float e = expf(a - m);
    float s = e / wsum(e);
    g_sct[wid*KC + lane] = s;
    float sq = wsum(s*s);
    if (lane == 0){
        g_sqct[wid] = sq;
        g_ninfo[wid] = make_float4(s0, s1, sq, 0.f);
    }

    // ---- per-batch scalar partials ----
    if (lane == 0){
        atomicAdd(&sh[0], (float)deg*(s0*s0 + s1*s1)); // den_rw
        atomicAdd(&sh[1], s0*s0);                      // s00
        atomicAdd(&sh[2], s0*s1);                      // s01
        atomicAdd(&sh[3], s1*s1);                      // s11
        atomicAdd(&sh[4], sq);                         // den_ct
        atomicAdd(&sh[5], (float)deg*sq);              // sds
    }
    __syncthreads();
    int b = blockIdx.x >> 7;
    if (threadIdx.x < 6){
        const int dst[6] = {ACC_DENRW, ACC_S00, ACC_S01, ACC_S11, ACC_DENCT, ACC_SDS};
        atomicAdd(&g_acc[dst[threadIdx.x] + b], sh[threadIdx.x]);
    }
    if (threadIdx.x == 0){
        float vs = 0.f;
        #pragma unroll
        for (int i = 0; i < 8; i++) vs += svol[i];
        atomicAdd(&g_acc[ACC_VOL + b], vs);
    }
}

// S^T S partials from smem tiles (128-node chunks)
__global__ void k_ctpart(){
    int b = blockIdx.x >> 3, c = blockIdx.x & 7;
    int t = threadIdx.x;   // 1024
    __shared__ float S[128][33];
    int n0 = (b*N + c*128)*KC;
    #pragma unroll
    for (int i = 0; i < 4; i++){
        int idx = t + i*1024;
        S[idx>>5][idx&31] = g_sct[n0 + idx];
    }
    __syncthreads();
    int k = t >> 5, l = t & 31;
    float ssv = 0.f;
    #pragma unroll 8
    for (int n = 0; n < 128; n++)
        ssv += S[n][k]*S[n][l];
    atomicAdd(&g_acc[ACC_SSCT + b*1024 + t], ssv);
}

// per-edge weights + num_rw/sas partials.
// Lane-per-edge, but neighbor rows staged cooperatively through smem:
// 8 lanes per row x float4 => 8 LDG.128 per 32 edges, 4 lines each.
// Per-edge scalars come from one packed float4 gather (g_ninfo).
__global__ void k_edges(){
    int wid = (blockIdx.x*blockDim.x + threadIdx.x) >> 5;
    int lane = threadIdx.x & 31;
    int w = threadIdx.x >> 5;
    __shared__ float S[8][32*33 + 1];
    float* Sw = S[w];
    int b = wid >> 10, bN = b << 10;
    int deg = g_deg[wid];
    const int* cols = g_cols + wid*MAXD;
    float f_n = g_srw[2*wid];
    float s1n = g_srw[2*wid+1];
    float sn  = g_sct[wid*KC + lane];     // lane holds s_n[lane]
    float sqn = g_sqct[wid];
    float invvol = 1.f/(g_acc[ACC_VOL + b] + EPSV);
    float num_acc = 0.f, sas_acc = 0.f;

    int r8 = lane >> 3;        // row within group of 4 (8 lanes/row)
    int p8 = lane & 7;         // float4 slot within row

    for (int j0 = 0; j0 < deg; j0 += 32){
        // cooperative stage of up to 32 neighbor rows into smem
        #pragma unroll
        for (int g = 0; g < 8; g++){
            int e = g*4 + r8;
            int j = j0 + e;
            if (j < deg){
                int rm = bN + cols[j];
                float4 v = ((const float4*)(g_sct + (size_t)rm*KC))[p8];
                float* d = Sw + e*33 + p8*4;
                d[0]=v.x; d[1]=v.y; d[2]=v.z; d[3]=v.w;
            }
        }
        __syncwarp();
        int j = j0 + lane;
        bool act = j < deg;
        const float* Se = Sw + lane*33;
        float dot = 0.f;
        #pragma unroll
        for (int k = 0; k < 32; k++)
            dot += Se[k] * __shfl_sync(FULL, sn, k);
        if (act){
            int rm = bN + cols[j];
            float4 ni = g_ninfo[rm];
            float d = f_n - ni.x;
            float q2 = sqn + ni.z - 2.f*dot;
            g_wgap[wid*MAXD + j] = 1.f - d*d;
            g_wct [wid*MAXD + j] = sqrtf(fmaxf(q2, 0.f) + 1e-12f)*invvol;
            num_acc += f_n*ni.x + s1n*ni.y;
            sas_acc += dot;
        }
        __syncwarp();
    }
    num_acc = wsum(num_acc);
    sas_acc = wsum(sas_acc);

    __shared__ float sh[2];
    if (threadIdx.x < 2) sh[threadIdx.x] = 0.f;
    __syncthreads();
    if (lane == 0){
        atomicAdd(&sh[0], num_acc);
        atomicAdd(&sh[1], sas_acc);
    }
    __syncthreads();
    if (threadIdx.x < 2){
        const int dst[2] = {ACC_NUMRW, ACC_SAS};
        atomicAdd(&g_acc[dst[threadIdx.x] + (blockIdx.x>>7)], sh[threadIdx.x]);
    }
}

// CT losses (ortho over 32x32 S^T S + ct term) + rewiring losses (fused)
__global__ void k_ctfin(){
    int b = blockIdx.x, t = threadIdx.x;   // 1024
    __shared__ float ss[1024], red[1024], nrm_s;
    ss[t] = g_acc[ACC_SSCT + b*1024 + t];
    __syncthreads();
    red[t] = ss[t]*ss[t];
    __syncthreads();
    for (int o = 512; o; o >>= 1){ if (t < o) red[t] += red[t+o]; __syncthreads(); }
    if (t == 0) nrm_s = sqrtf(red[0]);
    __syncthreads();
    int k = t >> 5, l = t & 31;
    float d = ss[t]/nrm_s - ((k == l) ? 0.17677669529663687f : 0.f);
    red[t] = d*d;
    __syncthreads();
    for (int o = 512; o; o >>= 1){ if (t < o) red[t] += red[t+o]; __syncthreads(); }
    if (t == 0){
        float sas = g_acc[ACC_SAS + b];
        float den = g_acc[ACC_DENCT + b] + EPSV;
        float sds = g_acc[ACC_SDS + b];
        float lm = ((sds - sas)/den)/(float)B;
        float lo = sqrtf(red[0])/(float)B;
        float num = g_acc[ACC_NUMRW + b];
        float dnr = g_acc[ACC_DENRW + b] + EPSV;
        float s00 = g_acc[ACC_S00 + b];
        float s01 = g_acc[ACC_S01 + b];
        float s11 = g_acc[ACC_S11 + b];
        float nrm = sqrtf(s00*s00 + 2.f*s01*s01 + s11*s11);
        const float isk = 0.70710678118654752f;
        float d00 = s00/nrm - isk, d01 = s01/nrm, d11 = s11/nrm - isk;
        lm += -(num/dnr)/(float)B;
        lo += sqrtf(d00*d00 + 2.f*d01*d01 + d11*d11)/(float)B;
        atomicAdd(&g_acc[ACC_LOSS],   lm);
        atomicAdd(&g_acc[ACC_LOSS+1], lo);
    }
}

// fused: y = A_w @ xh ; xg = y@Wrel + brel + xh@Wroot ; smc = softmax(xg@Wmc+bmc)
//        den_pool partial (dnew * ||s||^2). Both branches via blockIdx.y.
__global__ void k_agglin(const float* __restrict__ Wr0, const float* __restrict__ br0,
                         const float* __restrict__ Wo0, const float* __restrict__ Wm0,
                         const float* __restrict__ bm0,
                         const float* __restrict__ Wr1, const float* __restrict__ br1,
                         const float* __restrict__ Wo1, const float* __restrict__ Wm1,
                         const float* __restrict__ bm1){
    int br = blockIdx.y;
    __shared__ float Wrs[H*H], Wos[H*H], Wms[H*KM];
    __shared__ float shden;
    {
        const float* Wrel  = br ? Wr1 : Wr0;
        const float* Wroot = br ? Wo1 : Wo0;
        const float* Wmc   = br ? Wm1 : Wm0;
        for (int i = threadIdx.x; i < H*H; i += blockDim.x){ Wrs[i]=Wrel[i]; Wos[i]=Wroot[i]; }
        for (int i = threadIdx.x; i < H*KM; i += blockDim.x) Wms[i]=Wmc[i];
        if (threadIdx.x == 0) shden = 0.f;
    }
    __syncthreads();
    const float* brel = br ? br1 : br0;
    const float* bmc  = br ? bm1 : bm0;

    int wid = (blockIdx.x*blockDim.x + threadIdx.x) >> 5;
    int lane = threadIdx.x & 31;
    int bN = (wid >> 10) << 10;
    int deg = g_deg[wid];
    const int* cols = g_cols + wid*MAXD;
    const float* w_arr = (br ? g_wct : g_wgap) + wid*MAXD;

    float y = 0.f, dsum = 0.f;
    for (int j = 0; j < deg; j++){
        int m = cols[j];
        float w = w_arr[j];
        y    += w * g_xh[(bN+m)*H + lane];
        dsum += w;
    }
    float xh = g_xh[wid*H + lane];
    float acc = brel[lane];
    #pragma unroll
    for (int j = 0; j < 32; j++){
        acc += __shfl_sync(FULL, y,  j) * Wrs[j*H + lane];
        acc += __shfl_sync(FULL, xh, j) * Wos[j*H + lane];
    }
    g_xg[br*BN*H + wid*H + lane] = acc;

    float a = (lane < KM) ? bmc[lane] : 0.f;
    #pragma unroll
    for (int j = 0; j < 32; j++){
        float xj = __shfl_sync(FULL, acc, j);
        if (lane < KM) a += xj * Wms[j*KM + lane];
    }
    float mm = a;
    #pragma unroll
    for (int o = 8; o; o >>= 1) mm = fmaxf(mm, __shfl_xor_sync(FULL, mm, o, 16));
    float e = (lane < KM) ? expf(a - mm) : 0.f;
    float es = wsum16(e);
    float s = e/es;
    if (lane < KM) g_smc[br*BN*KM + wid*KM + lane] = s;
    float sq = wsum16(s*s);
    if (lane == 0) atomicAdd(&shden, dsum*sq);
    __syncthreads();
    if (threadIdx.x == 0)
        atomicAdd(&g_acc[ACC_DENP + br*B + (blockIdx.x>>7)], shden);
}

// fused t16 + pooled partials over 32-node chunks
__global__ void k_pool(){
    int c = blockIdx.x, b = blockIdx.y, br = blockIdx.z;
    int t = threadIdx.x;              // 1024 = 32 warps
    int w = t >> 5, lane = t & 31;
    __shared__ float ssmc[32][17];    // [node][cluster] (pad)
    __shared__ float st16[32][17];
    __shared__ float sxg[32][33];     // [node][h]
    const float* smc = g_smc + br*BN*KM;
    const float* xg  = g_xg  + br*BN*H;
    int bN = b*N;
    int r = bN + c*32 + w;            // warp w handles node r
    if (lane < KM) ssmc[w][lane] = smc[r*KM + lane];
    sxg[w][lane] = xg[r*H + lane];
    {
        int deg = g_deg[r];
        const int* cols = g_cols + r*MAXD;
        const float* w_arr = (br ? g_wct : g_wgap) + r*MAXD;
        float tacc = 0.f;
        for (int j = 0; j < deg; j++){
            int m = cols[j];
            float wv = w_arr[j];
            if (lane < KM) tacc += wv * smc[(bN+m)*KM + lane];
        }
        if (lane < KM) st16[w][lane] = tacc;
    }
    __syncthreads();
    int base = (br*B + b)*256;
    if (t < 256){
        int k = t >> 4, l = t & 15;
        float oa = 0.f;
        #pragma unroll 8
        for (int n = 0; n < 32; n++) oa += ssmc[n][k]*st16[n][l];
        atomicAdd(&g_acc[ACC_OA + base + t], oa);
    } else if (t < 512){
        int k = (t-256) >> 4, l = t & 15;
        float ssv = 0.f;
        #pragma unroll 8
        for (int n = 0; n < 32; n++) ssv += ssmc[n][k]*ssmc[n][l];
        atomicAdd(&g_acc[ACC_SSP + base + (t-256)], ssv);
    } else {
        int kk = (t-512) >> 5, h = t & 31;
        float px = 0.f;
        #pragma unroll 8
        for (int n = 0; n < 32; n++) px += ssmc[n][kk]*sxg[n][h];
        atomicAdd(&g_acc[ACC_PX + (br*B + b)*512 + (t-512)], px);
    }
}

// finalize pool: losses + normalized pooladj + pooled DGC (conv2gap weights)
__global__ void k_poolfin(const float* __restrict__ W2g_rel, const float* __restrict__ b2g,
                          const float* __restrict__ W2g_root){
    int b = blockIdx.x, br = blockIdx.y, t = threadIdx.x;   // 512
    __shared__ float oa[256], ssm[256], px[512], t2[512], pa[256], red[512], nrm_s;
    int base = (br*B + b)*256;
    if (t < 256){ oa[t] = g_acc[ACC_OA + base + t]; ssm[t] = g_acc[ACC_SSP + base + t]; }
    px[t] = g_acc[ACC_PX + (br*B + b)*512 + t];
    __syncthreads();
    red[t] = (t < 256) ? ssm[t]*ssm[t] : 0.f;
    __syncthreads();
    for (int o = 256; o; o >>= 1){ if (t < o) red[t] += red[t+o]; __syncthreads(); }
    if (t == 0) nrm_s = sqrtf(red[0]);
    __syncthreads();
    if (t < 256){
        int k = t >> 4, l = t & 15;
        float d = ssm[t]/nrm_s - ((k == l) ? 0.25f : 0.f);
        red[t] = d*d;
    } else red[t] = 0.f;
    __syncthreads();
    for (int o = 256; o; o >>= 1){ if (t < o) red[t] += red[t+o]; __syncthreads(); }
    if (t == 0){
        float num = 0.f;
        #pragma unroll
        for (int k = 0; k < KM; k++) num += oa[k*KM + k];
        float den = g_acc[ACC_DENP + br*B + b] + EPSV;
        atomicAdd(&g_acc[ACC_LOSS],   -(num/den)/(float)B);
        atomicAdd(&g_acc[ACC_LOSS+1], sqrtf(red[0])/(float)B);
    }
    __shared__ float dsq[KM];
    if (t < KM){
        float rs = 0.f;
        #pragma unroll
        for (int l = 0; l < KM; l++) rs += (l == t) ? 0.f : oa[t*KM + l];
        dsq[t] = sqrtf(rs) + EPSV;
    }
    __syncthreads();
    if (t < 256){
        int k = t >> 4, l = t & 15;
        pa[t] = (k == l) ? 0.f : oa[t]/(dsq[k]*dsq[l]);
    }
    __syncthreads();
    int k = t >> 5, h = t & 31;
    float a = 0.f;
    #pragma unroll
    for (int l = 0; l < KM; l++) a += pa[k*KM + l]*px[l*H + h];
    t2[t] = a;
    __syncthreads();
    float accv = b2g[h];
    #pragma unroll
    for (int j = 0; j < H; j++)
        accv += t2[k*H + j]*W2g_rel[j*H + h] + px[k*H + j]*W2g_root[j*H + h];
    g_x2[br*B*KM*H + b*KM*H + t] = accv;
}

__global__ void k_readout(const float* __restrict__ Wcat, const float* __restrict__ bcat,
                          const float* __restrict__ W2,  const float* __restrict__ b2,
                          const float* __restrict__ W3,  const float* __restrict__ b3,
                          float* __restrict__ out){
    int b = blockIdx.x, h = threadIdx.x;   // 32
    __shared__ float h1[H], h2[H], lg[10];
    float acc = 0.f;
    for (int kk = 0; kk < KM; kk++){
        float z = bcat[h];
        #pragma unroll
        for (int j = 0; j < H; j++) z += g_x2[b*KM*H + kk*H + j]*Wcat[j*H + h];
        #pragma unroll
        for (int j = 0; j < H; j++) z += g_x2[B*KM*H + b*KM*H + kk*H + j]*Wcat[(H+j)*H + h];
        acc += fmaxf(z, 0.f);
    }
    h1[h] = acc; __syncwarp();
    float z2 = b2[h];
    #pragma unroll
    for (int j = 0; j < H; j++) z2 += h1[j]*W2[j*H + h];
    h2[h] = fmaxf(z2, 0.f); __syncwarp();
    if (h < 10){
        float z = b3[h];
        #pragma unroll
        for (int j = 0; j < H; j++) z += h2[j]*W3[j*10 + h];
        lg[h] = z;
    }
    __syncwarp();
    if (h < 10){
        float m = lg[0];
        #pragma unroll
        for (int i = 1; i < 10; i++) m = fmaxf(m, lg[i]);
        float s = 0.f;
        #pragma unroll
        for (int i = 0; i < 10; i++) s += expf(lg[i] - m);
        out[b*10 + h] = lg[h] - m - logf(s);
    }
    if (b == 0 && h == 31){
        out[B*10]     = g_acc[ACC_LOSS];
        out[B*10 + 1] = g_acc[ACC_LOSS+1];
    }
}

extern "C" void kernel_launch(void* const* d_in, const int* in_sizes, int n_in,
                              void* d_out, int out_size){
    const float* x      = (const float*)d_in[0];
    const float* adj    = (const float*)d_in[1];
    const float* W1     = (const float*)d_in[3];
    const float* b1     = (const float*)d_in[4];
    const float* Wrw    = (const float*)d_in[5];
    const float* brw    = (const float*)d_in[6];
    const float* Wg_rel = (const float*)d_in[7];
    const float* bg     = (const float*)d_in[8];
    const float* Wg_root= (const float*)d_in[9];
    const float* Wmcg   = (const float*)d_in[10];
    const float* bmcg   = (const float*)d_in[11];
    const float* W2g_rel= (const float*)d_in[12];
    const float* b2g    = (const float*)d_in[13];
    const float* W2g_root=(const float*)d_in[14];
    const float* Wct    = (const float*)d_in[15];
    const float* bct    = (const float*)d_in[16];
    const float* Wc_rel = (const float*)d_in[17];
    const float* bc     = (const float*)d_in[18];
    const float* Wc_root= (const float*)d_in[19];
    const float* Wmcc   = (const float*)d_in[20];
    const float* bmcc   = (const float*)d_in[21];
    const float* Wcat   = (const float*)d_in[22];
    const float* bcat   = (const float*)d_in[23];
    const float* W2     = (const float*)d_in[24];
    const float* b2     = (const float*)d_in[25];
    const float* W3     = (const float*)d_in[26];
    const float* b3     = (const float*)d_in[27];
    float* out = (float*)d_out;

    k_init<<<(ACC_TOTAL+511)/512, 512>>>();
    k_build_soft<<<BN/8, 256>>>(adj, x, W1, b1, Wrw, brw, Wct, bct);
    k_ctpart<<<B*8, 1024>>>();
    k_edges<<<BN/8, 256>>>();
    k_ctfin<<<B, 1024>>>();
    k_agglin<<<dim3(BN/8, 2), 256>>>(Wg_rel, bg, Wg_root, Wmcg, bmcg,
                                     Wc_rel, bc, Wc_root, Wmcc, bmcc);
    k_pool<<<dim3(32, B, 2), 1024>>>();
    k_poolfin<<<dim3(B, 2), 512>>>(W2g_rel, b2g, W2g_root);
    k_readout<<<B, 32>>>(Wcat, bcat, W2, b2, W3, b3, out);

    (void)in_sizes; (void)n_in; (void)out_size;
}

// round 8
// speedup vs baseline: 2.8830x; 1.0125x over previous
#include <cuda_runtime.h>
#include <math.h>
#include <stdint.h>

#define B 16
#define N 1024
#define BN (B*N)
#define IN 128
#define H 32
#define KC 32
#define KM 16
#define MAXD 128
#define EPSV 1e-15f
#define FULL 0xffffffffu

// ---------------- accumulator slab (atomically accumulated; zeroed per run) --
#define ACC_NUMRW 0                    // [B]
#define ACC_DENRW 16                   // [B]
#define ACC_S00   32                   // [B]
#define ACC_S01   48                   // [B]
#define ACC_S11   64                   // [B]
#define ACC_SAS   80                   // [B]
#define ACC_DENCT 96                   // [B]
#define ACC_SDS   112                  // [B]
#define ACC_VOL   128                  // [B]
#define ACC_SSCT  144                  // [B][32*32]
#define ACC_OA    (ACC_SSCT+B*1024)    // [2][B][256]
#define ACC_SSP   (ACC_OA+2*B*256)     // [2][B][256]
#define ACC_PX    (ACC_SSP+2*B*256)    // [2][B][512]
#define ACC_DENP  (ACC_PX+2*B*512)     // [2][B]
#define ACC_LOSS  (ACC_DENP+2*B)       // [2] main, ortho
#define ACC_TOTAL (ACC_LOSS+2)

__device__ float g_acc[ACC_TOTAL];

// ---------------- scratch ----------------------------------------------------
__device__ float g_xh[BN*H];
__device__ int   g_cols[BN*MAXD];
__device__ int   g_deg[BN];
__device__ float g_srw[BN*2];
__device__ float4 g_ninfo[BN];        // {srw0, srw1, sqct, 0} packed per node
__device__ float g_sct[BN*KC];
__device__ float g_sqct[BN];
__device__ float g_wgap[BN*MAXD];
__device__ float g_wct[BN*MAXD];
__device__ float g_xg[2*BN*H];
__device__ float g_smc[2*BN*KM];
__device__ float g_x2[2*B*KM*H];

__device__ __forceinline__ float wsum(float v){
    #pragma unroll
    for(int o=16;o;o>>=1) v += __shfl_xor_sync(FULL, v, o);
    return v;
}
__device__ __forceinline__ float wsum16(float v){
    #pragma unroll
    for(int o=8;o;o>>=1) v += __shfl_xor_sync(FULL, v, o, 16);
    return v;
}

__global__ void k_init(){
    int i = blockIdx.x*blockDim.x + threadIdx.x;
    if (i < ACC_TOTAL) g_acc[i] = 0.f;
}

// fused: neighbor lists (prefetched float4 + ballot compaction, MLP=8) + vol +
//        xh=x@W1+b1 + rewiring softmax(k=2) + CT softmax(k=32) + scalar partials
__global__ void k_build_soft(const float* __restrict__ adj, const float* __restrict__ x,
                             const float* __restrict__ W1,  const float* __restrict__ b1,
                             const float* __restrict__ Wrw, const float* __restrict__ brw,
                             const float* __restrict__ Wct, const float* __restrict__ bct){
    __shared__ float W1s[IN*H];      // 16 KB
    __shared__ float Wcts[H*KC];     // 4 KB
    __shared__ float svol[8];
    __shared__ float sh[6];
    for (int i = threadIdx.x; i < IN*H; i += blockDim.x) W1s[i] = W1[i];
    for (int i = threadIdx.x; i < H*KC; i += blockDim.x) Wcts[i] = Wct[i];
    if (threadIdx.x < 6) sh[threadIdx.x] = 0.f;
    __syncthreads();

    int wid = (blockIdx.x*blockDim.x + threadIdx.x) >> 5;
    int lane = threadIdx.x & 31;
    int wz = threadIdx.x >> 5;

    // ---- neighbor list: prefetch entire row (MLP=8), then compact ----
    const float4* row = (const float4*)(adj + (size_t)wid * N);
    int* cols = g_cols + (size_t)wid * MAXD;
    float4 v[8];
    #pragma unroll
    for (int i = 0; i < 8; i++) v[i] = row[i*32 + lane];
    int cnt = 0;
    #pragma unroll
    for (int i = 0; i < 8; i++){
        bool n0=v[i].x!=0.f, n1=v[i].y!=0.f, n2=v[i].z!=0.f, n3=v[i].w!=0.f;
        unsigned m0=__ballot_sync(FULL,n0), m1=__ballot_sync(FULL,n1);
        unsigned m2=__ballot_sync(FULL,n2), m3=__ballot_sync(FULL,n3);
        unsigned below = (1u<<lane) - 1u;
        int idx = cnt + __popc(m0&below)+__popc(m1&below)+__popc(m2&below)+__popc(m3&below);
        int col0 = i*128 + lane*4;
        if(n0 && idx<MAXD){ cols[idx]=col0;   idx++; }
        if(n1 && idx<MAXD){ cols[idx]=col0+1; idx++; }
        if(n2 && idx<MAXD){ cols[idx]=col0+2; idx++; }
        if(n3 && idx<MAXD){ cols[idx]=col0+3; idx++; }
        cnt += __popc(m0)+__popc(m1)+__popc(m2)+__popc(m3);
    }
    int deg = cnt < MAXD ? cnt : MAXD;
    if (lane == 0){ g_deg[wid] = deg; svol[wz] = (float)deg; }

    // ---- xh = x @ W1 + b1 (lane = h) ----
    float acc = b1[lane];
    const float* xr = x + (size_t)wid*IN;
    #pragma unroll
    for (int c = 0; c < 4; c++){
        float xv = xr[c*32 + lane];
        #pragma unroll
        for (int j = 0; j < 32; j++)
            acc += __shfl_sync(FULL, xv, j) * W1s[(c*32+j)*H + lane];
    }
    g_xh[wid*H + lane] = acc;

    // ---- rewiring softmax (k=2) ----
    float a0 = wsum(acc*Wrw[lane*2])   + brw[0];
    float a1 = wsum(acc*Wrw[lane*2+1]) + brw[1];
    float mm = fmaxf(a0,a1);
    float e0 = expf(a0-mm), e1 = expf(a1-mm);
    float inv = 1.f/(e0+e1);
    float s0 = e0*inv, s1 = e1*inv;
    if (lane == 0){ g_srw[2*wid]=s0; g_srw[2*wid+1]=s1; }

    // ---- CT softmax (k=32, lane = k) ----
    float a = bct[lane];
    #pragma unroll
    for (int j = 0; j < 32; j++)
        a += __shfl_sync(FULL, acc, j) * Wcts[j*KC + lane];
    float m = a;
    #pragma unroll
    for (int o = 16; o; o >>= 1) m = fmaxf(m, __shfl_xor_sync(FULL, m, o));
    float e = expf(a - m);
    float s = e / wsum(e);
    g_sct[wid*KC + lane] = s;
    float sq = wsum(s*s);
    if (lane == 0){
        g_sqct[wid] = sq;
        g_ninfo[wid] = make_float4(s0, s1, sq, 0.f);
    }

    // ---- per-batch scalar partials ----
    if (lane == 0){
        atomicAdd(&sh[0], (float)deg*(s0*s0 + s1*s1)); // den_rw
        atomicAdd(&sh[1], s0*s0);                      // s00
        atomicAdd(&sh[2], s0*s1);                      // s01
        atomicAdd(&sh[3], s1*s1);                      // s11
        atomicAdd(&sh[4], sq);                         // den_ct
        atomicAdd(&sh[5], (float)deg*sq);              // sds
    }
    __syncthreads();
    int b = blockIdx.x >> 7;
    if (threadIdx.x < 6){
        const int dst[6] = {ACC_DENRW, ACC_S00, ACC_S01, ACC_S11, ACC_DENCT, ACC_SDS};
        atomicAdd(&g_acc[dst[threadIdx.x] + b], sh[threadIdx.x]);
    }
    if (threadIdx.x == 0){
        float vs = 0.f;
        #pragma unroll
        for (int i = 0; i < 8; i++) vs += svol[i];
        atomicAdd(&g_acc[ACC_VOL + b], vs);
    }
}

// S^T S partials from smem tiles (128-node chunks)
__global__ void k_ctpart(){
    int b = blockIdx.x >> 3, c = blockIdx.x & 7;
    int t = threadIdx.x;   // 1024
    __shared__ float S[128][33];
    int n0 = (b*N + c*128)*KC;
    #pragma unroll
    for (int i = 0; i < 4; i++){
        int idx = t + i*1024;
        S[idx>>5][idx&31] = g_sct[n0 + idx];
    }
    __syncthreads();
    int k = t >> 5, l = t & 31;
    float ssv = 0.f;
    #pragma unroll 8
    for (int n = 0; n < 128; n++)
        ssv += S[n][k]*S[n][l];
    atomicAdd(&g_acc[ACC_SSCT + b*1024 + t], ssv);
}

// MEGA-FUSED edge kernel: per warp = node.
// 1) per-edge wgap/wct (lane-per-edge, smem-staged sct rows) + num/sas partials
// 2) y_gap/y_ct = A_w @ xh accumulated from ONE coalesced xh row load per edge
// 3) lin (Wrel,Wroot) + pool softmax for BOTH branches, den_pool partials
__global__ void k_edgeagg(const float* __restrict__ Wr0, const float* __restrict__ br0,
                          const float* __restrict__ Wo0, const float* __restrict__ Wm0,
                          const float* __restrict__ bm0,
                          const float* __restrict__ Wr1, const float* __restrict__ br1,
                          const float* __restrict__ Wo1, const float* __restrict__ Wm1,
                          const float* __restrict__ bm1){
    __shared__ float S[8][32*33 + 1];               // sct staging per warp
    __shared__ float Wrs[2][H*H], Wos[2][H*H], Wms[2][H*KM];
    __shared__ float shred[4];                      // num, sas, denp0, denp1
    for (int i = threadIdx.x; i < H*H; i += blockDim.x){
        Wrs[0][i] = Wr0[i]; Wrs[1][i] = Wr1[i];
        Wos[0][i] = Wo0[i]; Wos[1][i] = Wo1[i];
    }
    for (int i = threadIdx.x; i < H*KM; i += blockDim.x){
        Wms[0][i] = Wm0[i]; Wms[1][i] = Wm1[i];
    }
    if (threadIdx.x < 4) shred[threadIdx.x] = 0.f;
    __syncthreads();

    int wid = (blockIdx.x*blockDim.x + threadIdx.x) >> 5;
    int lane = threadIdx.x & 31;
    int w = threadIdx.x >> 5;
    float* Sw = S[w];
    int b = wid >> 10, bN = b << 10;
    int deg = g_deg[wid];
    const int* cols = g_cols + wid*MAXD;
    float f_n = g_srw[2*wid];
    float s1n = g_srw[2*wid+1];
    float sn  = g_sct[wid*KC + lane];
    float sqn = g_sqct[wid];
    float invvol = 1.f/(g_acc[ACC_VOL + b] + EPSV);
    float num_acc = 0.f, sas_acc = 0.f;
    float dg_acc = 0.f, dc_acc = 0.f;      // dnew rowsums (per lane partial)
    float y_gap = 0.f, y_ct = 0.f;         // lane = h

    int r8 = lane >> 3;
    int p8 = lane & 7;

    for (int j0 = 0; j0 < deg; j0 += 32){
        int tlen = deg - j0; if (tlen > 32) tlen = 32;
        // cooperative stage of neighbor sct rows
        #pragma unroll
        for (int g = 0; g < 8; g++){
            int e = g*4 + r8;
            int j = j0 + e;
            if (j < deg){
                int rm = bN + cols[j];
                float4 v = ((const float4*)(g_sct + (size_t)rm*KC))[p8];
                float* d = Sw + e*33 + p8*4;
                d[0]=v.x; d[1]=v.y; d[2]=v.z; d[3]=v.w;
            }
        }
        __syncwarp();
        int j = j0 + lane;
        bool act = j < deg;
        int mc = act ? cols[j] : 0;
        const float* Se = Sw + lane*33;
        float dot = 0.f;
        #pragma unroll
        for (int k = 0; k < 32; k++)
            dot += Se[k] * __shfl_sync(FULL, sn, k);
        float wg = 0.f, wc = 0.f;
        if (act){
            float4 ni = g_ninfo[bN + mc];
            float d = f_n - ni.x;
            float q2 = sqn + ni.z - 2.f*dot;
            wg = 1.f - d*d;
            wc = sqrtf(fmaxf(q2, 0.f) + 1e-12f)*invvol;
            g_wgap[wid*MAXD + j] = wg;
            g_wct [wid*MAXD + j] = wc;
            num_acc += f_n*ni.x + s1n*ni.y;
            sas_acc += dot;
        }
        dg_acc += wg; dc_acc += wc;
        // both-branch aggregation: one xh row load per edge
        for (int jj = 0; jj < tlen; jj++){
            int   mcj = __shfl_sync(FULL, mc, jj);
            float wgj = __shfl_sync(FULL, wg, jj);
            float wcj = __shfl_sync(FULL, wc, jj);
            float xv  = g_xh[(bN + mcj)*H + lane];
            y_gap += wgj*xv;
            y_ct  += wcj*xv;
        }
        __syncwarp();
    }
    num_acc = wsum(num_acc);
    sas_acc = wsum(sas_acc);
    float dsum_g = wsum(dg_acc);
    float dsum_c = wsum(dc_acc);

    // lin + pool softmax for both branches
    float xh = g_xh[wid*H + lane];
    float den_g = 0.f, den_c = 0.f;
    #pragma unroll
    for (int br = 0; br < 2; br++){
        float y = br ? y_ct : y_gap;
        const float* brel = br ? br1 : br0;
        const float* bmc  = br ? bm1 : bm0;
        const float* Wr = Wrs[br];
        const float* Wo = Wos[br];
        const float* Wm = Wms[br];
        float acc = brel[lane];
        #pragma unroll
        for (int j = 0; j < 32; j++){
            acc += __shfl_sync(FULL, y,  j) * Wr[j*H + lane];
            acc += __shfl_sync(FULL, xh, j) * Wo[j*H + lane];
        }
        g_xg[br*BN*H + wid*H + lane] = acc;
        float a = (lane < KM) ? bmc[lane] : 0.f;
        #pragma unroll
        for (int j = 0; j < 32; j++){
            float xj = __shfl_sync(FULL, acc, j);
            if (lane < KM) a += xj * Wm[j*KM + lane];
        }
        float mm = a;
        #pragma unroll
        for (int o = 8; o; o >>= 1) mm = fmaxf(mm, __shfl_xor_sync(FULL, mm, o, 16));
        float e = (lane < KM) ? expf(a - mm) : 0.f;
        float es = wsum16(e);
        float s = e/es;
        if (lane < KM) g_smc[br*BN*KM + wid*KM + lane] = s;
        float sq = wsum16(s*s);
        if (br) den_c = sq; else den_g = sq;
    }
    if (lane == 0){
        atomicAdd(&shred[0], num_acc);
        atomicAdd(&shred[1], sas_acc);
        atomicAdd(&shred[2], dsum_g*den_g);
        atomicAdd(&shred[3], dsum_c*den_c);
    }
    __syncthreads();
    if (threadIdx.x < 4){
        int bb = blockIdx.x >> 7;
        const int dst[4] = {ACC_NUMRW, ACC_SAS, ACC_DENP, ACC_DENP + B};
        atomicAdd(&g_acc[dst[threadIdx.x] + bb], shred[threadIdx.x]);
    }
}

// CT losses (ortho over 32x32 S^T S + ct term) + rewiring losses (fused)
__global__ void k_ctfin(){
    int b = blockIdx.x, t = threadIdx.x;   // 1024
    __shared__ float ss[1024], red[1024], nrm_s;
    ss[t] = g_acc[ACC_SSCT + b*1024 + t];
    __syncthreads();
    red[t] = ss[t]*ss[t];
    __syncthreads();
    for (int o = 512; o; o >>= 1){ if (t < o) red[t] += red[t+o]; __syncthreads(); }
    if (t == 0) nrm_s = sqrtf(red[0]);
    __syncthreads();
    int k = t >> 5, l = t & 31;
    float d = ss[t]/nrm_s - ((k == l) ? 0.17677669529663687f : 0.f);
    red[t] = d*d;
    __syncthreads();
    for (int o = 512; o; o >>= 1){ if (t < o) red[t] += red[t+o]; __syncthreads(); }
    if (t == 0){
        float sas = g_acc[ACC_SAS + b];
        float den = g_acc[ACC_DENCT + b] + EPSV;
        float sds = g_acc[ACC_SDS + b];
        float lm = ((sds - sas)/den)/(float)B;
        float lo = sqrtf(red[0])/(float)B;
        float num = g_acc[ACC_NUMRW + b];
        float dnr = g_acc[ACC_DENRW + b] + EPSV;
        float s00 = g_acc[ACC_S00 + b];
        float s01 = g_acc[ACC_S01 + b];
        float s11 = g_acc[ACC_S11 + b];
        float nrm = sqrtf(s00*s00 + 2.f*s01*s01 + s11*s11);
        const float isk = 0.70710678118654752f;
        float d00 = s00/nrm - isk, d01 = s01/nrm, d11 = s11/nrm - isk;
        lm += -(num/dnr)/(float)B;
        lo += sqrtf(d00*d00 + 2.f*d01*d01 + d11*d11)/(float)B;
        atomicAdd(&g_acc[ACC_LOSS],   lm);
        atomicAdd(&g_acc[ACC_LOSS+1], lo);
    }
}

// fused t16 + pooled partials over 32-node chunks
__global__ void k_pool(){
    int c = blockIdx.x, b = blockIdx.y, br = blockIdx.z;
    int t = threadIdx.x;              // 1024 = 32 warps
    int w = t >> 5, lane = t & 31;
    __shared__ float ssmc[32][17];
    __shared__ float st16[32][17];
    __shared__ float sxg[32][33];
    const float* smc = g_smc + br*BN*KM;
    const float* xg  = g_xg  + br*BN*H;
    int bN = b*N;
    int r = bN + c*32 + w;
    if (lane < KM) ssmc[w][lane] = smc[r*KM + lane];
    sxg[w][lane] = xg[r*H + lane];
    {
        int deg = g_deg[r];
        const int* cols = g_cols + r*MAXD;
        const float* w_arr = (br ? g_wct : g_wgap) + r*MAXD;
        float tacc = 0.f;
        for (int j = 0; j < deg; j++){
            int m = cols[j];
            float wv = w_arr[j];
            if (lane < KM) tacc += wv * smc[(bN+m)*KM + lane];
        }
        if (lane < KM) st16[w][lane] = tacc;
    }
    __syncthreads();
    int base = (br*B + b)*256;
    if (t < 256){
        int k = t >> 4, l = t & 15;
        float oa = 0.f;
        #pragma unroll 8
        for (int n = 0; n < 32; n++) oa += ssmc[n][k]*st16[n][l];
        atomicAdd(&g_acc[ACC_OA + base + t], oa);
    } else if (t < 512){
        int k = (t-256) >> 4, l = t & 15;
        float ssv = 0.f;
        #pragma unroll 8
        for (int n = 0; n < 32; n++) ssv += ssmc[n][k]*ssmc[n][l];
        atomicAdd(&g_acc[ACC_SSP + base + (t-256)], ssv);
    } else {
        int kk = (t-512) >> 5, h = t & 31;
        float px = 0.f;
        #pragma unroll 8
        for (int n = 0; n < 32; n++) px += ssmc[n][kk]*sxg[n][h];
        atomicAdd(&g_acc[ACC_PX + (br*B + b)*512 + (t-512)], px);
    }
}

// finalize pool: losses + normalized pooladj + pooled DGC (conv2gap weights)
__global__ void k_poolfin(const float* __restrict__ W2g_rel, const float* __restrict__ b2g,
                          const float* __restrict__ W2g_root){
    int b = blockIdx.x, br = blockIdx.y, t = threadIdx.x;   // 512
    __shared__ float oa[256], ssm[256], px[512], t2[512], pa[256], red[512], nrm_s;
    int base = (br*B + b)*256;
    if (t < 256){ oa[t] = g_acc[ACC_OA + base + t]; ssm[t] = g_acc[ACC_SSP + base + t]; }
    px[t] = g_acc[ACC_PX + (br*B + b)*512 + t];
    __syncthreads();
    red[t] = (t < 256) ? ssm[t]*ssm[t] : 0.f;
    __syncthreads();
    for (int o = 256; o; o >>= 1){ if (t < o) red[t] += red[t+o]; __syncthreads(); }
    if (t == 0) nrm_s = sqrtf(red[0]);
    __syncthreads();
    if (t < 256){
        int k = t >> 4, l = t & 15;
        float d = ssm[t]/nrm_s - ((k == l) ? 0.25f : 0.f);
        red[t] = d*d;
    } else red[t] = 0.f;
    __syncthreads();
    for (int o = 256; o; o >>= 1){ if (t < o) red[t] += red[t+o]; __syncthreads(); }
    if (t == 0){
        float num = 0.f;
        #pragma unroll
        for (int k = 0; k < KM; k++) num += oa[k*KM + k];
        float den = g_acc[ACC_DENP + br*B + b] + EPSV;
        atomicAdd(&g_acc[ACC_LOSS],   -(num/den)/(float)B);
        atomicAdd(&g_acc[ACC_LOSS+1], sqrtf(red[0])/(float)B);
    }
    __shared__ float dsq[KM];
    if (t < KM){
        float rs = 0.f;
        #pragma unroll
        for (int l = 0; l < KM; l++) rs += (l == t) ? 0.f : oa[t*KM + l];
        dsq[t] = sqrtf(rs) + EPSV;
    }
    __syncthreads();
    if (t < 256){
        int k = t >> 4, l = t & 15;
        pa[t] = (k == l) ? 0.f : oa[t]/(dsq[k]*dsq[l]);
    }
    __syncthreads();
    int k = t >> 5, h = t & 31;
    float a = 0.f;
    #pragma unroll
    for (int l = 0; l < KM; l++) a += pa[k*KM + l]*px[l*H + h];
    t2[t] = a;
    __syncthreads();
    float accv = b2g[h];
    #pragma unroll
    for (int j = 0; j < H; j++)
        accv += t2[k*H + j]*W2g_rel[j*H + h] + px[k*H + j]*W2g_root[j*H + h];
    g_x2[br*B*KM*H + b*KM*H + t] = accv;
}

__global__ void k_readout(const float* __restrict__ Wcat, const float* __restrict__ bcat,
                          const float* __restrict__ W2,  const float* __restrict__ b2,
                          const float* __restrict__ W3,  const float* __restrict__ b3,
                          float* __restrict__ out){
    int b = blockIdx.x, h = threadIdx.x;   // 32
    __shared__ float h1[H], h2[H], lg[10];
    float acc = 0.f;
    for (int kk = 0; kk < KM; kk++){
        float z = bcat[h];
        #pragma unroll
        for (int j = 0; j < H; j++) z += g_x2[b*KM*H + kk*H + j]*Wcat[j*H + h];
        #pragma unroll
        for (int j = 0; j < H; j++) z += g_x2[B*KM*H + b*KM*H + kk*H + j]*Wcat[(H+j)*H + h];
        acc += fmaxf(z, 0.f);
    }
    h1[h] = acc; __syncwarp();
    float z2 = b2[h];
    #pragma unroll
    for (int j = 0; j < H; j++) z2 += h1[j]*W2[j*H + h];
    h2[h] = fmaxf(z2, 0.f); __syncwarp();
    if (h < 10){
        float z = b3[h];
        #pragma unroll
        for (int j = 0; j < H; j++) z += h2[j]*W3[j*10 + h];
        lg[h] = z;
    }
    __syncwarp();
    if (h < 10){
        float m = lg[0];
        #pragma unroll
        for (int i = 1; i < 10; i++) m = fmaxf(m, lg[i]);
        float s = 0.f;
        #pragma unroll
        for (int i = 0; i < 10; i++) s += expf(lg[i] - m);
        out[b*10 + h] = lg[h] - m - logf(s);
    }
    if (b == 0 && h == 31){
        out[B*10]     = g_acc[ACC_LOSS];
        out[B*10 + 1] = g_acc[ACC_LOSS+1];
    }
}

extern "C" void kernel_launch(void* const* d_in, const int* in_sizes, int n_in,
                              void* d_out, int out_size){
    const float* x      = (const float*)d_in[0];
    const float* adj    = (const float*)d_in[1];
    const float* W1     = (const float*)d_in[3];
    const float* b1     = (const float*)d_in[4];
    const float* Wrw    = (const float*)d_in[5];
    const float* brw    = (const float*)d_in[6];
    const float* Wg_rel = (const float*)d_in[7];
    const float* bg     = (const float*)d_in[8];
    const float* Wg_root= (const float*)d_in[9];
    const float* Wmcg   = (const float*)d_in[10];
    const float* bmcg   = (const float*)d_in[11];
    const float* W2g_rel= (const float*)d_in[12];
    const float* b2g    = (const float*)d_in[13];
    const float* W2g_root=(const float*)d_in[14];
    const float* Wct    = (const float*)d_in[15];
    const float* bct    = (const float*)d_in[16];
    const float* Wc_rel = (const float*)d_in[17];
    const float* bc     = (const float*)d_in[18];
    const float* Wc_root= (const float*)d_in[19];
    const float* Wmcc   = (const float*)d_in[20];
    const float* bmcc   = (const float*)d_in[21];
    const float* Wcat   = (const float*)d_in[22];
    const float* bcat   = (const float*)d_in[23];
    const float* W2     = (const float*)d_in[24];
    const float* b2     = (const float*)d_in[25];
    const float* W3     = (const float*)d_in[26];
    const float* b3     = (const float*)d_in[27];
    float* out = (float*)d_out;

    k_init<<<(ACC_TOTAL+511)/512, 512>>>();
    k_build_soft<<<BN/8, 256>>>(adj, x, W1, b1, Wrw, brw, Wct, bct);
    k_ctpart<<<B*8, 1024>>>();
    k_edgeagg<<<BN/8, 256>>>(Wg_rel, bg, Wg_root, Wmcg, bmcg,
                             Wc_rel, bc, Wc_root, Wmcc, bmcc);
    k_ctfin<<<B, 1024>>>();
    k_pool<<<dim3(32, B, 2), 1024>>>();
    k_poolfin<<<dim3(B, 2), 512>>>(W2g_rel, b2g, W2g_root);
    k_readout<<<B, 32>>>(Wcat, bcat, W2, b2, W3, b3, out);

    (void)in_sizes; (void)n_in; (void)out_size;
}

// round 9
// speedup vs baseline: 3.0809x; 1.0686x over previous
#include <cuda_runtime.h>
#include <math.h>
#include <stdint.h>

#define B 16
#define N 1024
#define BN (B*N)
#define IN 128
#define H 32
#define KC 32
#define KM 16
#define MAXD 128
#define EPSV 1e-15f
#define FULL 0xffffffffu

// ---------------- accumulator slab (atomically accumulated; zeroed per run) --
#define ACC_NUMRW 0                    // [B]
#define ACC_DENRW 16                   // [B]
#define ACC_S00   32                   // [B]
#define ACC_S01   48                   // [B]
#define ACC_S11   64                   // [B]
#define ACC_SAS   80                   // [B]
#define ACC_DENCT 96                   // [B]
#define ACC_SDS   112                  // [B]
#define ACC_VOL   128                  // [B]
#define ACC_SSCT  144                  // [B][32*32]
#define ACC_OA    (ACC_SSCT+B*1024)    // [2][B][256]
#define ACC_SSP   (ACC_OA+2*B*256)     // [2][B][256]
#define ACC_PX    (ACC_SSP+2*B*256)    // [2][B][512]
#define ACC_DENP  (ACC_PX+2*B*512)     // [2][B]
#define ACC_LOSS  (ACC_DENP+2*B)       // [2] main, ortho
#define ACC_TOTAL (ACC_LOSS+2)

__device__ float g_acc[ACC_TOTAL];

// ---------------- scratch ----------------------------------------------------
__device__ float g_xh[BN*H];
__device__ int   g_cols[BN*MAXD];
__device__ int   g_deg[BN];
__device__ float g_srw[BN*2];
__device__ float4 g_ninfo[BN];        // {srw0, srw1, sqct, 0} packed per node
__device__ float g_sct[BN*KC];
__device__ float g_sqct[BN];
__device__ float g_wgap[BN*MAXD];
__device__ float g_wct[BN*MAXD];
__device__ float g_xg[2*BN*H];
__device__ float g_smc[2*BN*KM];
__device__ float g_x2[2*B*KM*H];

__device__ __forceinline__ float wsum(float v){
    #pragma unroll
    for(int o=16;o;o>>=1) v += __shfl_xor_sync(FULL, v, o);
    return v;
}
__device__ __forceinline__ float wsum16(float v){
    #pragma unroll
    for(int o=8;o;o>>=1) v += __shfl_xor_sync(FULL, v, o, 16);
    return v;
}

__global__ void k_init(){
    int i = blockIdx.x*blockDim.x + threadIdx.x;
    if (i < ACC_TOTAL) g_acc[i] = 0.f;
}

// fused: neighbor lists (prefetched float4 + ballot compaction, MLP=8) + vol +
//        xh=x@W1+b1 + rewiring softmax(k=2) + CT softmax(k=32) + scalar partials
__global__ void k_build_soft(const float* __restrict__ adj, const float* __restrict__ x,
                             const float* __restrict__ W1,  const float* __restrict__ b1,
                             const float* __restrict__ Wrw, const float* __restrict__ brw,
                             const float* __restrict__ Wct, const float* __restrict__ bct){
    __shared__ float W1s[IN*H];      // 16 KB
    __shared__ float Wcts[H*KC];     // 4 KB
    __shared__ float svol[8];
    __shared__ float sh[6];
    for (int i = threadIdx.x; i < IN*H; i += blockDim.x) W1s[i] = W1[i];
    for (int i = threadIdx.x; i < H*KC; i += blockDim.x) Wcts[i] = Wct[i];
    if (threadIdx.x < 6) sh[threadIdx.x] = 0.f;
    __syncthreads();

    int wid = (blockIdx.x*blockDim.x + threadIdx.x) >> 5;
    int lane = threadIdx.x & 31;
    int wz = threadIdx.x >> 5;

    // ---- neighbor list: prefetch entire row (MLP=8), then compact ----
    const float4* row = (const float4*)(adj + (size_t)wid * N);
    int* cols = g_cols + (size_t)wid * MAXD;
    float4 v[8];
    #pragma unroll
    for (int i = 0; i < 8; i++) v[i] = row[i*32 + lane];
    int cnt = 0;
    #pragma unroll
    for (int i = 0; i < 8; i++){
        bool n0=v[i].x!=0.f, n1=v[i].y!=0.f, n2=v[i].z!=0.f, n3=v[i].w!=0.f;
        unsigned m0=__ballot_sync(FULL,n0), m1=__ballot_sync(FULL,n1);
        unsigned m2=__ballot_sync(FULL,n2), m3=__ballot_sync(FULL,n3);
        unsigned below = (1u<<lane) - 1u;
        int idx = cnt + __popc(m0&below)+__popc(m1&below)+__popc(m2&below)+__popc(m3&below);
        int col0 = i*128 + lane*4;
        if(n0 && idx<MAXD){ cols[idx]=col0;   idx++; }
        if(n1 && idx<MAXD){ cols[idx]=col0+1; idx++; }
        if(n2 && idx<MAXD){ cols[idx]=col0+2; idx++; }
        if(n3 && idx<MAXD){ cols[idx]=col0+3; idx++; }
        cnt += __popc(m0)+__popc(m1)+__popc(m2)+__popc(m3);
    }
    int deg = cnt < MAXD ? cnt : MAXD;
    if (lane == 0){ g_deg[wid] = deg; svol[wz] = (float)deg; }

    // ---- xh = x @ W1 + b1 (lane = h) ----
    float acc = b1[lane];
    const float* xr = x + (size_t)wid*IN;
    #pragma unroll
    for (int c = 0; c < 4; c++){
        float xv = xr[c*32 + lane];
        #pragma unroll
        for (int j = 0; j < 32; j++)
            acc += __shfl_sync(FULL, xv, j) * W1s[(c*32+j)*H + lane];
    }
    g_xh[wid*H + lane] = acc;

    // ---- rewiring softmax (k=2) ----
    float a0 = wsum(acc*Wrw[lane*2])   + brw[0];
    float a1 = wsum(acc*Wrw[lane*2+1]) + brw[1];
    float mm = fmaxf(a0,a1);
    float e0 = expf(a0-mm), e1 = expf(a1-mm);
    float inv = 1.f/(e0+e1);
    float s0 = e0*inv, s1 = e1*inv;
    if (lane == 0){ g_srw[2*wid]=s0; g_srw[2*wid+1]=s1; }

    // ---- CT softmax (k=32, lane = k) ----
    float a = bct[lane];
    #pragma unroll
    for (int j = 0; j < 32; j++)
        a += __shfl_sync(FULL, acc, j) * Wcts[j*KC + lane];
    float m = a;
    #pragma unroll
    for (int o = 16; o; o >>= 1) m = fmaxf(m, __shfl_xor_sync(FULL, m, o));
    float e = expf(a - m);
    float s = e / wsum(e);
    g_sct[wid*KC + lane] = s;
    float sq = wsum(s*s);
    if (lane == 0){
        g_sqct[wid] = sq;
        g_ninfo[wid] = make_float4(s0, s1, sq, 0.f);
    }

    // ---- per-batch scalar partials ----
    if (lane == 0){
        atomicAdd(&sh[0], (float)deg*(s0*s0 + s1*s1)); // den_rw
        atomicAdd(&sh[1], s0*s0);                      // s00
        atomicAdd(&sh[2], s0*s1);                      // s01
        atomicAdd(&sh[3], s1*s1);                      // s11
        atomicAdd(&sh[4], sq);                         // den_ct
        atomicAdd(&sh[5], (float)deg*sq);              // sds
    }
    __syncthreads();
    int b = blockIdx.x >> 7;
    if (threadIdx.x < 6){
        const int dst[6] = {ACC_DENRW, ACC_S00, ACC_S01, ACC_S11, ACC_DENCT, ACC_SDS};
        atomicAdd(&g_acc[dst[threadIdx.x] + b], sh[threadIdx.x]);
    }
    if (threadIdx.x == 0){
        float vs = 0.f;
        #pragma unroll
        for (int i = 0; i < 8; i++) vs += svol[i];
        atomicAdd(&g_acc[ACC_VOL + b], vs);
    }
}

// S^T S partials from smem tiles (128-node chunks)
__global__ void k_ctpart(){
    int b = blockIdx.x >> 3, c = blockIdx.x & 7;
    int t = threadIdx.x;   // 1024
    __shared__ float S[128][33];
    int n0 = (b*N + c*128)*KC;
    #pragma unroll
    for (int i = 0; i < 4; i++){
        int idx = t + i*1024;
        S[idx>>5][idx&31] = g_sct[n0 + idx];
    }
    __syncthreads();
    int k = t >> 5, l = t & 31;
    float ssv = 0.f;
    #pragma unroll 8
    for (int n = 0; n < 128; n++)
        ssv += S[n][k]*S[n][l];
    atomicAdd(&g_acc[ACC_SSCT + b*1024 + t], ssv);
}

// MEGA-FUSED edge kernel, vectorized:
// - sct rows staged with stride 36 (float4 STS/LDS, conflict-free quarter-warps)
// - dot: 8 LDS.128 (row) + 8 LDS.128 broadcast (sn) + 2 accumulators
// - agg loop: packed {wg,wc,mc} float4 smem broadcast + unroll-4 coalesced LDG
__global__ void k_edgeagg(const float* __restrict__ Wr0, const float* __restrict__ br0,
                          const float* __restrict__ Wo0, const float* __restrict__ Wm0,
                          const float* __restrict__ bm0,
                          const float* __restrict__ Wr1, const float* __restrict__ br1,
                          const float* __restrict__ Wo1, const float* __restrict__ Wm1,
                          const float* __restrict__ bm1){
    __shared__ float  S[8*32*36];                   // 36 KB row staging
    __shared__ float4 SN[8][8];                     // sn per warp (32 floats)
    __shared__ float4 WGC[8][32];                   // {wg, wc, mc, 0} per edge
    __shared__ float Wrs[2][H*H], Wos[2][H*H], Wms[2][H*KM];
    __shared__ float shred[4];                      // num, sas, denp0, denp1
    for (int i = threadIdx.x; i < H*H; i += blockDim.x){
        Wrs[0][i] = Wr0[i]; Wrs[1][i] = Wr1[i];
        Wos[0][i] = Wo0[i]; Wos[1][i] = Wo1[i];
    }
    for (int i = threadIdx.x; i < H*KM; i += blockDim.x){
        Wms[0][i] = Wm0[i]; Wms[1][i] = Wm1[i];
    }
    if (threadIdx.x < 4) shred[threadIdx.x] = 0.f;
    __syncthreads();

    int wid = (blockIdx.x*blockDim.x + threadIdx.x) >> 5;
    int lane = threadIdx.x & 31;
    int w = threadIdx.x >> 5;
    float* Sw = S + w*32*36;
    float4* wgc = WGC[w];
    int b = wid >> 10, bN = b << 10;
    int deg = g_deg[wid];
    const int* cols = g_cols + wid*MAXD;
    float f_n = g_srw[2*wid];
    float s1n = g_srw[2*wid+1];
    float sn  = g_sct[wid*KC + lane];
    float sqn = g_sqct[wid];
    float invvol = 1.f/(g_acc[ACC_VOL + b] + EPSV);
    float num_acc = 0.f, sas_acc = 0.f;
    float dg_acc = 0.f, dc_acc = 0.f;
    float y_gap = 0.f, y_ct = 0.f;         // lane = h

    // stage sn into smem once (read back as float4 broadcast)
    ((float*)SN[w])[lane] = sn;
    __syncwarp();

    int r8 = lane >> 3;        // 0..3 : row group
    int p8 = lane & 7;         // 0..7 : float4 slot

    for (int j0 = 0; j0 < deg; j0 += 32){
        int tlen = deg - j0; if (tlen > 32) tlen = 32;
        // cooperative vectorized staging of up to 32 neighbor sct rows
        #pragma unroll
        for (int g = 0; g < 8; g++){
            int e = g*4 + r8;
            int j = j0 + e;
            if (j < deg){
                int rm = bN + cols[j];
                float4 v = ((const float4*)(g_sct + (size_t)rm*KC))[p8];
                ((float4*)(Sw + e*36))[p8] = v;
            }
        }
        __syncwarp();
        int j = j0 + lane;
        bool act = j < deg;
        int mc = act ? cols[j] : 0;
        const float4* row4 = (const float4*)(Sw + lane*36);
        const float4* sn4  = SN[w];
        float dA = 0.f, dB = 0.f;
        #pragma unroll
        for (int q = 0; q < 4; q++){
            float4 va = row4[2*q],   sa = sn4[2*q];
            float4 vb = row4[2*q+1], sb = sn4[2*q+1];
            dA += va.x*sa.x + va.y*sa.y + va.z*sa.z + va.w*sa.w;
            dB += vb.x*sb.x + vb.y*sb.y + vb.z*sb.z + vb.w*sb.w;
        }
        float dot = dA + dB;
        float wg = 0.f, wc = 0.f;
        if (act){
            float4 ni = g_ninfo[bN + mc];
            float d = f_n - ni.x;
            float q2 = sqn + ni.z - 2.f*dot;
            wg = 1.f - d*d;
            wc = sqrtf(fmaxf(q2, 0.f) + 1e-12f)*invvol;
            g_wgap[wid*MAXD + j] = wg;
            g_wct [wid*MAXD + j] = wc;
            num_acc += f_n*ni.x + s1n*ni.y;
            sas_acc += dot;
        }
        dg_acc += wg; dc_acc += wc;
        wgc[lane] = make_float4(wg, wc, __int_as_float(mc), 0.f);
        __syncwarp();
        // both-branch aggregation: broadcast LDS.128 + coalesced LDG, unroll 4
        #pragma unroll 4
        for (int jj = 0; jj < tlen; jj++){
            float4 q = wgc[jj];
            float xv = g_xh[(bN + __float_as_int(q.z))*H + lane];
            y_gap += q.x*xv;
            y_ct  += q.y*xv;
        }
        __syncwarp();
    }
    num_acc = wsum(num_acc);
    sas_acc = wsum(sas_acc);
    float dsum_g = wsum(dg_acc);
    float dsum_c = wsum(dc_acc);

    // lin + pool softmax for both branches
    float xh = g_xh[wid*H + lane];
    float den_g = 0.f, den_c = 0.f;
    #pragma unroll
    for (int br = 0; br < 2; br++){
        float y = br ? y_ct : y_gap;
        const float* brel = br ? br1 : br0;
        const float* bmc  = br ? bm1 : bm0;
        const float* Wr = Wrs[br];
        const float* Wo = Wos[br];
        const float* Wm = Wms[br];
        float acc = brel[lane];
        #pragma unroll
        for (int j = 0; j < 32; j++){
            acc += __shfl_sync(FULL, y,  j) * Wr[j*H + lane];
            acc += __shfl_sync(FULL, xh, j) * Wo[j*H + lane];
        }
        g_xg[br*BN*H + wid*H + lane] = acc;
        float a = (lane < KM) ? bmc[lane] : 0.f;
        #pragma unroll
        for (int j = 0; j < 32; j++){
            float xj = __shfl_sync(FULL, acc, j);
            if (lane < KM) a += xj * Wm[j*KM + lane];
        }
        float mm = a;
        #pragma unroll
        for (int o = 8; o; o >>= 1) mm = fmaxf(mm, __shfl_xor_sync(FULL, mm, o, 16));
        float e = (lane < KM) ? expf(a - mm) : 0.f;
        float es = wsum16(e);
        float s = e/es;
        if (lane < KM) g_smc[br*BN*KM + wid*KM + lane] = s;
        float sq = wsum16(s*s);
        if (br) den_c = sq; else den_g = sq;
    }
    if (lane == 0){
        atomicAdd(&shred[0], num_acc);
        atomicAdd(&shred[1], sas_acc);
        atomicAdd(&shred[2], dsum_g*den_g);
        atomicAdd(&shred[3], dsum_c*den_c);
    }
    __syncthreads();
    if (threadIdx.x < 4){
        int bb = blockIdx.x >> 7;
        const int dst[4] = {ACC_NUMRW, ACC_SAS, ACC_DENP, ACC_DENP + B};
        atomicAdd(&g_acc[dst[threadIdx.x] + bb], shred[threadIdx.x]);
    }
}

// CT losses (ortho over 32x32 S^T S + ct term) + rewiring losses (fused)
__global__ void k_ctfin(){
    int b = blockIdx.x, t = threadIdx.x;   // 1024
    __shared__ float ss[1024], red[1024], nrm_s;
    ss[t] = g_acc[ACC_SSCT + b*1024 + t];
    __syncthreads();
    red[t] = ss[t]*ss[t];
    __syncthreads();
    for (int o = 512; o; o >>= 1){ if (t < o) red[t] += red[t+o]; __syncthreads(); }
    if (t == 0) nrm_s = sqrtf(red[0]);
    __syncthreads();
    int k = t >> 5, l = t & 31;
    float d = ss[t]/nrm_s - ((k == l) ? 0.17677669529663687f : 0.f);
    red[t] = d*d;
    __syncthreads();
    for (int o = 512; o; o >>= 1){ if (t < o) red[t] += red[t+o]; __syncthreads(); }
    if (t == 0){
        float sas = g_acc[ACC_SAS + b];
        float den = g_acc[ACC_DENCT + b] + EPSV;
        float sds = g_acc[ACC_SDS + b];
        float lm = ((sds - sas)/den)/(float)B;
        float lo = sqrtf(red[0])/(float)B;
        float num = g_acc[ACC_NUMRW + b];
        float dnr = g_acc[ACC_DENRW + b] + EPSV;
        float s00 = g_acc[ACC_S00 + b];
        float s01 = g_acc[ACC_S01 + b];
        float s11 = g_acc[ACC_S11 + b];
        float nrm = sqrtf(s00*s00 + 2.f*s01*s01 + s11*s11);
        const float isk = 0.70710678118654752f;
        float d00 = s00/nrm - isk, d01 = s01/nrm, d11 = s11/nrm - isk;
        lm += -(num/dnr)/(float)B;
        lo += sqrtf(d00*d00 + 2.f*d01*d01 + d11*d11)/(float)B;
        atomicAdd(&g_acc[ACC_LOSS],   lm);
        atomicAdd(&g_acc[ACC_LOSS+1], lo);
    }
}

// fused t16 + pooled partials over 32-node chunks; both half-warps gather
__global__ void k_pool(){
    int c = blockIdx.x, b = blockIdx.y, br = blockIdx.z;
    int t = threadIdx.x;              // 1024 = 32 warps
    int w = t >> 5, lane = t & 31;
    __shared__ float ssmc[32][17];
    __shared__ float st16[32][17];
    __shared__ float sxg[32][33];
    const float* smc = g_smc + br*BN*KM;
    const float* xg  = g_xg  + br*BN*H;
    int bN = b*N;
    int r = bN + c*32 + w;
    if (lane < KM) ssmc[w][lane] = smc[r*KM + lane];
    sxg[w][lane] = xg[r*H + lane];
    {
        int deg = g_deg[r];
        const int* cols = g_cols + r*MAXD;
        const float* w_arr = (br ? g_wct : g_wgap) + r*MAXD;
        int half = lane >> 4;       // both half-warps gather alternate edges
        int l16 = lane & 15;
        float tacc = 0.f;
        #pragma unroll 2
        for (int j = half; j < deg; j += 2){
            int m = cols[j];
            float wv = w_arr[j];
            tacc += wv * smc[(bN+m)*KM + l16];
        }
        tacc += __shfl_down_sync(FULL, tacc, 16);
        if (lane < KM) st16[w][lane] = tacc;
    }
    __syncthreads();
    int base = (br*B + b)*256;
    if (t < 256){
        int k = t >> 4, l = t & 15;
        float oa = 0.f;
        #pragma unroll 8
        for (int n = 0; n < 32; n++) oa += ssmc[n][k]*st16[n][l];
        atomicAdd(&g_acc[ACC_OA + base + t], oa);
    } else if (t < 512){
        int k = (t-256) >> 4, l = t & 15;
        float ssv = 0.f;
        #pragma unroll 8
        for (int n = 0; n < 32; n++) ssv += ssmc[n][k]*ssmc[n][l];
        atomicAdd(&g_acc[ACC_SSP + base + (t-256)], ssv);
    } else {
        int kk = (t-512) >> 5, h = t & 31;
        float px = 0.f;
        #pragma unroll 8
        for (int n = 0; n < 32; n++) px += ssmc[n][kk]*sxg[n][h];
        atomicAdd(&g_acc[ACC_PX + (br*B + b)*512 + (t-512)], px);
    }
}

// finalize pool: losses + normalized pooladj + pooled DGC (conv2gap weights)
__global__ void k_poolfin(const float* __restrict__ W2g_rel, const float* __restrict__ b2g,
                          const float* __restrict__ W2g_root){
    int b = blockIdx.x, br = blockIdx.y, t = threadIdx.x;   // 512
    __shared__ float oa[256], ssm[256], px[512], t2[512], pa[256], red[512], nrm_s;
    int base = (br*B + b)*256;
    if (t < 256){ oa[t] = g_acc[ACC_OA + base + t]; ssm[t] = g_acc[ACC_SSP + base + t]; }
    px[t] = g_acc[ACC_PX + (br*B + b)*512 + t];
    __syncthreads();
    red[t] = (t < 256) ? ssm[t]*ssm[t] : 0.f;
    __syncthreads();
    for (int o = 256; o; o >>= 1){ if (t < o) red[t] += red[t+o]; __syncthreads(); }
    if (t == 0) nrm_s = sqrtf(red[0]);
    __syncthreads();
    if (t < 256){
        int k = t >> 4, l = t & 15;
        float d = ssm[t]/nrm_s - ((k == l) ? 0.25f : 0.f);
        red[t] = d*d;
    } else red[t] = 0.f;
    __syncthreads();
    for (int o = 256; o; o >>= 1){ if (t < o) red[t] += red[t+o]; __syncthreads(); }
    if (t == 0){
        float num = 0.f;
        #pragma unroll
        for (int k = 0; k < KM; k++) num += oa[k*KM + k];
        float den = g_acc[ACC_DENP + br*B + b] + EPSV;
        atomicAdd(&g_acc[ACC_LOSS],   -(num/den)/(float)B);
        atomicAdd(&g_acc[ACC_LOSS+1], sqrtf(red[0])/(float)B);
    }
    __shared__ float dsq[KM];
    if (t < KM){
        float rs = 0.f;
        #pragma unroll
        for (int l = 0; l < KM; l++) rs += (l == t) ? 0.f : oa[t*KM + l];
        dsq[t] = sqrtf(rs) + EPSV;
    }
    __syncthreads();
    if (t < 256){
        int k = t >> 4, l = t & 15;
        pa[t] = (k == l) ? 0.f : oa[t]/(dsq[k]*dsq[l]);
    }
    __syncthreads();
    int k = t >> 5, h = t & 31;
    float a = 0.f;
    #pragma unroll
    for (int l = 0; l < KM; l++) a += pa[k*KM + l]*px[l*H + h];
    t2[t] = a;
    __syncthreads();
    float accv = b2g[h];
    #pragma unroll
    for (int j = 0; j < H; j++)
        accv += t2[k*H + j]*W2g_rel[j*H + h] + px[k*H + j]*W2g_root[j*H + h];
    g_x2[br*B*KM*H + b*KM*H + t] = accv;
}

__global__ void k_readout(const float* __restrict__ Wcat, const float* __restrict__ bcat,
                          const float* __restrict__ W2,  const float* __restrict__ b2,
                          const float* __restrict__ W3,  const float* __restrict__ b3,
                          float* __restrict__ out){
    int b = blockIdx.x, h = threadIdx.x;   // 32
    __shared__ float h1[H], h2[H], lg[10];
    float acc = 0.f;
    for (int kk = 0; kk < KM; kk++){
        float z = bcat[h];
        #pragma unroll
        for (int j = 0; j < H; j++) z += g_x2[b*KM*H + kk*H + j]*Wcat[j*H + h];
        #pragma unroll
        for (int j = 0; j < H; j++) z += g_x2[B*KM*H + b*KM*H + kk*H + j]*Wcat[(H+j)*H + h];
        acc += fmaxf(z, 0.f);
    }
    h1[h] = acc; __syncwarp();
    float z2 = b2[h];
    #pragma unroll
    for (int j = 0; j < H; j++) z2 += h1[j]*W2[j*H + h];
    h2[h] = fmaxf(z2, 0.f); __syncwarp();
    if (h < 10){
        float z = b3[h];
        #pragma unroll
        for (int j = 0; j < H; j++) z += h2[j]*W3[j*10 + h];
        lg[h] = z;
    }
    __syncwarp();
    if (h < 10){
        float m = lg[0];
        #pragma unroll
        for (int i = 1; i < 10; i++) m = fmaxf(m, lg[i]);
        float s = 0.f;
        #pragma unroll
        for (int i = 0; i < 10; i++) s += expf(lg[i] - m);
        out[b*10 + h] = lg[h] - m - logf(s);
    }
    if (b == 0 && h == 31){
        out[B*10]     = g_acc[ACC_LOSS];
        out[B*10 + 1] = g_acc[ACC_LOSS+1];
    }
}

extern "C" void kernel_launch(void* const* d_in, const int* in_sizes, int n_in,
                              void* d_out, int out_size){
    const float* x      = (const float*)d_in[0];
    const float* adj    = (const float*)d_in[1];
    const float* W1     = (const float*)d_in[3];
    const float* b1     = (const float*)d_in[4];
    const float* Wrw    = (const float*)d_in[5];
    const float* brw    = (const float*)d_in[6];
    const float* Wg_rel = (const float*)d_in[7];
    const float* bg     = (const float*)d_in[8];
    const float* Wg_root= (const float*)d_in[9];
    const float* Wmcg   = (const float*)d_in[10];
    const float* bmcg   = (const float*)d_in[11];
    const float* W2g_rel= (const float*)d_in[12];
    const float* b2g    = (const float*)d_in[13];
    const float* W2g_root=(const float*)d_in[14];
    const float* Wct    = (const float*)d_in[15];
    const float* bct    = (const float*)d_in[16];
    const float* Wc_rel = (const float*)d_in[17];
    const float* bc     = (const float*)d_in[18];
    const float* Wc_root= (const float*)d_in[19];
    const float* Wmcc   = (const float*)d_in[20];
    const float* bmcc   = (const float*)d_in[21];
    const float* Wcat   = (const float*)d_in[22];
    const float* bcat   = (const float*)d_in[23];
    const float* W2     = (const float*)d_in[24];
    const float* b2     = (const float*)d_in[25];
    const float* W3     = (const float*)d_in[26];
    const float* b3     = (const float*)d_in[27];
    float* out = (float*)d_out;

    k_init<<<(ACC_TOTAL+511)/512, 512>>>();
    k_build_soft<<<BN/8, 256>>>(adj, x, W1, b1, Wrw, brw, Wct, bct);
    k_ctpart<<<B*8, 1024>>>();
    k_edgeagg<<<BN/8, 256>>>(Wg_rel, bg, Wg_root, Wmcg, bmcg,
                             Wc_rel, bc, Wc_root, Wmcc, bmcc);
    k_ctfin<<<B, 1024>>>();
    k_pool<<<dim3(32, B, 2), 1024>>>();
    k_poolfin<<<dim3(B, 2), 512>>>(W2g_rel, b2g, W2g_root);
    k_readout<<<B, 32>>>(Wcat, bcat, W2, b2, W3, b3, out);

    (void)in_sizes; (void)n_in; (void)out_size;
}

// round 10
// speedup vs baseline: 3.2770x; 1.0637x over previous
#include <cuda_runtime.h>
#include <math.h>
#include <stdint.h>

#define B 16
#define N 1024
#define BN (B*N)
#define IN 128
#define H 32
#define KC 32
#define KM 16
#define MAXD 128
#define EPSV 1e-15f
#define FULL 0xffffffffu

// ---------------- accumulator slab (atomically accumulated; zeroed per run) --
#define ACC_NUMRW 0                    // [B]
#define ACC_DENRW 16                   // [B]
#define ACC_S00   32                   // [B]
#define ACC_S01   48                   // [B]
#define ACC_S11   64                   // [B]
#define ACC_SAS   80                   // [B]
#define ACC_DENCT 96                   // [B]
#define ACC_SDS   112                  // [B]
#define ACC_VOL   128                  // [B]
#define ACC_SSCT  144                  // [B][32*32]
#define ACC_OA    (ACC_SSCT+B*1024)    // [2][B][256]
#define ACC_SSP   (ACC_OA+2*B*256)     // [2][B][256]
#define ACC_PX    (ACC_SSP+2*B*256)    // [2][B][512]
#define ACC_DENP  (ACC_PX+2*B*512)     // [2][B]
#define ACC_LOSS  (ACC_DENP+2*B)       // [2] main, ortho
#define ACC_TOTAL (ACC_LOSS+2)

__device__ float g_acc[ACC_TOTAL];

// ---------------- scratch ----------------------------------------------------
__device__ float g_xh[BN*H];
__device__ int   g_cols[BN*MAXD];
__device__ int   g_deg[BN];
__device__ float g_srw[BN*2];
__device__ float4 g_ninfo[BN];        // {srw0, srw1, sqct, 0} packed per node
__device__ float g_sct[BN*KC];
__device__ float g_sqct[BN];
__device__ float g_wgap[BN*MAXD];
__device__ float g_wct[BN*MAXD];
__device__ float g_xg[2*BN*H];
__device__ float g_smc[2*BN*KM];
__device__ float g_x2[2*B*KM*H];

__device__ __forceinline__ float wsum(float v){
    #pragma unroll
    for(int o=16;o;o>>=1) v += __shfl_xor_sync(FULL, v, o);
    return v;
}
__device__ __forceinline__ float wsum16(float v){
    #pragma unroll
    for(int o=8;o;o>>=1) v += __shfl_xor_sync(FULL, v, o, 16);
    return v;
}

__global__ void k_init(){
    int i = blockIdx.x*blockDim.x + threadIdx.x;
    if (i < ACC_TOTAL) g_acc[i] = 0.f;
}

// fused: neighbor lists (prefetched float4 + ballot compaction, MLP=8) + vol +
//        xh=x@W1+b1 + rewiring softmax(k=2) + CT softmax(k=32) + scalar partials
__global__ void k_build_soft(const float* __restrict__ adj, const float* __restrict__ x,
                             const float* __restrict__ W1,  const float* __restrict__ b1,
                             const float* __restrict__ Wrw, const float* __restrict__ brw,
                             const float* __restrict__ Wct, const float* __restrict__ bct){
    __shared__ float W1s[IN*H];      // 16 KB
    __shared__ float Wcts[H*KC];     // 4 KB
    __shared__ float svol[8];
    __shared__ float sh[6];
    for (int i = threadIdx.x; i < IN*H; i += blockDim.x) W1s[i] = W1[i];
    for (int i = threadIdx.x; i < H*KC; i += blockDim.x) Wcts[i] = Wct[i];
    if (threadIdx.x < 6) sh[threadIdx.x] = 0.f;
    __syncthreads();

    int wid = (blockIdx.x*blockDim.x + threadIdx.x) >> 5;
    int lane = threadIdx.x & 31;
    int wz = threadIdx.x >> 5;

    // ---- neighbor list: prefetch entire row (MLP=8), then compact ----
    const float4* row = (const float4*)(adj + (size_t)wid * N);
    int* cols = g_cols + (size_t)wid * MAXD;
    float4 v[8];
    #pragma unroll
    for (int i = 0; i < 8; i++) v[i] = row[i*32 + lane];
    int cnt = 0;
    #pragma unroll
    for (int i = 0; i < 8; i++){
        bool n0=v[i].x!=0.f, n1=v[i].y!=0.f, n2=v[i].z!=0.f, n3=v[i].w!=0.f;
        unsigned m0=__ballot_sync(FULL,n0), m1=__ballot_sync(FULL,n1);
        unsigned m2=__ballot_sync(FULL,n2), m3=__ballot_sync(FULL,n3);
        unsigned below = (1u<<lane) - 1u;
        int idx = cnt + __popc(m0&below)+__popc(m1&below)+__popc(m2&below)+__popc(m3&below);
        int col0 = i*128 + lane*4;
        if(n0 && idx<MAXD){ cols[idx]=col0;   idx++; }
        if(n1 && idx<MAXD){ cols[idx]=col0+1; idx++; }
        if(n2 && idx<MAXD){ cols[idx]=col0+2; idx++; }
        if(n3 && idx<MAXD){ cols[idx]=col0+3; idx++; }
        cnt += __popc(m0)+__popc(m1)+__popc(m2)+__popc(m3);
    }
    int deg = cnt < MAXD ? cnt : MAXD;
    if (lane == 0){ g_deg[wid] = deg; svol[wz] = (float)deg; }

    // ---- xh = x @ W1 + b1 (lane = h) ----
    float acc = b1[lane];
    const float* xr = x + (size_t)wid*IN;
    #pragma unroll
    for (int c = 0; c < 4; c++){
        float xv = xr[c*32 + lane];
        #pragma unroll
        for (int j = 0; j < 32; j++)
            acc += __shfl_sync(FULL, xv, j) * W1s[(c*32+j)*H + lane];
    }
    g_xh[wid*H + lane] = acc;

    // ---- rewiring softmax (k=2) ----
    float a0 = wsum(acc*Wrw[lane*2])   + brw[0];
    float a1 = wsum(acc*Wrw[lane*2+1]) + brw[1];
    float mm = fmaxf(a0,a1);
    float e0 = expf(a0-mm), e1 = expf(a1-mm);
    float inv = 1.f/(e0+e1);
    float s0 = e0*inv, s1 = e1*inv;
    if (lane == 0){ g_srw[2*wid]=s0; g_srw[2*wid+1]=s1; }

    // ---- CT softmax (k=32, lane = k) ----
    float a = bct[lane];
    #pragma unroll
    for (int j = 0; j < 32; j++)
        a += __shfl_sync(FULL, acc, j) * Wcts[j*KC + lane];
    float m = a;
    #pragma unroll
    for (int o = 16; o; o >>= 1) m = fmaxf(m, __shfl_xor_sync(FULL, m, o));
    float e = expf(a - m);
    float s = e / wsum(e);
    g_sct[wid*KC + lane] = s;
    float sq = wsum(s*s);
    if (lane == 0){
        g_sqct[wid] = sq;
        g_ninfo[wid] = make_float4(s0, s1, sq, 0.f);
    }

    // ---- per-batch scalar partials ----
    if (lane == 0){
        atomicAdd(&sh[0], (float)deg*(s0*s0 + s1*s1)); // den_rw
        atomicAdd(&sh[1], s0*s0);                      // s00
        atomicAdd(&sh[2], s0*s1);                      // s01
        atomicAdd(&sh[3], s1*s1);                      // s11
        atomicAdd(&sh[4], sq);                         // den_ct
        atomicAdd(&sh[5], (float)deg*sq);              // sds
    }
    __syncthreads();
    int b = blockIdx.x >> 7;
    if (threadIdx.x < 6){
        const int dst[6] = {ACC_DENRW, ACC_S00, ACC_S01, ACC_S11, ACC_DENCT, ACC_SDS};
        atomicAdd(&g_acc[dst[threadIdx.x] + b], sh[threadIdx.x]);
    }
    if (threadIdx.x == 0){
        float vs = 0.f;
        #pragma unroll
        for (int i = 0; i < 8; i++) vs += svol[i];
        atomicAdd(&g_acc[ACC_VOL + b], vs);
    }
}

// S^T S partials from smem tiles (128-node chunks)
__global__ void k_ctpart(){
    int b = blockIdx.x >> 3, c = blockIdx.x & 7;
    int t = threadIdx.x;   // 1024
    __shared__ float S[128][33];
    int n0 = (b*N + c*128)*KC;
    #pragma unroll
    for (int i = 0; i < 4; i++){
        int idx = t + i*1024;
        S[idx>>5][idx&31] = g_sct[n0 + idx];
    }
    __syncthreads();
    int k = t >> 5, l = t & 31;
    float ssv = 0.f;
    #pragma unroll 8
    for (int n = 0; n < 128; n++)
        ssv += S[n][k]*S[n][l];
    atomicAdd(&g_acc[ACC_SSCT + b*1024 + t], ssv);
}

// MEGA-FUSED edge kernel, 16-edge subtiles for occupancy (~41.5KB smem -> 5 blk/SM):
// - sct rows staged vectorized; dot split across two lanes (16 elems each) + shfl combine
// - agg loop: packed {wg,wc,mc} smem broadcast + unroll-4 coalesced LDG
__global__ void k_edgeagg(const float* __restrict__ Wr0, const float* __restrict__ br0,
                          const float* __restrict__ Wo0, const float* __restrict__ Wm0,
                          const float* __restrict__ bm0,
                          const float* __restrict__ Wr1, const float* __restrict__ br1,
                          const float* __restrict__ Wo1, const float* __restrict__ Wm1,
                          const float* __restrict__ bm1){
    __shared__ float  S[8*16*36];                   // 18 KB row staging
    __shared__ float4 SN[8][8];                     // sn per warp (32 floats)
    __shared__ float4 WGC[8][16];                   // {wg, wc, mc, 0} per edge
    __shared__ float Wrs[2][H*H], Wos[2][H*H], Wms[2][H*KM];
    __shared__ float shred[4];                      // num, sas, denp0, denp1
    for (int i = threadIdx.x; i < H*H; i += blockDim.x){
        Wrs[0][i] = Wr0[i]; Wrs[1][i] = Wr1[i];
        Wos[0][i] = Wo0[i]; Wos[1][i] = Wo1[i];
    }
    for (int i = threadIdx.x; i < H*KM; i += blockDim.x){
        Wms[0][i] = Wm0[i]; Wms[1][i] = Wm1[i];
    }
    if (threadIdx.x < 4) shred[threadIdx.x] = 0.f;
    __syncthreads();

    int wid = (blockIdx.x*blockDim.x + threadIdx.x) >> 5;
    int lane = threadIdx.x & 31;
    int w = threadIdx.x >> 5;
    float* Sw = S + w*16*36;
    float4* wgc = WGC[w];
    int b = wid >> 10, bN = b << 10;
    int deg = g_deg[wid];
    const int* cols = g_cols + wid*MAXD;
    float f_n = g_srw[2*wid];
    float s1n = g_srw[2*wid+1];
    float sn  = g_sct[wid*KC + lane];
    float sqn = g_sqct[wid];
    float invvol = 1.f/(g_acc[ACC_VOL + b] + EPSV);
    float num_acc = 0.f, sas_acc = 0.f;
    float dg_acc = 0.f, dc_acc = 0.f;
    float y_gap = 0.f, y_ct = 0.f;         // lane = h

    // stage sn into smem once (read back as float4)
    ((float*)SN[w])[lane] = sn;
    __syncwarp();

    int r8 = lane >> 3;        // 0..3 : row group
    int p8 = lane & 7;         // 0..7 : float4 slot
    int eh = lane & 15;        // edge within subtile
    int half = lane >> 4;      // which 16 elements of the dot

    for (int j0 = 0; j0 < deg; j0 += 16){
        int tlen = deg - j0; if (tlen > 16) tlen = 16;
        // cooperative vectorized staging of up to 16 neighbor sct rows
        #pragma unroll
        for (int g = 0; g < 4; g++){
            int e = g*4 + r8;
            int j = j0 + e;
            if (j < deg){
                int rm = bN + cols[j];
                float4 v = ((const float4*)(g_sct + (size_t)rm*KC))[p8];
                ((float4*)(Sw + e*36))[p8] = v;
            }
        }
        __syncwarp();
        int j = j0 + eh;
        bool act = j < deg;
        int mc = act ? cols[j] : 0;
        const float4* row4 = (const float4*)(Sw + eh*36) + half*4;
        const float4* sn4  = SN[w] + half*4;
        float dA = 0.f, dB = 0.f;
        #pragma unroll
        for (int q = 0; q < 2; q++){
            float4 va = row4[2*q],   sa = sn4[2*q];
            float4 vb = row4[2*q+1], sb = sn4[2*q+1];
            dA += va.x*sa.x + va.y*sa.y + va.z*sa.z + va.w*sa.w;
            dB += vb.x*sb.x + vb.y*sb.y + vb.z*sb.z + vb.w*sb.w;
        }
        float dh = dA + dB;
        float dot = dh + __shfl_xor_sync(FULL, dh, 16);
        float wg = 0.f, wc = 0.f;
        if (act && half == 0){
            float4 ni = g_ninfo[bN + mc];
            float d = f_n - ni.x;
            float q2 = sqn + ni.z - 2.f*dot;
            wg = 1.f - d*d;
            wc = sqrtf(fmaxf(q2, 0.f) + 1e-12f)*invvol;
            g_wgap[wid*MAXD + j] = wg;
            g_wct [wid*MAXD + j] = wc;
            num_acc += f_n*ni.x + s1n*ni.y;
            sas_acc += dot;
        }
        dg_acc += wg; dc_acc += wc;
        if (half == 0) wgc[eh] = make_float4(wg, wc, __int_as_float(mc), 0.f);
        __syncwarp();
        // both-branch aggregation: broadcast LDS.128 + coalesced LDG, unroll 4
        #pragma unroll 4
        for (int jj = 0; jj < tlen; jj++){
            float4 q = wgc[jj];
            float xv = g_xh[(bN + __float_as_int(q.z))*H + lane];
            y_gap += q.x*xv;
            y_ct  += q.y*xv;
        }
        __syncwarp();
    }
    num_acc = wsum(num_acc);
    sas_acc = wsum(sas_acc);
    float dsum_g = wsum(dg_acc);
    float dsum_c = wsum(dc_acc);

    // lin + pool softmax for both branches
    float xh = g_xh[wid*H + lane];
    float den_g = 0.f, den_c = 0.f;
    #pragma unroll
    for (int br = 0; br < 2; br++){
        float y = br ? y_ct : y_gap;
        const float* brel = br ? br1 : br0;
        const float* bmc  = br ? bm1 : bm0;
        const float* Wr = Wrs[br];
        const float* Wo = Wos[br];
        const float* Wm = Wms[br];
        float acc = brel[lane];
        #pragma unroll
        for (int j = 0; j < 32; j++){
            acc += __shfl_sync(FULL, y,  j) * Wr[j*H + lane];
            acc += __shfl_sync(FULL, xh, j) * Wo[j*H + lane];
        }
        g_xg[br*BN*H + wid*H + lane] = acc;
        float a = (lane < KM) ? bmc[lane] : 0.f;
        #pragma unroll
        for (int j = 0; j < 32; j++){
            float xj = __shfl_sync(FULL, acc, j);
            if (lane < KM) a += xj * Wm[j*KM + lane];
        }
        float mm = a;
        #pragma unroll
        for (int o = 8; o; o >>= 1) mm = fmaxf(mm, __shfl_xor_sync(FULL, mm, o, 16));
        float e = (lane < KM) ? expf(a - mm) : 0.f;
        float es = wsum16(e);
        float s = e/es;
        if (lane < KM) g_smc[br*BN*KM + wid*KM + lane] = s;
        float sq = wsum16(s*s);
        if (br) den_c = sq; else den_g = sq;
    }
    if (lane == 0){
        atomicAdd(&shred[0], num_acc);
        atomicAdd(&shred[1], sas_acc);
        atomicAdd(&shred[2], dsum_g*den_g);
        atomicAdd(&shred[3], dsum_c*den_c);
    }
    __syncthreads();
    if (threadIdx.x < 4){
        int bb = blockIdx.x >> 7;
        const int dst[4] = {ACC_NUMRW, ACC_SAS, ACC_DENP, ACC_DENP + B};
        atomicAdd(&g_acc[dst[threadIdx.x] + bb], shred[threadIdx.x]);
    }
}

// CT losses (ortho over 32x32 S^T S + ct term) + rewiring losses (fused)
__global__ void k_ctfin(){
    int b = blockIdx.x, t = threadIdx.x;   // 1024
    __shared__ float ss[1024], red[1024], nrm_s;
    ss[t] = g_acc[ACC_SSCT + b*1024 + t];
    __syncthreads();
    red[t] = ss[t]*ss[t];
    __syncthreads();
    for (int o = 512; o; o >>= 1){ if (t < o) red[t] += red[t+o]; __syncthreads(); }
    if (t == 0) nrm_s = sqrtf(red[0]);
    __syncthreads();
    int k = t >> 5, l = t & 31;
    float d = ss[t]/nrm_s - ((k == l) ? 0.17677669529663687f : 0.f);
    red[t] = d*d;
    __syncthreads();
    for (int o = 512; o; o >>= 1){ if (t < o) red[t] += red[t+o]; __syncthreads(); }
    if (t == 0){
        float sas = g_acc[ACC_SAS + b];
        float den = g_acc[ACC_DENCT + b] + EPSV;
        float sds = g_acc[ACC_SDS + b];
        float lm = ((sds - sas)/den)/(float)B;
        float lo = sqrtf(red[0])/(float)B;
        float num = g_acc[ACC_NUMRW + b];
        float dnr = g_acc[ACC_DENRW + b] + EPSV;
        float s00 = g_acc[ACC_S00 + b];
        float s01 = g_acc[ACC_S01 + b];
        float s11 = g_acc[ACC_S11 + b];
        float nrm = sqrtf(s00*s00 + 2.f*s01*s01 + s11*s11);
        const float isk = 0.70710678118654752f;
        float d00 = s00/nrm - isk, d01 = s01/nrm, d11 = s11/nrm - isk;
        lm += -(num/dnr)/(float)B;
        lo += sqrtf(d00*d00 + 2.f*d01*d01 + d11*d11)/(float)B;
        atomicAdd(&g_acc[ACC_LOSS],   lm);
        atomicAdd(&g_acc[ACC_LOSS+1], lo);
    }
}

// batch-staged pool: one block = (128-node chunk, batch, branch).
// Full batch smc (64KB) staged in DYNAMIC smem; t16 gathers hit shared memory.
// Pooled partials (OA/SSP/PX) computed over the 128-node chunk.
__global__ void k_pool(){
    extern __shared__ float smc_s[];       // N*KM = 16384 floats = 64KB
    __shared__ float st16[128*17];
    int c = blockIdx.x, b = blockIdx.y, br = blockIdx.z;
    int t = threadIdx.x;                   // 1024
    int w = t >> 5, lane = t & 31;
    int bN = b*N;
    const float* smc = g_smc + br*BN*KM;
    {
        float4* dst = (float4*)smc_s;
        const float4* src = (const float4*)(smc + bN*KM);
        #pragma unroll
        for (int i = 0; i < 4; i++) dst[t + i*1024] = src[t + i*1024];
    }
    __syncthreads();
    int half = lane >> 4, l16 = lane & 15;
    #pragma unroll
    for (int q = 0; q < 4; q++){
        int nl = c*128 + w*4 + q;          // local node in batch
        int r = bN + nl;
        int deg = g_deg[r];
        const int* cols = g_cols + r*MAXD;
        const float* w_arr = (br ? g_wct : g_wgap) + r*MAXD;
        float tacc = 0.f;
        #pragma unroll 2
        for (int j = half; j < deg; j += 2)
            tacc += w_arr[j] * smc_s[cols[j]*KM + l16];
        tacc += __shfl_down_sync(FULL, tacc, 16);
        if (lane < KM) st16[(w*4+q)*17 + l16] = tacc;
    }
    __syncthreads();
    int base = (br*B + b)*256;
    int n0 = c*128;
    if (t < 256){
        int k = t >> 4, l = t & 15;
        float oa = 0.f;
        #pragma unroll 4
        for (int n = 0; n < 128; n++)
            oa += smc_s[(n0+n)*KM + k] * st16[n*17 + l];
        atomicAdd(&g_acc[ACC_OA + base + t], oa);
    } else if (t < 512){
        int k = (t-256) >> 4, l = t & 15;
        float ssv = 0.f;
        #pragma unroll 4
        for (int n = 0; n < 128; n++)
            ssv += smc_s[(n0+n)*KM + k] * smc_s[(n0+n)*KM + l];
        atomicAdd(&g_acc[ACC_SSP + base + (t-256)], ssv);
    } else {
        int kk = (t-512) >> 5, h = t & 31;
        float px = 0.f;
        const float* xg = g_xg + br*BN*H + (size_t)(bN + n0)*H;
        #pragma unroll 4
        for (int n = 0; n < 128; n++)
            px += smc_s[(n0+n)*KM + kk] * xg[n*H + h];
        atomicAdd(&g_acc[ACC_PX + (br*B + b)*512 + (t-512)], px);
    }
}

// finalize pool: losses + normalized pooladj + pooled DGC (conv2gap weights)
__global__ void k_poolfin(const float* __restrict__ W2g_rel, const float* __restrict__ b2g,
                          const float* __restrict__ W2g_root){
    int b = blockIdx.x, br = blockIdx.y, t = threadIdx.x;   // 512
    __shared__ float oa[256], ssm[256], px[512], t2[512], pa[256], red[512], nrm_s;
    int base = (br*B + b)*256;
    if (t < 256){ oa[t] = g_acc[ACC_OA + base + t]; ssm[t] = g_acc[ACC_SSP + base + t]; }
    px[t] = g_acc[ACC_PX + (br*B + b)*512 + t];
    __syncthreads();
    red[t] = (t < 256) ? ssm[t]*ssm[t] : 0.f;
    __syncthreads();
    for (int o = 256; o; o >>= 1){ if (t < o) red[t] += red[t+o]; __syncthreads(); }
    if (t == 0) nrm_s = sqrtf(red[0]);
    __syncthreads();
    if (t < 256){
        int k = t >> 4, l = t & 15;
        float d = ssm[t]/nrm_s - ((k == l) ? 0.25f : 0.f);
        red[t] = d*d;
    } else red[t] = 0.f;
    __syncthreads();
    for (int o = 256; o; o >>= 1){ if (t < o) red[t] += red[t+o]; __syncthreads(); }
    if (t == 0){
        float num = 0.f;
        #pragma unroll
        for (int k = 0; k < KM; k++) num += oa[k*KM + k];
        float den = g_acc[ACC_DENP + br*B + b] + EPSV;
        atomicAdd(&g_acc[ACC_LOSS],   -(num/den)/(float)B);
        atomicAdd(&g_acc[ACC_LOSS+1], sqrtf(red[0])/(float)B);
    }
    __shared__ float dsq[KM];
    if (t < KM){
        float rs = 0.f;
        #pragma unroll
        for (int l = 0; l < KM; l++) rs += (l == t) ? 0.f : oa[t*KM + l];
        dsq[t] = sqrtf(rs) + EPSV;
    }
    __syncthreads();
    if (t < 256){
        int k = t >> 4, l = t & 15;
        pa[t] = (k == l) ? 0.f : oa[t]/(dsq[k]*dsq[l]);
    }
    __syncthreads();
    int k = t >> 5, h = t & 31;
    float a = 0.f;
    #pragma unroll
    for (int l = 0; l < KM; l++) a += pa[k*KM + l]*px[l*H + h];
    t2[t] = a;
    __syncthreads();
    float accv = b2g[h];
    #pragma unroll
    for (int j = 0; j < H; j++)
        accv += t2[k*H + j]*W2g_rel[j*H + h] + px[k*H + j]*W2g_root[j*H + h];
    g_x2[br*B*KM*H + b*KM*H + t] = accv;
}

__global__ void k_readout(const float* __restrict__ Wcat, const float* __restrict__ bcat,
                          const float* __restrict__ W2,  const float* __restrict__ b2,
                          const float* __restrict__ W3,  const float* __restrict__ b3,
                          float* __restrict__ out){
    int b = blockIdx.x, h = threadIdx.x;   // 32
    __shared__ float h1[H], h2[H], lg[10];
    float acc = 0.f;
    for (int kk = 0; kk < KM; kk++){
        float z = bcat[h];
        #pragma unroll
        for (int j = 0; j < H; j++) z += g_x2[b*KM*H + kk*H + j]*Wcat[j*H + h];
        #pragma unroll
        for (int j = 0; j < H; j++) z += g_x2[B*KM*H + b*KM*H + kk*H + j]*Wcat[(H+j)*H + h];
        acc += fmaxf(z, 0.f);
    }
    h1[h] = acc; __syncwarp();
    float z2 = b2[h];
    #pragma unroll
    for (int j = 0; j < H; j++) z2 += h1[j]*W2[j*H + h];
    h2[h] = fmaxf(z2, 0.f); __syncwarp();
    if (h < 10){
        float z = b3[h];
        #pragma unroll
        for (int j = 0; j < H; j++) z += h2[j]*W3[j*10 + h];
        lg[h] = z;
    }
    __syncwarp();
    if (h < 10){
        float m = lg[0];
        #pragma unroll
        for (int i = 1; i < 10; i++) m = fmaxf(m, lg[i]);
        float s = 0.f;
        #pragma unroll
        for (int i = 0; i < 10; i++) s += expf(lg[i] - m);
        out[b*10 + h] = lg[h] - m - logf(s);
    }
    if (b == 0 && h == 31){
        out[B*10]     = g_acc[ACC_LOSS];
        out[B*10 + 1] = g_acc[ACC_LOSS+1];
    }
}

extern "C" void kernel_launch(void* const* d_in, const int* in_sizes, int n_in,
                              void* d_out, int out_size){
    const float* x      = (const float*)d_in[0];
    const float* adj    = (const float*)d_in[1];
    const float* W1     = (const float*)d_in[3];
    const float* b1     = (const float*)d_in[4];
    const float* Wrw    = (const float*)d_in[5];
    const float* brw    = (const float*)d_in[6];
    const float* Wg_rel = (const float*)d_in[7];
    const float* bg     = (const float*)d_in[8];
    const float* Wg_root= (const float*)d_in[9];
    const float* Wmcg   = (const float*)d_in[10];
    const float* bmcg   = (const float*)d_in[11];
    const float* W2g_rel= (const float*)d_in[12];
    const float* b2g    = (const float*)d_in[13];
    const float* W2g_root=(const float*)d_in[14];
    const float* Wct    = (const float*)d_in[15];
    const float* bct    = (const float*)d_in[16];
    const float* Wc_rel = (const float*)d_in[17];
    const float* bc     = (const float*)d_in[18];
    const float* Wc_root= (const float*)d_in[19];
    const float* Wmcc   = (const float*)d_in[20];
    const float* bmcc   = (const float*)d_in[21];
    const float* Wcat   = (const float*)d_in[22];
    const float* bcat   = (const float*)d_in[23];
    const float* W2     = (const float*)d_in[24];
    const float* b2     = (const float*)d_in[25];
    const float* W3     = (const float*)d_in[26];
    const float* b3     = (const float*)d_in[27];
    float* out = (float*)d_out;

    // allow 64KB dynamic smem for k_pool (host attribute set; not a stream op)
    cudaFuncSetAttribute(k_pool, cudaFuncAttributeMaxDynamicSharedMemorySize, 65536);

    k_init<<<(ACC_TOTAL+511)/512, 512>>>();
    k_build_soft<<<BN/8, 256>>>(adj, x, W1, b1, Wrw, brw, Wct, bct);
    k_ctpart<<<B*8, 1024>>>();
    k_edgeagg<<<BN/8, 256>>>(Wg_rel, bg, Wg_root, Wmcg, bmcg,
                             Wc_rel, bc, Wc_root, Wmcc, bmcc);
    k_ctfin<<<B, 1024>>>();
    k_pool<<<dim3(8, B, 2), 1024, 65536>>>();
    k_poolfin<<<dim3(B, 2), 512>>>(W2g_rel, b2g, W2g_root);
    k_readout<<<B, 32>>>(Wcat, bcat, W2, b2, W3, b3, out);

    (void)in_sizes; (void)n_in; (void)out_size;
}